// round 1
// baseline (speedup 1.0000x reference)
#include <cuda_runtime.h>
#include <cuda_bf16.h>
#include <math.h>

// ---------------------------------------------------------------------------
// EfficientTransformerEncoder: B=32, D=256, H=W=32 -> L=1024, NH=8 (dh=32),
// NL=3, DFF=1024, WIN=64. fp32 throughout.
// ---------------------------------------------------------------------------

#define T_TOK   32768        // 32 * 1024 tokens
#define DMODEL  256
#define DQKV    768
#define DFFN    1024

// Scratch buffers (allocation-free: __device__ globals)
__device__ float g_x  [(size_t)T_TOK * DMODEL];
__device__ float g_qkv[(size_t)T_TOK * DQKV];
__device__ float g_att[(size_t)T_TOK * DMODEL];
__device__ float g_tmp[(size_t)T_TOK * DMODEL];
__device__ float g_h  [(size_t)T_TOK * DFFN];

// ---------------------------------------------------------------------------
// Embed: x[b,l,d] = features[b,d,l] + PE(l,d).  Tiled transpose via smem.
// grid (L/32, D/32, B), block (32,32)
// ---------------------------------------------------------------------------
__device__ __forceinline__ float pe_val(int l, int d) {
    int i = d >> 1;
    // exp(-(2i) * ln(10000)/256)
    float freq = expf(-(float)(2 * i) * 0.0359778920439f);
    float ang = (float)l * freq;
    return (d & 1) ? cosf(ang) : sinf(ang);
}

__global__ void embed_kernel(const float* __restrict__ f, float* __restrict__ x) {
    __shared__ float tile[32][33];
    int b  = blockIdx.z;
    int l0 = blockIdx.x * 32, d0 = blockIdx.y * 32;
    int tx = threadIdx.x, ty = threadIdx.y;
    // read f[b, d0+ty, l0+tx]  (coalesced over l)
    tile[ty][tx] = f[((size_t)b * DMODEL + d0 + ty) * 1024 + l0 + tx];
    __syncthreads();
    int l = l0 + ty, d = d0 + tx;
    x[((size_t)b * 1024 + l) * DMODEL + d] = tile[tx][ty] + pe_val(l, d);
}

// ---------------------------------------------------------------------------
// Generic NT GEMM: C[M,N] = A[M,K] * B[N,K]^T + bias[N]; act: 0=none, 1=gelu.
// 64x64x16 tile, 256 threads, 4x4 per thread. M%64==0, N%64==0, K%16==0.
// ---------------------------------------------------------------------------
#define BM 64
#define BN 64
#define BK 16

__device__ __forceinline__ float gelu_exact(float v) {
    return 0.5f * v * (1.0f + erff(v * 0.7071067811865476f));
}

__global__ __launch_bounds__(256)
void gemm_nt(const float* __restrict__ A, const float* __restrict__ B,
             const float* __restrict__ bias, float* __restrict__ C,
             int M, int N, int K, int act)
{
    __shared__ float As[BK][BM + 4];
    __shared__ float Bs[BK][BN + 4];

    int tid = threadIdx.x;
    int tx = tid & 15;          // 0..15 -> N
    int ty = tid >> 4;          // 0..15 -> M
    const float* Ab = A + (size_t)blockIdx.y * BM * K;
    const float* Bb = B + (size_t)blockIdx.x * BN * K;

    int lr = tid >> 2;          // 0..63 row in tile
    int lc = (tid & 3) * 4;     // 0,4,8,12 col in k-tile

    float acc[4][4];
#pragma unroll
    for (int i = 0; i < 4; i++)
#pragma unroll
        for (int j = 0; j < 4; j++) acc[i][j] = 0.0f;

    for (int kt = 0; kt < K; kt += BK) {
        float4 av = *(const float4*)(Ab + (size_t)lr * K + kt + lc);
        float4 bv = *(const float4*)(Bb + (size_t)lr * K + kt + lc);
        As[lc + 0][lr] = av.x; As[lc + 1][lr] = av.y;
        As[lc + 2][lr] = av.z; As[lc + 3][lr] = av.w;
        Bs[lc + 0][lr] = bv.x; Bs[lc + 1][lr] = bv.y;
        Bs[lc + 2][lr] = bv.z; Bs[lc + 3][lr] = bv.w;
        __syncthreads();
#pragma unroll
        for (int k = 0; k < BK; k++) {
            float4 a4 = *(const float4*)(&As[k][ty * 4]);
            float4 b4 = *(const float4*)(&Bs[k][tx * 4]);
            float a[4] = {a4.x, a4.y, a4.z, a4.w};
            float b[4] = {b4.x, b4.y, b4.z, b4.w};
#pragma unroll
            for (int i = 0; i < 4; i++)
#pragma unroll
                for (int j = 0; j < 4; j++) acc[i][j] = fmaf(a[i], b[j], acc[i][j]);
        }
        __syncthreads();
    }

    int col0 = blockIdx.x * BN + tx * 4;
    float bsv[4] = {bias[col0], bias[col0 + 1], bias[col0 + 2], bias[col0 + 3]};
#pragma unroll
    for (int i = 0; i < 4; i++) {
        size_t row = (size_t)blockIdx.y * BM + ty * 4 + i;
        float4 o;
        float v0 = acc[i][0] + bsv[0];
        float v1 = acc[i][1] + bsv[1];
        float v2 = acc[i][2] + bsv[2];
        float v3 = acc[i][3] + bsv[3];
        if (act == 1) {
            v0 = gelu_exact(v0); v1 = gelu_exact(v1);
            v2 = gelu_exact(v2); v3 = gelu_exact(v3);
        }
        o.x = v0; o.y = v1; o.z = v2; o.w = v3;
        *(float4*)(C + row * N + col0) = o;
    }
}

// ---------------------------------------------------------------------------
// Windowed attention: grid (512 windows, 8 heads), block 64 threads.
// qkv layout [T, 768] = [q(256) | k(256) | v(256)], head h = cols h*32..h*32+31.
// ---------------------------------------------------------------------------
__global__ __launch_bounds__(64)
void attn_kernel(const float* __restrict__ qkv, float* __restrict__ att)
{
    __shared__ float Ks[64][33];
    __shared__ float Vs[64][33];
    __shared__ float Ss[64][65];   // scores[row][col], conflict-free stride

    int w = blockIdx.x;
    int h = blockIdx.y;
    int r = threadIdx.x;           // query row within window

    const float* base = qkv + (size_t)w * 64 * DQKV;
    const float* qrow = base + (size_t)r * DQKV + h * 32;

    float q[32];
#pragma unroll
    for (int d4 = 0; d4 < 32; d4 += 4) {
        float4 qv = *(const float4*)(qrow + d4);
        q[d4 + 0] = qv.x * 0.17677669529663687f;   // 1/sqrt(32)
        q[d4 + 1] = qv.y * 0.17677669529663687f;
        q[d4 + 2] = qv.z * 0.17677669529663687f;
        q[d4 + 3] = qv.w * 0.17677669529663687f;
#pragma unroll
        for (int j = 0; j < 4; j++) {
            Ks[r][d4 + j] = qrow[256 + d4 + j];
            Vs[r][d4 + j] = qrow[512 + d4 + j];
        }
    }
    __syncthreads();

    float mx = -1e30f;
    for (int c = 0; c < 64; c++) {
        float acc = 0.0f;
#pragma unroll
        for (int d = 0; d < 32; d++) acc = fmaf(q[d], Ks[c][d], acc);
        Ss[r][c] = acc;
        mx = fmaxf(mx, acc);
    }
    float sum = 0.0f;
    for (int c = 0; c < 64; c++) {
        float e = expf(Ss[r][c] - mx);
        Ss[r][c] = e;
        sum += e;
    }
    float inv = 1.0f / sum;

    float o[32];
#pragma unroll
    for (int d = 0; d < 32; d++) o[d] = 0.0f;
    for (int c = 0; c < 64; c++) {
        float p = Ss[r][c] * inv;
#pragma unroll
        for (int d = 0; d < 32; d++) o[d] = fmaf(p, Vs[c][d], o[d]);
    }

    float* ob = att + (size_t)(w * 64 + r) * DMODEL + h * 32;
#pragma unroll
    for (int d4 = 0; d4 < 32; d4 += 4) {
        float4 ov = {o[d4], o[d4 + 1], o[d4 + 2], o[d4 + 3]};
        *(float4*)(ob + d4) = ov;
    }
}

// ---------------------------------------------------------------------------
// Fused residual + LayerNorm: x = LN(x + res) * s + b.  grid T, block 256.
// ---------------------------------------------------------------------------
__global__ __launch_bounds__(256)
void add_ln(float* __restrict__ x, const float* __restrict__ res,
            const float* __restrict__ s, const float* __restrict__ b)
{
    __shared__ float red[256];
    int t = blockIdx.x, d = threadIdx.x;
    size_t idx = (size_t)t * DMODEL + d;
    float v = x[idx] + res[idx];
    red[d] = v;
    __syncthreads();
#pragma unroll
    for (int o = 128; o > 0; o >>= 1) {
        if (d < o) red[d] += red[d + o];
        __syncthreads();
    }
    float m = red[0] * (1.0f / 256.0f);
    __syncthreads();
    float dv = v - m;
    red[d] = dv * dv;
    __syncthreads();
#pragma unroll
    for (int o = 128; o > 0; o >>= 1) {
        if (d < o) red[d] += red[d + o];
        __syncthreads();
    }
    float rs = rsqrtf(red[0] * (1.0f / 256.0f) + 1e-5f);
    x[idx] = dv * rs * s[d] + b[d];
}

// ---------------------------------------------------------------------------
// Final LN + transpose back to [B, C, H*W].  grid T, block 256.
// ---------------------------------------------------------------------------
__global__ __launch_bounds__(256)
void final_ln(const float* __restrict__ x, const float* __restrict__ s,
              const float* __restrict__ b, float* __restrict__ out)
{
    __shared__ float red[256];
    int t = blockIdx.x, d = threadIdx.x;
    size_t idx = (size_t)t * DMODEL + d;
    float v = x[idx];
    red[d] = v;
    __syncthreads();
#pragma unroll
    for (int o = 128; o > 0; o >>= 1) {
        if (d < o) red[d] += red[d + o];
        __syncthreads();
    }
    float m = red[0] * (1.0f / 256.0f);
    __syncthreads();
    float dv = v - m;
    red[d] = dv * dv;
    __syncthreads();
#pragma unroll
    for (int o = 128; o > 0; o >>= 1) {
        if (d < o) red[d] += red[d + o];
        __syncthreads();
    }
    float rs = rsqrtf(red[0] * (1.0f / 256.0f) + 1e-5f);
    float val = dv * rs * s[d] + b[d];
    int bidx = t >> 10, l = t & 1023;
    out[((size_t)bidx * DMODEL + d) * 1024 + l] = val;
}

// ---------------------------------------------------------------------------
extern "C" void kernel_launch(void* const* d_in, const int* in_sizes, int n_in,
                              void* d_out, int out_size)
{
    const float* features = (const float*)d_in[0];
    const float* in_w  = (const float*)d_in[1];
    const float* in_b  = (const float*)d_in[2];
    const float* ow    = (const float*)d_in[3];
    const float* ob    = (const float*)d_in[4];
    const float* w1    = (const float*)d_in[5];
    const float* b1    = (const float*)d_in[6];
    const float* w2    = (const float*)d_in[7];
    const float* b2    = (const float*)d_in[8];
    const float* ln1s  = (const float*)d_in[9];
    const float* ln1b  = (const float*)d_in[10];
    const float* ln2s  = (const float*)d_in[11];
    const float* ln2b  = (const float*)d_in[12];
    const float* fns   = (const float*)d_in[13];
    const float* fnb   = (const float*)d_in[14];
    float* out = (float*)d_out;

    float *x, *qkv, *att, *tmp, *hh;
    cudaGetSymbolAddress((void**)&x,   g_x);
    cudaGetSymbolAddress((void**)&qkv, g_qkv);
    cudaGetSymbolAddress((void**)&att, g_att);
    cudaGetSymbolAddress((void**)&tmp, g_tmp);
    cudaGetSymbolAddress((void**)&hh,  g_h);

    dim3 eb(32, 32);
    dim3 eg(32, 8, 32);   // (L/32, D/32, B)
    embed_kernel<<<eg, eb>>>(features, x);

    const int T = T_TOK;
    for (int i = 0; i < 3; i++) {
        // QKV projection
        gemm_nt<<<dim3(DQKV / BN, T / BM), 256>>>(
            x, in_w + (size_t)i * DQKV * DMODEL, in_b + (size_t)i * DQKV,
            qkv, T, DQKV, DMODEL, 0);
        // Windowed MHA
        attn_kernel<<<dim3(512, 8), 64>>>(qkv, att);
        // Output projection
        gemm_nt<<<dim3(DMODEL / BN, T / BM), 256>>>(
            att, ow + (size_t)i * DMODEL * DMODEL, ob + (size_t)i * DMODEL,
            tmp, T, DMODEL, DMODEL, 0);
        // x = LN(x + att_out)
        add_ln<<<T, 256>>>(x, tmp, ln1s + (size_t)i * DMODEL, ln1b + (size_t)i * DMODEL);
        // FFN up + GELU
        gemm_nt<<<dim3(DFFN / BN, T / BM), 256>>>(
            x, w1 + (size_t)i * DFFN * DMODEL, b1 + (size_t)i * DFFN,
            hh, T, DFFN, DMODEL, 1);
        // FFN down
        gemm_nt<<<dim3(DMODEL / BN, T / BM), 256>>>(
            hh, w2 + (size_t)i * DMODEL * DFFN, b2 + (size_t)i * DMODEL,
            tmp, T, DMODEL, DFFN, 0);
        // x = LN(x + ffn_out)
        add_ln<<<T, 256>>>(x, tmp, ln2s + (size_t)i * DMODEL, ln2b + (size_t)i * DMODEL);
    }
    final_ln<<<T, 256>>>(x, fns, fnb, out);
}

// round 2
// speedup vs baseline: 2.0213x; 2.0213x over previous
#include <cuda_runtime.h>
#include <cuda_bf16.h>
#include <math.h>
#include <stdint.h>

// ---------------------------------------------------------------------------
// EfficientTransformerEncoder: B=32, D=256, H=W=32 -> L=1024, NH=8 (dh=32),
// NL=3, DFF=1024, WIN=64. TF32 tensor-core GEMMs, fp32 elsewhere.
// ---------------------------------------------------------------------------

#define T_TOK   32768        // 32 * 1024 tokens
#define DMODEL  256
#define DQKV    768
#define DFFN    1024

// Scratch buffers (allocation-free: __device__ globals)
__device__ float g_x  [(size_t)T_TOK * DMODEL];
__device__ float g_qkv[(size_t)T_TOK * DQKV];
__device__ float g_att[(size_t)T_TOK * DMODEL];
__device__ float g_tmp[(size_t)T_TOK * DMODEL];
__device__ float g_h  [(size_t)T_TOK * DFFN];

// ---------------------------------------------------------------------------
// Embed: x[b,l,d] = features[b,d,l] + PE(l,d).  Tiled transpose via smem.
// ---------------------------------------------------------------------------
__device__ __forceinline__ float pe_val(int l, int d) {
    int i = d >> 1;
    float freq = expf(-(float)(2 * i) * 0.0359778920439f);  // ln(10000)/256
    float ang = (float)l * freq;
    return (d & 1) ? cosf(ang) : sinf(ang);
}

__global__ void embed_kernel(const float* __restrict__ f, float* __restrict__ x) {
    __shared__ float tile[32][33];
    int b  = blockIdx.z;
    int l0 = blockIdx.x * 32, d0 = blockIdx.y * 32;
    int tx = threadIdx.x, ty = threadIdx.y;
    tile[ty][tx] = f[((size_t)b * DMODEL + d0 + ty) * 1024 + l0 + tx];
    __syncthreads();
    int l = l0 + ty, d = d0 + tx;
    x[((size_t)b * 1024 + l) * DMODEL + d] = tile[tx][ty] + pe_val(l, d);
}

// ---------------------------------------------------------------------------
// TF32 tensor-core NT GEMM: C[M,N] = A[M,K] * B[N,K]^T + bias[N]; act=1 -> GELU.
// Block tile 128x128x16, 256 threads (8 warps as 2x4), warp tile 64x32.
// mma.sync.aligned.m16n8k8.row.col.f32.tf32.tf32.f32
// Requires M%128==0, N%128==0, K%16==0.
// ---------------------------------------------------------------------------
__device__ __forceinline__ float gelu_exact(float v) {
    return 0.5f * v * (1.0f + erff(v * 0.7071067811865476f));
}

__device__ __forceinline__ uint32_t f2tf32(float x) {
    uint32_t y;
    asm("cvt.rna.tf32.f32 %0, %1;" : "=r"(y) : "f"(x));
    return y;
}

__device__ __forceinline__ void mma_tf32(float c[4], const uint32_t a[4], const uint32_t b[2]) {
    asm volatile(
        "mma.sync.aligned.m16n8k8.row.col.f32.tf32.tf32.f32 "
        "{%0,%1,%2,%3}, {%4,%5,%6,%7}, {%8,%9}, {%0,%1,%2,%3};\n"
        : "+f"(c[0]), "+f"(c[1]), "+f"(c[2]), "+f"(c[3])
        : "r"(a[0]), "r"(a[1]), "r"(a[2]), "r"(a[3]), "r"(b[0]), "r"(b[1]));
}

#define SMS 20   // smem row stride (floats): 20*grp mod 32 all-distinct -> conflict-free

__global__ __launch_bounds__(256, 2)
void gemm_tf32(const float* __restrict__ A, const float* __restrict__ B,
               const float* __restrict__ bias, float* __restrict__ C,
               int M, int N, int K, int act)
{
    __shared__ float As[128][SMS];
    __shared__ float Bs[128][SMS];

    int tid  = threadIdx.x;
    int warp = tid >> 5, lane = tid & 31;
    int wm = (warp >> 2) * 64;     // warp m offset within block tile (0,64)
    int wn = (warp & 3) * 32;      // warp n offset within block tile (0..96)
    int grp = lane >> 2, tig = lane & 3;

    const float* Ab = A + (size_t)blockIdx.y * 128 * K;
    const float* Bb = B + (size_t)blockIdx.x * 128 * K;

    int lr = tid >> 2;             // 0..63 : tile row for gmem load
    int lc = (tid & 3) * 4;        // 0,4,8,12 : k offset

    float acc[4][4][4];
#pragma unroll
    for (int mi = 0; mi < 4; mi++)
#pragma unroll
        for (int ni = 0; ni < 4; ni++)
#pragma unroll
            for (int r = 0; r < 4; r++) acc[mi][ni][r] = 0.0f;

    for (int kt = 0; kt < K; kt += 16) {
        float4 a0v = *(const float4*)(Ab + (size_t)lr * K + kt + lc);
        float4 a1v = *(const float4*)(Ab + (size_t)(lr + 64) * K + kt + lc);
        float4 b0v = *(const float4*)(Bb + (size_t)lr * K + kt + lc);
        float4 b1v = *(const float4*)(Bb + (size_t)(lr + 64) * K + kt + lc);
        // convert to tf32 bit patterns once, on the way into smem
        float4 ta0, ta1, tb0, tb1;
        ta0.x = __uint_as_float(f2tf32(a0v.x)); ta0.y = __uint_as_float(f2tf32(a0v.y));
        ta0.z = __uint_as_float(f2tf32(a0v.z)); ta0.w = __uint_as_float(f2tf32(a0v.w));
        ta1.x = __uint_as_float(f2tf32(a1v.x)); ta1.y = __uint_as_float(f2tf32(a1v.y));
        ta1.z = __uint_as_float(f2tf32(a1v.z)); ta1.w = __uint_as_float(f2tf32(a1v.w));
        tb0.x = __uint_as_float(f2tf32(b0v.x)); tb0.y = __uint_as_float(f2tf32(b0v.y));
        tb0.z = __uint_as_float(f2tf32(b0v.z)); tb0.w = __uint_as_float(f2tf32(b0v.w));
        tb1.x = __uint_as_float(f2tf32(b1v.x)); tb1.y = __uint_as_float(f2tf32(b1v.y));
        tb1.z = __uint_as_float(f2tf32(b1v.z)); tb1.w = __uint_as_float(f2tf32(b1v.w));
        *(float4*)(&As[lr     ][lc]) = ta0;
        *(float4*)(&As[lr + 64][lc]) = ta1;
        *(float4*)(&Bs[lr     ][lc]) = tb0;
        *(float4*)(&Bs[lr + 64][lc]) = tb1;
        __syncthreads();

#pragma unroll
        for (int ks = 0; ks < 2; ks++) {
            int kb = ks * 8;
            uint32_t af[4][4], bf[4][2];
#pragma unroll
            for (int mi = 0; mi < 4; mi++) {
                int r = wm + mi * 16 + grp;
                af[mi][0] = __float_as_uint(As[r    ][kb + tig]);
                af[mi][1] = __float_as_uint(As[r + 8][kb + tig]);
                af[mi][2] = __float_as_uint(As[r    ][kb + tig + 4]);
                af[mi][3] = __float_as_uint(As[r + 8][kb + tig + 4]);
            }
#pragma unroll
            for (int ni = 0; ni < 4; ni++) {
                int c = wn + ni * 8 + grp;
                bf[ni][0] = __float_as_uint(Bs[c][kb + tig]);
                bf[ni][1] = __float_as_uint(Bs[c][kb + tig + 4]);
            }
#pragma unroll
            for (int mi = 0; mi < 4; mi++)
#pragma unroll
                for (int ni = 0; ni < 4; ni++)
                    mma_tf32(acc[mi][ni], af[mi], bf[ni]);
        }
        __syncthreads();
    }

    // Epilogue: bias (+ GELU), fp32 out
#pragma unroll
    for (int mi = 0; mi < 4; mi++) {
        int r0 = blockIdx.y * 128 + wm + mi * 16 + grp;
#pragma unroll
        for (int ni = 0; ni < 4; ni++) {
            int c = blockIdx.x * 128 + wn + ni * 8 + tig * 2;
            float bv0 = bias[c], bv1 = bias[c + 1];
            float v0 = acc[mi][ni][0] + bv0;
            float v1 = acc[mi][ni][1] + bv1;
            float v2 = acc[mi][ni][2] + bv0;
            float v3 = acc[mi][ni][3] + bv1;
            if (act == 1) {
                v0 = gelu_exact(v0); v1 = gelu_exact(v1);
                v2 = gelu_exact(v2); v3 = gelu_exact(v3);
            }
            float2 p0 = {v0, v1}, p1 = {v2, v3};
            *(float2*)(C + (size_t)r0 * N + c) = p0;
            *(float2*)(C + (size_t)(r0 + 8) * N + c) = p1;
        }
    }
}

// ---------------------------------------------------------------------------
// Windowed attention: grid (512 windows, 8 heads), block 64 threads.
// ---------------------------------------------------------------------------
__global__ __launch_bounds__(64)
void attn_kernel(const float* __restrict__ qkv, float* __restrict__ att)
{
    __shared__ float Ks[64][33];
    __shared__ float Vs[64][33];
    __shared__ float Ss[64][65];

    int w = blockIdx.x;
    int h = blockIdx.y;
    int r = threadIdx.x;

    const float* qrow = qkv + (size_t)w * 64 * DQKV + (size_t)r * DQKV + h * 32;

    float q[32];
#pragma unroll
    for (int d4 = 0; d4 < 32; d4 += 4) {
        float4 qv = *(const float4*)(qrow + d4);
        q[d4 + 0] = qv.x * 0.17677669529663687f;
        q[d4 + 1] = qv.y * 0.17677669529663687f;
        q[d4 + 2] = qv.z * 0.17677669529663687f;
        q[d4 + 3] = qv.w * 0.17677669529663687f;
#pragma unroll
        for (int j = 0; j < 4; j++) {
            Ks[r][d4 + j] = qrow[256 + d4 + j];
            Vs[r][d4 + j] = qrow[512 + d4 + j];
        }
    }
    __syncthreads();

    float mx = -1e30f;
    for (int c = 0; c < 64; c++) {
        float acc = 0.0f;
#pragma unroll
        for (int d = 0; d < 32; d++) acc = fmaf(q[d], Ks[c][d], acc);
        Ss[r][c] = acc;
        mx = fmaxf(mx, acc);
    }
    float sum = 0.0f;
    for (int c = 0; c < 64; c++) {
        float e = expf(Ss[r][c] - mx);
        Ss[r][c] = e;
        sum += e;
    }
    float inv = 1.0f / sum;

    float o[32];
#pragma unroll
    for (int d = 0; d < 32; d++) o[d] = 0.0f;
    for (int c = 0; c < 64; c++) {
        float p = Ss[r][c] * inv;
#pragma unroll
        for (int d = 0; d < 32; d++) o[d] = fmaf(p, Vs[c][d], o[d]);
    }

    float* obp = att + (size_t)(w * 64 + r) * DMODEL + h * 32;
#pragma unroll
    for (int d4 = 0; d4 < 32; d4 += 4) {
        float4 ov = {o[d4], o[d4 + 1], o[d4 + 2], o[d4 + 3]};
        *(float4*)(obp + d4) = ov;
    }
}

// ---------------------------------------------------------------------------
// Fused residual + LayerNorm: x = LN(x + res) * s + b.
// ---------------------------------------------------------------------------
__global__ __launch_bounds__(256)
void add_ln(float* __restrict__ x, const float* __restrict__ res,
            const float* __restrict__ s, const float* __restrict__ b)
{
    __shared__ float red[256];
    int t = blockIdx.x, d = threadIdx.x;
    size_t idx = (size_t)t * DMODEL + d;
    float v = x[idx] + res[idx];
    red[d] = v;
    __syncthreads();
#pragma unroll
    for (int o = 128; o > 0; o >>= 1) {
        if (d < o) red[d] += red[d + o];
        __syncthreads();
    }
    float m = red[0] * (1.0f / 256.0f);
    __syncthreads();
    float dv = v - m;
    red[d] = dv * dv;
    __syncthreads();
#pragma unroll
    for (int o = 128; o > 0; o >>= 1) {
        if (d < o) red[d] += red[d + o];
        __syncthreads();
    }
    float rs = rsqrtf(red[0] * (1.0f / 256.0f) + 1e-5f);
    x[idx] = dv * rs * s[d] + b[d];
}

// ---------------------------------------------------------------------------
// Final LN + transpose back to [B, C, H*W].
// ---------------------------------------------------------------------------
__global__ __launch_bounds__(256)
void final_ln(const float* __restrict__ x, const float* __restrict__ s,
              const float* __restrict__ b, float* __restrict__ out)
{
    __shared__ float red[256];
    int t = blockIdx.x, d = threadIdx.x;
    size_t idx = (size_t)t * DMODEL + d;
    float v = x[idx];
    red[d] = v;
    __syncthreads();
#pragma unroll
    for (int o = 128; o > 0; o >>= 1) {
        if (d < o) red[d] += red[d + o];
        __syncthreads();
    }
    float m = red[0] * (1.0f / 256.0f);
    __syncthreads();
    float dv = v - m;
    red[d] = dv * dv;
    __syncthreads();
#pragma unroll
    for (int o = 128; o > 0; o >>= 1) {
        if (d < o) red[d] += red[d + o];
        __syncthreads();
    }
    float rs = rsqrtf(red[0] * (1.0f / 256.0f) + 1e-5f);
    float val = dv * rs * s[d] + b[d];
    int bidx = t >> 10, l = t & 1023;
    out[((size_t)bidx * DMODEL + d) * 1024 + l] = val;
}

// ---------------------------------------------------------------------------
extern "C" void kernel_launch(void* const* d_in, const int* in_sizes, int n_in,
                              void* d_out, int out_size)
{
    const float* features = (const float*)d_in[0];
    const float* in_w  = (const float*)d_in[1];
    const float* in_b  = (const float*)d_in[2];
    const float* ow    = (const float*)d_in[3];
    const float* ob    = (const float*)d_in[4];
    const float* w1    = (const float*)d_in[5];
    const float* b1    = (const float*)d_in[6];
    const float* w2    = (const float*)d_in[7];
    const float* b2    = (const float*)d_in[8];
    const float* ln1s  = (const float*)d_in[9];
    const float* ln1b  = (const float*)d_in[10];
    const float* ln2s  = (const float*)d_in[11];
    const float* ln2b  = (const float*)d_in[12];
    const float* fns   = (const float*)d_in[13];
    const float* fnb   = (const float*)d_in[14];
    float* out = (float*)d_out;

    float *x, *qkv, *att, *tmp, *hh;
    cudaGetSymbolAddress((void**)&x,   g_x);
    cudaGetSymbolAddress((void**)&qkv, g_qkv);
    cudaGetSymbolAddress((void**)&att, g_att);
    cudaGetSymbolAddress((void**)&tmp, g_tmp);
    cudaGetSymbolAddress((void**)&hh,  g_h);

    dim3 eb(32, 32);
    dim3 eg(32, 8, 32);
    embed_kernel<<<eg, eb>>>(features, x);

    const int T = T_TOK;
    for (int i = 0; i < 3; i++) {
        gemm_tf32<<<dim3(DQKV / 128, T / 128), 256>>>(
            x, in_w + (size_t)i * DQKV * DMODEL, in_b + (size_t)i * DQKV,
            qkv, T, DQKV, DMODEL, 0);
        attn_kernel<<<dim3(512, 8), 64>>>(qkv, att);
        gemm_tf32<<<dim3(DMODEL / 128, T / 128), 256>>>(
            att, ow + (size_t)i * DMODEL * DMODEL, ob + (size_t)i * DMODEL,
            tmp, T, DMODEL, DMODEL, 0);
        add_ln<<<T, 256>>>(x, tmp, ln1s + (size_t)i * DMODEL, ln1b + (size_t)i * DMODEL);
        gemm_tf32<<<dim3(DFFN / 128, T / 128), 256>>>(
            x, w1 + (size_t)i * DFFN * DMODEL, b1 + (size_t)i * DFFN,
            hh, T, DFFN, DMODEL, 1);
        gemm_tf32<<<dim3(DMODEL / 128, T / 128), 256>>>(
            hh, w2 + (size_t)i * DMODEL * DFFN, b2 + (size_t)i * DMODEL,
            tmp, T, DMODEL, DFFN, 0);
        add_ln<<<T, 256>>>(x, tmp, ln2s + (size_t)i * DMODEL, ln2b + (size_t)i * DMODEL);
    }
    final_ln<<<T, 256>>>(x, fns, fnb, out);
}

// round 3
// speedup vs baseline: 2.1313x; 1.0544x over previous
#include <cuda_runtime.h>
#include <cuda_bf16.h>
#include <math.h>
#include <stdint.h>

// ---------------------------------------------------------------------------
// EfficientTransformerEncoder: B=32, D=256, H=W=32 -> L=1024, NH=8 (dh=32),
// NL=3, DFF=1024, WIN=64. TF32 tensor-core GEMMs (cp.async pipelined).
// ---------------------------------------------------------------------------

#define T_TOK   32768        // 32 * 1024 tokens
#define DMODEL  256
#define DQKV    768
#define DFFN    1024

__device__ float g_x  [(size_t)T_TOK * DMODEL];
__device__ float g_qkv[(size_t)T_TOK * DQKV];
__device__ float g_att[(size_t)T_TOK * DMODEL];
__device__ float g_tmp[(size_t)T_TOK * DMODEL];
__device__ float g_h  [(size_t)T_TOK * DFFN];

// ---------------------------------------------------------------------------
// Embed: x[b,l,d] = features[b,d,l] + PE(l,d).
// ---------------------------------------------------------------------------
__device__ __forceinline__ float pe_val(int l, int d) {
    int i = d >> 1;
    float freq = expf(-(float)(2 * i) * 0.0359778920439f);  // ln(10000)/256
    float ang = (float)l * freq;
    return (d & 1) ? cosf(ang) : sinf(ang);
}

__global__ void embed_kernel(const float* __restrict__ f, float* __restrict__ x) {
    __shared__ float tile[32][33];
    int b  = blockIdx.z;
    int l0 = blockIdx.x * 32, d0 = blockIdx.y * 32;
    int tx = threadIdx.x, ty = threadIdx.y;
    tile[ty][tx] = f[((size_t)b * DMODEL + d0 + ty) * 1024 + l0 + tx];
    __syncthreads();
    int l = l0 + ty, d = d0 + tx;
    x[((size_t)b * 1024 + l) * DMODEL + d] = tile[tx][ty] + pe_val(l, d);
}

// ---------------------------------------------------------------------------
// TF32 tensor-core NT GEMM, cp.async double-buffered.
// C[M,N] = A[M,K] * B[N,K]^T + bias[N]; act=1 -> exact GELU.
// Block tile 128x128x16, 256 threads (8 warps as 2x4), warp tile 64x32.
// ---------------------------------------------------------------------------
__device__ __forceinline__ float gelu_exact(float v) {
    return 0.5f * v * (1.0f + erff(v * 0.7071067811865476f));
}

__device__ __forceinline__ uint32_t f2tf32(float x) {
    uint32_t y;
    asm("cvt.rna.tf32.f32 %0, %1;" : "=r"(y) : "f"(x));
    return y;
}

__device__ __forceinline__ void mma_tf32(float c[4], const uint32_t a[4], const uint32_t b[2]) {
    asm volatile(
        "mma.sync.aligned.m16n8k8.row.col.f32.tf32.tf32.f32 "
        "{%0,%1,%2,%3}, {%4,%5,%6,%7}, {%8,%9}, {%0,%1,%2,%3};\n"
        : "+f"(c[0]), "+f"(c[1]), "+f"(c[2]), "+f"(c[3])
        : "r"(a[0]), "r"(a[1]), "r"(a[2]), "r"(a[3]), "r"(b[0]), "r"(b[1]));
}

__device__ __forceinline__ void cpa16(uint32_t dst, const float* src) {
    asm volatile("cp.async.cg.shared.global [%0], [%1], 16;\n" :: "r"(dst), "l"(src));
}
__device__ __forceinline__ void cpa_commit() {
    asm volatile("cp.async.commit_group;\n" ::: "memory");
}
__device__ __forceinline__ void cpa_wait0() {
    asm volatile("cp.async.wait_group 0;\n" ::: "memory");
}

#define SMS 20                       // stride 20 floats -> conflict-free frags
#define BUFB (128 * SMS * 4)         // bytes per buffer per matrix

__global__ __launch_bounds__(256, 2)
void gemm_tf32(const float* __restrict__ A, const float* __restrict__ B,
               const float* __restrict__ bias, float* __restrict__ C,
               int M, int N, int K, int act)
{
    __shared__ float As[2][128][SMS];
    __shared__ float Bs[2][128][SMS];

    int tid  = threadIdx.x;
    int warp = tid >> 5, lane = tid & 31;
    int wm = (warp >> 2) * 64;
    int wn = (warp & 3) * 32;
    int grp = lane >> 2, tig = lane & 3;

    const float* Ab = A + (size_t)blockIdx.y * 128 * K;
    const float* Bb = B + (size_t)blockIdx.x * 128 * K;

    int lr = tid >> 2;               // 0..63
    int lc = (tid & 3) * 4;          // 0,4,8,12

    const float* aSrc0 = Ab + (size_t)lr * K + lc;
    const float* aSrc1 = Ab + (size_t)(lr + 64) * K + lc;
    const float* bSrc0 = Bb + (size_t)lr * K + lc;
    const float* bSrc1 = Bb + (size_t)(lr + 64) * K + lc;

    uint32_t dA0 = (uint32_t)__cvta_generic_to_shared(&As[0][lr][lc]);
    uint32_t dA1 = (uint32_t)__cvta_generic_to_shared(&As[0][lr + 64][lc]);
    uint32_t dB0 = (uint32_t)__cvta_generic_to_shared(&Bs[0][lr][lc]);
    uint32_t dB1 = (uint32_t)__cvta_generic_to_shared(&Bs[0][lr + 64][lc]);

    float acc[4][4][4];
#pragma unroll
    for (int mi = 0; mi < 4; mi++)
#pragma unroll
        for (int ni = 0; ni < 4; ni++)
#pragma unroll
            for (int r = 0; r < 4; r++) acc[mi][ni][r] = 0.0f;

    int nt = K >> 4;

    // prefetch tile 0 into buf 0
    cpa16(dA0, aSrc0); cpa16(dA1, aSrc1);
    cpa16(dB0, bSrc0); cpa16(dB1, bSrc1);
    cpa_commit();

    for (int j = 0; j < nt; j++) {
        cpa_wait0();
        __syncthreads();

        if (j + 1 < nt) {
            uint32_t o = ((j + 1) & 1) * BUFB;
            int ko = (j + 1) << 4;
            cpa16(dA0 + o, aSrc0 + ko); cpa16(dA1 + o, aSrc1 + ko);
            cpa16(dB0 + o, bSrc0 + ko); cpa16(dB1 + o, bSrc1 + ko);
            cpa_commit();
        }

        int buf = j & 1;
#pragma unroll
        for (int ks = 0; ks < 2; ks++) {
            int kb = ks * 8;
            uint32_t af[4][4], bf[4][2];
#pragma unroll
            for (int mi = 0; mi < 4; mi++) {
                int r = wm + mi * 16 + grp;
                af[mi][0] = f2tf32(As[buf][r    ][kb + tig]);
                af[mi][1] = f2tf32(As[buf][r + 8][kb + tig]);
                af[mi][2] = f2tf32(As[buf][r    ][kb + tig + 4]);
                af[mi][3] = f2tf32(As[buf][r + 8][kb + tig + 4]);
            }
#pragma unroll
            for (int ni = 0; ni < 4; ni++) {
                int c = wn + ni * 8 + grp;
                bf[ni][0] = f2tf32(Bs[buf][c][kb + tig]);
                bf[ni][1] = f2tf32(Bs[buf][c][kb + tig + 4]);
            }
#pragma unroll
            for (int mi = 0; mi < 4; mi++)
#pragma unroll
                for (int ni = 0; ni < 4; ni++)
                    mma_tf32(acc[mi][ni], af[mi], bf[ni]);
        }
        __syncthreads();
    }

    // Epilogue: bias (+ GELU), fp32 out
#pragma unroll
    for (int mi = 0; mi < 4; mi++) {
        int r0 = blockIdx.y * 128 + wm + mi * 16 + grp;
#pragma unroll
        for (int ni = 0; ni < 4; ni++) {
            int c = blockIdx.x * 128 + wn + ni * 8 + tig * 2;
            float bv0 = bias[c], bv1 = bias[c + 1];
            float v0 = acc[mi][ni][0] + bv0;
            float v1 = acc[mi][ni][1] + bv1;
            float v2 = acc[mi][ni][2] + bv0;
            float v3 = acc[mi][ni][3] + bv1;
            if (act == 1) {
                v0 = gelu_exact(v0); v1 = gelu_exact(v1);
                v2 = gelu_exact(v2); v3 = gelu_exact(v3);
            }
            float2 p0 = {v0, v1}, p1 = {v2, v3};
            *(float2*)(C + (size_t)r0 * N + c) = p0;
            *(float2*)(C + (size_t)(r0 + 8) * N + c) = p1;
        }
    }
}

// ---------------------------------------------------------------------------
// Windowed attention: grid (512 windows, 8 heads), block 64 threads.
// ---------------------------------------------------------------------------
__global__ __launch_bounds__(64)
void attn_kernel(const float* __restrict__ qkv, float* __restrict__ att)
{
    __shared__ float Ks[64][33];
    __shared__ float Vs[64][33];
    __shared__ float Ss[64][65];

    int w = blockIdx.x;
    int h = blockIdx.y;
    int r = threadIdx.x;

    const float* qrow = qkv + (size_t)w * 64 * DQKV + (size_t)r * DQKV + h * 32;

    float q[32];
#pragma unroll
    for (int d4 = 0; d4 < 32; d4 += 4) {
        float4 qv = *(const float4*)(qrow + d4);
        q[d4 + 0] = qv.x * 0.17677669529663687f;
        q[d4 + 1] = qv.y * 0.17677669529663687f;
        q[d4 + 2] = qv.z * 0.17677669529663687f;
        q[d4 + 3] = qv.w * 0.17677669529663687f;
#pragma unroll
        for (int j = 0; j < 4; j++) {
            Ks[r][d4 + j] = qrow[256 + d4 + j];
            Vs[r][d4 + j] = qrow[512 + d4 + j];
        }
    }
    __syncthreads();

    float mx = -1e30f;
    for (int c = 0; c < 64; c++) {
        float acc = 0.0f;
#pragma unroll
        for (int d = 0; d < 32; d++) acc = fmaf(q[d], Ks[c][d], acc);
        Ss[r][c] = acc;
        mx = fmaxf(mx, acc);
    }
    float sum = 0.0f;
    for (int c = 0; c < 64; c++) {
        float e = expf(Ss[r][c] - mx);
        Ss[r][c] = e;
        sum += e;
    }
    float inv = 1.0f / sum;

    float o[32];
#pragma unroll
    for (int d = 0; d < 32; d++) o[d] = 0.0f;
    for (int c = 0; c < 64; c++) {
        float p = Ss[r][c] * inv;
#pragma unroll
        for (int d = 0; d < 32; d++) o[d] = fmaf(p, Vs[c][d], o[d]);
    }

    float* obp = att + (size_t)(w * 64 + r) * DMODEL + h * 32;
#pragma unroll
    for (int d4 = 0; d4 < 32; d4 += 4) {
        float4 ov = {o[d4], o[d4 + 1], o[d4 + 2], o[d4 + 3]};
        *(float4*)(obp + d4) = ov;
    }
}

// ---------------------------------------------------------------------------
// Fused residual + LayerNorm: x = LN(x + res) * s + b.
// ---------------------------------------------------------------------------
__global__ __launch_bounds__(256)
void add_ln(float* __restrict__ x, const float* __restrict__ res,
            const float* __restrict__ s, const float* __restrict__ b)
{
    __shared__ float red[256];
    int t = blockIdx.x, d = threadIdx.x;
    size_t idx = (size_t)t * DMODEL + d;
    float v = x[idx] + res[idx];
    red[d] = v;
    __syncthreads();
#pragma unroll
    for (int o = 128; o > 0; o >>= 1) {
        if (d < o) red[d] += red[d + o];
        __syncthreads();
    }
    float m = red[0] * (1.0f / 256.0f);
    __syncthreads();
    float dv = v - m;
    red[d] = dv * dv;
    __syncthreads();
#pragma unroll
    for (int o = 128; o > 0; o >>= 1) {
        if (d < o) red[d] += red[d + o];
        __syncthreads();
    }
    float rs = rsqrtf(red[0] * (1.0f / 256.0f) + 1e-5f);
    x[idx] = dv * rs * s[d] + b[d];
}

// ---------------------------------------------------------------------------
// Final LN + transpose back to [B, C, H*W].
// ---------------------------------------------------------------------------
__global__ __launch_bounds__(256)
void final_ln(const float* __restrict__ x, const float* __restrict__ s,
              const float* __restrict__ b, float* __restrict__ out)
{
    __shared__ float red[256];
    int t = blockIdx.x, d = threadIdx.x;
    size_t idx = (size_t)t * DMODEL + d;
    float v = x[idx];
    red[d] = v;
    __syncthreads();
#pragma unroll
    for (int o = 128; o > 0; o >>= 1) {
        if (d < o) red[d] += red[d + o];
        __syncthreads();
    }
    float m = red[0] * (1.0f / 256.0f);
    __syncthreads();
    float dv = v - m;
    red[d] = dv * dv;
    __syncthreads();
#pragma unroll
    for (int o = 128; o > 0; o >>= 1) {
        if (d < o) red[d] += red[d + o];
        __syncthreads();
    }
    float rs = rsqrtf(red[0] * (1.0f / 256.0f) + 1e-5f);
    float val = dv * rs * s[d] + b[d];
    int bidx = t >> 10, l = t & 1023;
    out[((size_t)bidx * DMODEL + d) * 1024 + l] = val;
}

// ---------------------------------------------------------------------------
extern "C" void kernel_launch(void* const* d_in, const int* in_sizes, int n_in,
                              void* d_out, int out_size)
{
    const float* features = (const float*)d_in[0];
    const float* in_w  = (const float*)d_in[1];
    const float* in_b  = (const float*)d_in[2];
    const float* ow    = (const float*)d_in[3];
    const float* ob    = (const float*)d_in[4];
    const float* w1    = (const float*)d_in[5];
    const float* b1    = (const float*)d_in[6];
    const float* w2    = (const float*)d_in[7];
    const float* b2    = (const float*)d_in[8];
    const float* ln1s  = (const float*)d_in[9];
    const float* ln1b  = (const float*)d_in[10];
    const float* ln2s  = (const float*)d_in[11];
    const float* ln2b  = (const float*)d_in[12];
    const float* fns   = (const float*)d_in[13];
    const float* fnb   = (const float*)d_in[14];
    float* out = (float*)d_out;

    float *x, *qkv, *att, *tmp, *hh;
    cudaGetSymbolAddress((void**)&x,   g_x);
    cudaGetSymbolAddress((void**)&qkv, g_qkv);
    cudaGetSymbolAddress((void**)&att, g_att);
    cudaGetSymbolAddress((void**)&tmp, g_tmp);
    cudaGetSymbolAddress((void**)&hh,  g_h);

    dim3 eb(32, 32);
    dim3 eg(32, 8, 32);
    embed_kernel<<<eg, eb>>>(features, x);

    const int T = T_TOK;
    for (int i = 0; i < 3; i++) {
        gemm_tf32<<<dim3(DQKV / 128, T / 128), 256>>>(
            x, in_w + (size_t)i * DQKV * DMODEL, in_b + (size_t)i * DQKV,
            qkv, T, DQKV, DMODEL, 0);
        attn_kernel<<<dim3(512, 8), 64>>>(qkv, att);
        gemm_tf32<<<dim3(DMODEL / 128, T / 128), 256>>>(
            att, ow + (size_t)i * DMODEL * DMODEL, ob + (size_t)i * DMODEL,
            tmp, T, DMODEL, DMODEL, 0);
        add_ln<<<T, 256>>>(x, tmp, ln1s + (size_t)i * DMODEL, ln1b + (size_t)i * DMODEL);
        gemm_tf32<<<dim3(DFFN / 128, T / 128), 256>>>(
            x, w1 + (size_t)i * DFFN * DMODEL, b1 + (size_t)i * DFFN,
            hh, T, DFFN, DMODEL, 1);
        gemm_tf32<<<dim3(DMODEL / 128, T / 128), 256>>>(
            hh, w2 + (size_t)i * DMODEL * DFFN, b2 + (size_t)i * DMODEL,
            tmp, T, DMODEL, DFFN, 0);
        add_ln<<<T, 256>>>(x, tmp, ln2s + (size_t)i * DMODEL, ln2b + (size_t)i * DMODEL);
    }
    final_ln<<<T, 256>>>(x, fns, fnb, out);
}

// round 4
// speedup vs baseline: 2.4471x; 1.1482x over previous
#include <cuda_runtime.h>
#include <cuda_bf16.h>
#include <math.h>
#include <stdint.h>

// ---------------------------------------------------------------------------
// EfficientTransformerEncoder: B=32, D=256, H=W=32 -> L=1024, NH=8 (dh=32),
// NL=3, DFF=1024, WIN=64. TF32 tensor-core GEMMs, operands pre-converted.
// ---------------------------------------------------------------------------

#define T_TOK   32768
#define DMODEL  256
#define DQKV    768
#define DFFN    1024

__device__ float g_x  [(size_t)T_TOK * DMODEL];   // fp32 residual stream
__device__ float g_xt [(size_t)T_TOK * DMODEL];   // tf32 copy of x
__device__ float g_qkv[(size_t)T_TOK * DQKV];     // fp32 (attn consumes)
__device__ float g_att[(size_t)T_TOK * DMODEL];   // tf32 (gemm consumes)
__device__ float g_tmp[(size_t)T_TOK * DMODEL];   // fp32 (add_ln consumes)
__device__ float g_h  [(size_t)T_TOK * DFFN];     // tf32 (gemm consumes)

// tf32-converted weights: [in_w | ow | w1 | w2]
#define WT_INW 0
#define WT_OW  (WT_INW + 3 * DQKV * DMODEL)
#define WT_W1  (WT_OW  + 3 * DMODEL * DMODEL)
#define WT_W2  (WT_W1  + 3 * DFFN * DMODEL)
#define WT_TOT (WT_W2  + 3 * DMODEL * DFFN)
__device__ float g_wt[WT_TOT];

__device__ __forceinline__ uint32_t f2tf32(float x) {
    uint32_t y;
    asm("cvt.rna.tf32.f32 %0, %1;" : "=r"(y) : "f"(x));
    return y;
}
__device__ __forceinline__ float f2tf32f(float x) { return __uint_as_float(f2tf32(x)); }

// ---------------------------------------------------------------------------
// Elementwise fp32 -> tf32-bits converter (weights). n divisible by 4.
// ---------------------------------------------------------------------------
__global__ void cvt_kernel(const float* __restrict__ src, float* __restrict__ dst, int n4) {
    int i = blockIdx.x * blockDim.x + threadIdx.x;
    if (i >= n4) return;
    float4 v = ((const float4*)src)[i];
    float4 o;
    o.x = f2tf32f(v.x); o.y = f2tf32f(v.y);
    o.z = f2tf32f(v.z); o.w = f2tf32f(v.w);
    ((float4*)dst)[i] = o;
}

// ---------------------------------------------------------------------------
// Embed: x[b,l,d] = features[b,d,l] + PE(l,d); writes fp32 + tf32 copies.
// ---------------------------------------------------------------------------
__device__ __forceinline__ float pe_val(int l, int d) {
    int i = d >> 1;
    float freq = expf(-(float)(2 * i) * 0.0359778920439f);
    float ang = (float)l * freq;
    return (d & 1) ? cosf(ang) : sinf(ang);
}

__global__ void embed_kernel(const float* __restrict__ f,
                             float* __restrict__ x, float* __restrict__ xt) {
    __shared__ float tile[32][33];
    int b  = blockIdx.z;
    int l0 = blockIdx.x * 32, d0 = blockIdx.y * 32;
    int tx = threadIdx.x, ty = threadIdx.y;
    tile[ty][tx] = f[((size_t)b * DMODEL + d0 + ty) * 1024 + l0 + tx];
    __syncthreads();
    int l = l0 + ty, d = d0 + tx;
    float v = tile[tx][ty] + pe_val(l, d);
    size_t idx = ((size_t)b * 1024 + l) * DMODEL + d;
    x[idx]  = v;
    xt[idx] = f2tf32f(v);
}

// ---------------------------------------------------------------------------
// TF32 NT GEMM, cp.async double-buffered, operands pre-converted (no cvt).
// C[M,N] = A[M,K]*B[N,K]^T + bias[N]; act=1 -> exact GELU; outcvt=1 -> tf32 out.
// Block 128x128x16, 256 threads (2x4 warps), warp tile 64x32.
// ---------------------------------------------------------------------------
__device__ __forceinline__ float gelu_exact(float v) {
    return 0.5f * v * (1.0f + erff(v * 0.7071067811865476f));
}

__device__ __forceinline__ void mma_tf32(float c[4], const uint32_t a[4], const uint32_t b[2]) {
    asm volatile(
        "mma.sync.aligned.m16n8k8.row.col.f32.tf32.tf32.f32 "
        "{%0,%1,%2,%3}, {%4,%5,%6,%7}, {%8,%9}, {%0,%1,%2,%3};\n"
        : "+f"(c[0]), "+f"(c[1]), "+f"(c[2]), "+f"(c[3])
        : "r"(a[0]), "r"(a[1]), "r"(a[2]), "r"(a[3]), "r"(b[0]), "r"(b[1]));
}

__device__ __forceinline__ void cpa16(uint32_t dst, const float* src) {
    asm volatile("cp.async.cg.shared.global [%0], [%1], 16;\n" :: "r"(dst), "l"(src));
}
__device__ __forceinline__ void cpa_commit() {
    asm volatile("cp.async.commit_group;\n" ::: "memory");
}
__device__ __forceinline__ void cpa_wait0() {
    asm volatile("cp.async.wait_group 0;\n" ::: "memory");
}

#define SMS 20
#define BUFB (128 * SMS * 4)

__global__ __launch_bounds__(256, 2)
void gemm_tf32(const float* __restrict__ A, const float* __restrict__ B,
               const float* __restrict__ bias, float* __restrict__ C,
               int M, int N, int K, int act, int outcvt)
{
    __shared__ float As[2][128][SMS];
    __shared__ float Bs[2][128][SMS];

    int tid  = threadIdx.x;
    int warp = tid >> 5, lane = tid & 31;
    int wm = (warp >> 2) * 64;
    int wn = (warp & 3) * 32;
    int grp = lane >> 2, tig = lane & 3;

    const float* Ab = A + (size_t)blockIdx.y * 128 * K;
    const float* Bb = B + (size_t)blockIdx.x * 128 * K;

    int lr = tid >> 2;
    int lc = (tid & 3) * 4;

    const float* aSrc0 = Ab + (size_t)lr * K + lc;
    const float* aSrc1 = Ab + (size_t)(lr + 64) * K + lc;
    const float* bSrc0 = Bb + (size_t)lr * K + lc;
    const float* bSrc1 = Bb + (size_t)(lr + 64) * K + lc;

    uint32_t dA0 = (uint32_t)__cvta_generic_to_shared(&As[0][lr][lc]);
    uint32_t dA1 = (uint32_t)__cvta_generic_to_shared(&As[0][lr + 64][lc]);
    uint32_t dB0 = (uint32_t)__cvta_generic_to_shared(&Bs[0][lr][lc]);
    uint32_t dB1 = (uint32_t)__cvta_generic_to_shared(&Bs[0][lr + 64][lc]);

    float acc[4][4][4];
#pragma unroll
    for (int mi = 0; mi < 4; mi++)
#pragma unroll
        for (int ni = 0; ni < 4; ni++)
#pragma unroll
            for (int r = 0; r < 4; r++) acc[mi][ni][r] = 0.0f;

    int nt = K >> 4;

    cpa16(dA0, aSrc0); cpa16(dA1, aSrc1);
    cpa16(dB0, bSrc0); cpa16(dB1, bSrc1);
    cpa_commit();

    for (int j = 0; j < nt; j++) {
        cpa_wait0();
        __syncthreads();

        if (j + 1 < nt) {
            uint32_t o = ((j + 1) & 1) * BUFB;
            int ko = (j + 1) << 4;
            cpa16(dA0 + o, aSrc0 + ko); cpa16(dA1 + o, aSrc1 + ko);
            cpa16(dB0 + o, bSrc0 + ko); cpa16(dB1 + o, bSrc1 + ko);
            cpa_commit();
        }

        int buf = j & 1;
#pragma unroll
        for (int ks = 0; ks < 2; ks++) {
            int kb = ks * 8;
            uint32_t af[4][4], bf[4][2];
#pragma unroll
            for (int mi = 0; mi < 4; mi++) {
                int r = wm + mi * 16 + grp;
                af[mi][0] = __float_as_uint(As[buf][r    ][kb + tig]);
                af[mi][1] = __float_as_uint(As[buf][r + 8][kb + tig]);
                af[mi][2] = __float_as_uint(As[buf][r    ][kb + tig + 4]);
                af[mi][3] = __float_as_uint(As[buf][r + 8][kb + tig + 4]);
            }
#pragma unroll
            for (int ni = 0; ni < 4; ni++) {
                int c = wn + ni * 8 + grp;
                bf[ni][0] = __float_as_uint(Bs[buf][c][kb + tig]);
                bf[ni][1] = __float_as_uint(Bs[buf][c][kb + tig + 4]);
            }
#pragma unroll
            for (int mi = 0; mi < 4; mi++)
#pragma unroll
                for (int ni = 0; ni < 4; ni++)
                    mma_tf32(acc[mi][ni], af[mi], bf[ni]);
        }
        __syncthreads();
    }

#pragma unroll
    for (int mi = 0; mi < 4; mi++) {
        int r0 = blockIdx.y * 128 + wm + mi * 16 + grp;
#pragma unroll
        for (int ni = 0; ni < 4; ni++) {
            int c = blockIdx.x * 128 + wn + ni * 8 + tig * 2;
            float bv0 = bias[c], bv1 = bias[c + 1];
            float v0 = acc[mi][ni][0] + bv0;
            float v1 = acc[mi][ni][1] + bv1;
            float v2 = acc[mi][ni][2] + bv0;
            float v3 = acc[mi][ni][3] + bv1;
            if (act == 1) {
                v0 = gelu_exact(v0); v1 = gelu_exact(v1);
                v2 = gelu_exact(v2); v3 = gelu_exact(v3);
            }
            if (outcvt) {
                v0 = f2tf32f(v0); v1 = f2tf32f(v1);
                v2 = f2tf32f(v2); v3 = f2tf32f(v3);
            }
            float2 p0 = {v0, v1}, p1 = {v2, v3};
            *(float2*)(C + (size_t)r0 * N + c) = p0;
            *(float2*)(C + (size_t)(r0 + 8) * N + c) = p1;
        }
    }
}

// ---------------------------------------------------------------------------
// Windowed attention; output written as tf32 bits (consumer is a GEMM).
// ---------------------------------------------------------------------------
__global__ __launch_bounds__(64)
void attn_kernel(const float* __restrict__ qkv, float* __restrict__ att)
{
    __shared__ float Ks[64][33];
    __shared__ float Vs[64][33];
    __shared__ float Ss[64][65];

    int w = blockIdx.x;
    int h = blockIdx.y;
    int r = threadIdx.x;

    const float* qrow = qkv + (size_t)w * 64 * DQKV + (size_t)r * DQKV + h * 32;

    float q[32];
#pragma unroll
    for (int d4 = 0; d4 < 32; d4 += 4) {
        float4 qv = *(const float4*)(qrow + d4);
        q[d4 + 0] = qv.x * 0.17677669529663687f;
        q[d4 + 1] = qv.y * 0.17677669529663687f;
        q[d4 + 2] = qv.z * 0.17677669529663687f;
        q[d4 + 3] = qv.w * 0.17677669529663687f;
#pragma unroll
        for (int j = 0; j < 4; j++) {
            Ks[r][d4 + j] = qrow[256 + d4 + j];
            Vs[r][d4 + j] = qrow[512 + d4 + j];
        }
    }
    __syncthreads();

    float mx = -1e30f;
    for (int c = 0; c < 64; c++) {
        float acc = 0.0f;
#pragma unroll
        for (int d = 0; d < 32; d++) acc = fmaf(q[d], Ks[c][d], acc);
        Ss[r][c] = acc;
        mx = fmaxf(mx, acc);
    }
    float sum = 0.0f;
    for (int c = 0; c < 64; c++) {
        float e = expf(Ss[r][c] - mx);
        Ss[r][c] = e;
        sum += e;
    }
    float inv = 1.0f / sum;

    float o[32];
#pragma unroll
    for (int d = 0; d < 32; d++) o[d] = 0.0f;
    for (int c = 0; c < 64; c++) {
        float p = Ss[r][c] * inv;
#pragma unroll
        for (int d = 0; d < 32; d++) o[d] = fmaf(p, Vs[c][d], o[d]);
    }

    float* obp = att + (size_t)(w * 64 + r) * DMODEL + h * 32;
#pragma unroll
    for (int d4 = 0; d4 < 32; d4 += 4) {
        float4 ov = {f2tf32f(o[d4]), f2tf32f(o[d4 + 1]),
                     f2tf32f(o[d4 + 2]), f2tf32f(o[d4 + 3])};
        *(float4*)(obp + d4) = ov;
    }
}

// ---------------------------------------------------------------------------
// Fused residual + LayerNorm, warp-per-token: x = LN(x+res)*s + b.
// Writes fp32 (x) and tf32 (xt). Block 256 = 8 tokens. Grid T/8.
// ---------------------------------------------------------------------------
__global__ __launch_bounds__(256)
void add_ln(float* __restrict__ x, float* __restrict__ xt,
            const float* __restrict__ res,
            const float* __restrict__ s, const float* __restrict__ b)
{
    int warp = threadIdx.x >> 5, lane = threadIdx.x & 31;
    int t = blockIdx.x * 8 + warp;
    size_t base = (size_t)t * DMODEL + lane * 8;

    float4 v0 = *(const float4*)(x + base);
    float4 v1 = *(const float4*)(x + base + 4);
    float4 r0 = *(const float4*)(res + base);
    float4 r1 = *(const float4*)(res + base + 4);
    float v[8] = {v0.x + r0.x, v0.y + r0.y, v0.z + r0.z, v0.w + r0.w,
                  v1.x + r1.x, v1.y + r1.y, v1.z + r1.z, v1.w + r1.w};

    float sum = 0.0f;
#pragma unroll
    for (int i = 0; i < 8; i++) sum += v[i];
#pragma unroll
    for (int o = 16; o > 0; o >>= 1) sum += __shfl_xor_sync(0xffffffffu, sum, o);
    float m = sum * (1.0f / 256.0f);

    float vs = 0.0f;
#pragma unroll
    for (int i = 0; i < 8; i++) { float d = v[i] - m; vs += d * d; }
#pragma unroll
    for (int o = 16; o > 0; o >>= 1) vs += __shfl_xor_sync(0xffffffffu, vs, o);
    float rstd = rsqrtf(vs * (1.0f / 256.0f) + 1e-5f);

    float4 sv0 = *(const float4*)(s + lane * 8);
    float4 sv1 = *(const float4*)(s + lane * 8 + 4);
    float4 bv0 = *(const float4*)(b + lane * 8);
    float4 bv1 = *(const float4*)(b + lane * 8 + 4);
    float sc[8] = {sv0.x, sv0.y, sv0.z, sv0.w, sv1.x, sv1.y, sv1.z, sv1.w};
    float bi[8] = {bv0.x, bv0.y, bv0.z, bv0.w, bv1.x, bv1.y, bv1.z, bv1.w};

    float o_[8];
#pragma unroll
    for (int i = 0; i < 8; i++) o_[i] = (v[i] - m) * rstd * sc[i] + bi[i];

    float4 w0 = {o_[0], o_[1], o_[2], o_[3]};
    float4 w1 = {o_[4], o_[5], o_[6], o_[7]};
    *(float4*)(x + base) = w0;
    *(float4*)(x + base + 4) = w1;
    float4 c0 = {f2tf32f(o_[0]), f2tf32f(o_[1]), f2tf32f(o_[2]), f2tf32f(o_[3])};
    float4 c1 = {f2tf32f(o_[4]), f2tf32f(o_[5]), f2tf32f(o_[6]), f2tf32f(o_[7])};
    *(float4*)(xt + base) = c0;
    *(float4*)(xt + base + 4) = c1;
}

// ---------------------------------------------------------------------------
// Final LN + transpose back to [B, C, H*W]. Warp-per-token.
// ---------------------------------------------------------------------------
__global__ __launch_bounds__(256)
void final_ln(const float* __restrict__ x, const float* __restrict__ s,
              const float* __restrict__ b, float* __restrict__ out)
{
    int warp = threadIdx.x >> 5, lane = threadIdx.x & 31;
    int t = blockIdx.x * 8 + warp;
    size_t base = (size_t)t * DMODEL + lane * 8;

    float4 v0 = *(const float4*)(x + base);
    float4 v1 = *(const float4*)(x + base + 4);
    float v[8] = {v0.x, v0.y, v0.z, v0.w, v1.x, v1.y, v1.z, v1.w};

    float sum = 0.0f;
#pragma unroll
    for (int i = 0; i < 8; i++) sum += v[i];
#pragma unroll
    for (int o = 16; o > 0; o >>= 1) sum += __shfl_xor_sync(0xffffffffu, sum, o);
    float m = sum * (1.0f / 256.0f);

    float vs = 0.0f;
#pragma unroll
    for (int i = 0; i < 8; i++) { float d = v[i] - m; vs += d * d; }
#pragma unroll
    for (int o = 16; o > 0; o >>= 1) vs += __shfl_xor_sync(0xffffffffu, vs, o);
    float rstd = rsqrtf(vs * (1.0f / 256.0f) + 1e-5f);

    int bidx = t >> 10, l = t & 1023;
    int d0 = lane * 8;
#pragma unroll
    for (int i = 0; i < 8; i++) {
        float val = (v[i] - m) * rstd * s[d0 + i] + b[d0 + i];
        out[((size_t)bidx * DMODEL + d0 + i) * 1024 + l] = val;
    }
}

// ---------------------------------------------------------------------------
extern "C" void kernel_launch(void* const* d_in, const int* in_sizes, int n_in,
                              void* d_out, int out_size)
{
    const float* features = (const float*)d_in[0];
    const float* in_w  = (const float*)d_in[1];
    const float* in_b  = (const float*)d_in[2];
    const float* ow    = (const float*)d_in[3];
    const float* ob    = (const float*)d_in[4];
    const float* w1    = (const float*)d_in[5];
    const float* b1    = (const float*)d_in[6];
    const float* w2    = (const float*)d_in[7];
    const float* b2    = (const float*)d_in[8];
    const float* ln1s  = (const float*)d_in[9];
    const float* ln1b  = (const float*)d_in[10];
    const float* ln2s  = (const float*)d_in[11];
    const float* ln2b  = (const float*)d_in[12];
    const float* fns   = (const float*)d_in[13];
    const float* fnb   = (const float*)d_in[14];
    float* out = (float*)d_out;

    float *x, *xt, *qkv, *att, *tmp, *hh, *wt;
    cudaGetSymbolAddress((void**)&x,   g_x);
    cudaGetSymbolAddress((void**)&xt,  g_xt);
    cudaGetSymbolAddress((void**)&qkv, g_qkv);
    cudaGetSymbolAddress((void**)&att, g_att);
    cudaGetSymbolAddress((void**)&tmp, g_tmp);
    cudaGetSymbolAddress((void**)&hh,  g_h);
    cudaGetSymbolAddress((void**)&wt,  g_wt);

    // Pre-convert all weights to tf32 bit patterns
    {
        int n;
        n = 3 * DQKV * DMODEL / 4;
        cvt_kernel<<<(n + 255) / 256, 256>>>(in_w, wt + WT_INW, n);
        n = 3 * DMODEL * DMODEL / 4;
        cvt_kernel<<<(n + 255) / 256, 256>>>(ow, wt + WT_OW, n);
        n = 3 * DFFN * DMODEL / 4;
        cvt_kernel<<<(n + 255) / 256, 256>>>(w1, wt + WT_W1, n);
        n = 3 * DMODEL * DFFN / 4;
        cvt_kernel<<<(n + 255) / 256, 256>>>(w2, wt + WT_W2, n);
    }

    dim3 eb(32, 32);
    dim3 eg(32, 8, 32);
    embed_kernel<<<eg, eb>>>(features, x, xt);

    const int T = T_TOK;
    for (int i = 0; i < 3; i++) {
        gemm_tf32<<<dim3(DQKV / 128, T / 128), 256>>>(
            xt, wt + WT_INW + (size_t)i * DQKV * DMODEL, in_b + (size_t)i * DQKV,
            qkv, T, DQKV, DMODEL, 0, 0);
        attn_kernel<<<dim3(512, 8), 64>>>(qkv, att);
        gemm_tf32<<<dim3(DMODEL / 128, T / 128), 256>>>(
            att, wt + WT_OW + (size_t)i * DMODEL * DMODEL, ob + (size_t)i * DMODEL,
            tmp, T, DMODEL, DMODEL, 0, 0);
        add_ln<<<T / 8, 256>>>(x, xt, tmp,
                               ln1s + (size_t)i * DMODEL, ln1b + (size_t)i * DMODEL);
        gemm_tf32<<<dim3(DFFN / 128, T / 128), 256>>>(
            xt, wt + WT_W1 + (size_t)i * DFFN * DMODEL, b1 + (size_t)i * DFFN,
            hh, T, DFFN, DMODEL, 1, 1);
        gemm_tf32<<<dim3(DMODEL / 128, T / 128), 256>>>(
            hh, wt + WT_W2 + (size_t)i * DMODEL * DFFN, b2 + (size_t)i * DMODEL,
            tmp, T, DMODEL, DFFN, 0, 0);
        add_ln<<<T / 8, 256>>>(x, xt, tmp,
                               ln2s + (size_t)i * DMODEL, ln2b + (size_t)i * DMODEL);
    }
    final_ln<<<T / 8, 256>>>(x, fns, fnb, out);
}

// round 5
// speedup vs baseline: 3.1304x; 1.2792x over previous
#include <cuda_runtime.h>
#include <cuda_bf16.h>
#include <math.h>
#include <stdint.h>

// ---------------------------------------------------------------------------
// EfficientTransformerEncoder: B=32, D=256, H=W=32 -> L=1024, NH=8 (dh=32),
// NL=3, DFF=1024, WIN=64. bf16 tensor-core GEMMs (fp32 accum), fp32 elsewhere.
// ---------------------------------------------------------------------------

#define T_TOK   32768
#define DMODEL  256
#define DQKV    768
#define DFFN    1024

__device__ float          g_x  [(size_t)T_TOK * DMODEL];  // fp32 residual
__device__ __nv_bfloat16  g_xb [(size_t)T_TOK * DMODEL];  // bf16 copy of x
__device__ float          g_qkv[(size_t)T_TOK * DQKV];    // fp32 (attn reads)
__device__ __nv_bfloat16  g_att[(size_t)T_TOK * DMODEL];  // bf16 (gemm reads)
__device__ float          g_tmp[(size_t)T_TOK * DMODEL];  // fp32 (add_ln reads)
__device__ __nv_bfloat16  g_h  [(size_t)T_TOK * DFFN];    // bf16 (gemm reads)

// bf16-converted weights: [in_w | ow | w1 | w2]
#define WT_INW 0
#define WT_OW  (WT_INW + 3 * DQKV * DMODEL)
#define WT_W1  (WT_OW  + 3 * DMODEL * DMODEL)
#define WT_W2  (WT_W1  + 3 * DFFN * DMODEL)
#define WT_TOT (WT_W2  + 3 * DMODEL * DFFN)
__device__ __nv_bfloat16 g_wb[WT_TOT];

// ---------------------------------------------------------------------------
// Elementwise fp32 -> bf16 converter (weights). n4 = n/4.
// ---------------------------------------------------------------------------
__global__ void cvt_kernel(const float* __restrict__ src,
                           __nv_bfloat16* __restrict__ dst, int n4) {
    int i = blockIdx.x * blockDim.x + threadIdx.x;
    if (i >= n4) return;
    float4 v = ((const float4*)src)[i];
    __nv_bfloat162 lo = {__float2bfloat16_rn(v.x), __float2bfloat16_rn(v.y)};
    __nv_bfloat162 hi = {__float2bfloat16_rn(v.z), __float2bfloat16_rn(v.w)};
    ((__nv_bfloat162*)dst)[i * 2]     = lo;
    ((__nv_bfloat162*)dst)[i * 2 + 1] = hi;
}

// ---------------------------------------------------------------------------
// Embed: x[b,l,d] = features[b,d,l] + PE(l,d); fp32 + bf16 copies.
// ---------------------------------------------------------------------------
__device__ __forceinline__ float pe_val(int l, int d) {
    int i = d >> 1;
    float freq = expf(-(float)(2 * i) * 0.0359778920439f);
    float ang = (float)l * freq;
    return (d & 1) ? cosf(ang) : sinf(ang);
}

__global__ void embed_kernel(const float* __restrict__ f,
                             float* __restrict__ x, __nv_bfloat16* __restrict__ xb) {
    __shared__ float tile[32][33];
    int b  = blockIdx.z;
    int l0 = blockIdx.x * 32, d0 = blockIdx.y * 32;
    int tx = threadIdx.x, ty = threadIdx.y;
    tile[ty][tx] = f[((size_t)b * DMODEL + d0 + ty) * 1024 + l0 + tx];
    __syncthreads();
    int l = l0 + ty, d = d0 + tx;
    float v = tile[tx][ty] + pe_val(l, d);
    size_t idx = ((size_t)b * 1024 + l) * DMODEL + d;
    x[idx]  = v;
    xb[idx] = __float2bfloat16_rn(v);
}

// ---------------------------------------------------------------------------
// bf16 NT GEMM, cp.async double-buffered, k-tile 32.
// C[M,N] = A[M,K]*B[N,K]^T + bias[N]; act=1 -> exact GELU;
// outbf=1 -> write bf16 into Cb, else fp32 into Cf.
// Block 128x128x32, 256 threads (2x4 warps), warp tile 64x32.
// mma.sync.aligned.m16n8k16.row.col.f32.bf16.bf16.f32
// ---------------------------------------------------------------------------
__device__ __forceinline__ float gelu_exact(float v) {
    return 0.5f * v * (1.0f + erff(v * 0.7071067811865476f));
}

__device__ __forceinline__ void mma_bf16(float c[4], const uint32_t a[4], const uint32_t b[2]) {
    asm volatile(
        "mma.sync.aligned.m16n8k16.row.col.f32.bf16.bf16.f32 "
        "{%0,%1,%2,%3}, {%4,%5,%6,%7}, {%8,%9}, {%0,%1,%2,%3};\n"
        : "+f"(c[0]), "+f"(c[1]), "+f"(c[2]), "+f"(c[3])
        : "r"(a[0]), "r"(a[1]), "r"(a[2]), "r"(a[3]), "r"(b[0]), "r"(b[1]));
}

__device__ __forceinline__ void cpa16(uint32_t dst, const void* src) {
    asm volatile("cp.async.cg.shared.global [%0], [%1], 16;\n" :: "r"(dst), "l"(src));
}
__device__ __forceinline__ void cpa_commit() {
    asm volatile("cp.async.commit_group;\n" ::: "memory");
}
__device__ __forceinline__ void cpa_wait0() {
    asm volatile("cp.async.wait_group 0;\n" ::: "memory");
}

// smem row: 32 bf16 data + 8 pad = 40 bf16 (80 B). Word stride 20:
// 20*grp mod 32 = {0,20,8,28,16,4,24,12} all distinct -> conflict-free frags.
#define SMH 40
#define BUFB (128 * SMH * 2)   // bytes per buffer per matrix

__global__ __launch_bounds__(256, 2)
void gemm_bf16(const __nv_bfloat16* __restrict__ A, const __nv_bfloat16* __restrict__ B,
               const float* __restrict__ bias, float* __restrict__ Cf,
               __nv_bfloat16* __restrict__ Cb,
               int M, int N, int K, int act, int outbf)
{
    __shared__ __nv_bfloat16 As[2][128][SMH];
    __shared__ __nv_bfloat16 Bs[2][128][SMH];

    int tid  = threadIdx.x;
    int warp = tid >> 5, lane = tid & 31;
    int wm = (warp >> 2) * 64;
    int wn = (warp & 3) * 32;
    int grp = lane >> 2, tig = lane & 3;

    const __nv_bfloat16* Ab = A + (size_t)blockIdx.y * 128 * K;
    const __nv_bfloat16* Bb = B + (size_t)blockIdx.x * 128 * K;

    // load mapping: 512 16B-chunks per matrix per k32 tile, 2 per thread.
    int r0c = tid >> 1;                 // rows tid/2 (chunk set 0: rows 0..127, sub 0..1)
    int s0  = (tid & 1) * 8;            // bf16 offset within row (sub*8)
    // chunk set 1: sub 2..3
    int s1  = s0 + 16;

    const __nv_bfloat16* aS0 = Ab + (size_t)r0c * K + s0;
    const __nv_bfloat16* aS1 = Ab + (size_t)r0c * K + s1;
    const __nv_bfloat16* bS0 = Bb + (size_t)r0c * K + s0;
    const __nv_bfloat16* bS1 = Bb + (size_t)r0c * K + s1;

    uint32_t dA0 = (uint32_t)__cvta_generic_to_shared(&As[0][r0c][s0]);
    uint32_t dA1 = (uint32_t)__cvta_generic_to_shared(&As[0][r0c][s1]);
    uint32_t dB0 = (uint32_t)__cvta_generic_to_shared(&Bs[0][r0c][s0]);
    uint32_t dB1 = (uint32_t)__cvta_generic_to_shared(&Bs[0][r0c][s1]);

    float acc[4][4][4];
#pragma unroll
    for (int mi = 0; mi < 4; mi++)
#pragma unroll
        for (int ni = 0; ni < 4; ni++)
#pragma unroll
            for (int r = 0; r < 4; r++) acc[mi][ni][r] = 0.0f;

    int nt = K >> 5;   // k32 tiles

    cpa16(dA0, aS0); cpa16(dA1, aS1);
    cpa16(dB0, bS0); cpa16(dB1, bS1);
    cpa_commit();

    for (int j = 0; j < nt; j++) {
        cpa_wait0();
        __syncthreads();

        if (j + 1 < nt) {
            uint32_t o = ((j + 1) & 1) * BUFB;
            int ko = (j + 1) << 5;
            cpa16(dA0 + o, aS0 + ko); cpa16(dA1 + o, aS1 + ko);
            cpa16(dB0 + o, bS0 + ko); cpa16(dB1 + o, bS1 + ko);
            cpa_commit();
        }

        int buf = j & 1;
#pragma unroll
        for (int ks = 0; ks < 2; ks++) {
            int kb = ks * 16;            // bf16 offset of this k16 step
            uint32_t af[4][4], bf[4][2];
#pragma unroll
            for (int mi = 0; mi < 4; mi++) {
                int r = wm + mi * 16 + grp;
                af[mi][0] = *(const uint32_t*)(&As[buf][r    ][kb + tig * 2]);
                af[mi][1] = *(const uint32_t*)(&As[buf][r + 8][kb + tig * 2]);
                af[mi][2] = *(const uint32_t*)(&As[buf][r    ][kb + tig * 2 + 8]);
                af[mi][3] = *(const uint32_t*)(&As[buf][r + 8][kb + tig * 2 + 8]);
            }
#pragma unroll
            for (int ni = 0; ni < 4; ni++) {
                int c = wn + ni * 8 + grp;
                bf[ni][0] = *(const uint32_t*)(&Bs[buf][c][kb + tig * 2]);
                bf[ni][1] = *(const uint32_t*)(&Bs[buf][c][kb + tig * 2 + 8]);
            }
#pragma unroll
            for (int mi = 0; mi < 4; mi++)
#pragma unroll
                for (int ni = 0; ni < 4; ni++)
                    mma_bf16(acc[mi][ni], af[mi], bf[ni]);
        }
        __syncthreads();
    }

    // Epilogue: bias (+ GELU); fp32 or bf16 out.
#pragma unroll
    for (int mi = 0; mi < 4; mi++) {
        int r0 = blockIdx.y * 128 + wm + mi * 16 + grp;
#pragma unroll
        for (int ni = 0; ni < 4; ni++) {
            int c = blockIdx.x * 128 + wn + ni * 8 + tig * 2;
            float bv0 = bias[c], bv1 = bias[c + 1];
            float v0 = acc[mi][ni][0] + bv0;
            float v1 = acc[mi][ni][1] + bv1;
            float v2 = acc[mi][ni][2] + bv0;
            float v3 = acc[mi][ni][3] + bv1;
            if (act == 1) {
                v0 = gelu_exact(v0); v1 = gelu_exact(v1);
                v2 = gelu_exact(v2); v3 = gelu_exact(v3);
            }
            if (outbf) {
                __nv_bfloat162 p0 = {__float2bfloat16_rn(v0), __float2bfloat16_rn(v1)};
                __nv_bfloat162 p1 = {__float2bfloat16_rn(v2), __float2bfloat16_rn(v3)};
                *(__nv_bfloat162*)(Cb + (size_t)r0 * N + c) = p0;
                *(__nv_bfloat162*)(Cb + (size_t)(r0 + 8) * N + c) = p1;
            } else {
                float2 p0 = {v0, v1}, p1 = {v2, v3};
                *(float2*)(Cf + (size_t)r0 * N + c) = p0;
                *(float2*)(Cf + (size_t)(r0 + 8) * N + c) = p1;
            }
        }
    }
}

// ---------------------------------------------------------------------------
// Windowed attention (fp32 math); output written as bf16 (consumer is a GEMM).
// ---------------------------------------------------------------------------
__global__ __launch_bounds__(64)
void attn_kernel(const float* __restrict__ qkv, __nv_bfloat16* __restrict__ att)
{
    __shared__ float Ks[64][33];
    __shared__ float Vs[64][33];
    __shared__ float Ss[64][65];

    int w = blockIdx.x;
    int h = blockIdx.y;
    int r = threadIdx.x;

    const float* qrow = qkv + (size_t)w * 64 * DQKV + (size_t)r * DQKV + h * 32;

    float q[32];
#pragma unroll
    for (int d4 = 0; d4 < 32; d4 += 4) {
        float4 qv = *(const float4*)(qrow + d4);
        q[d4 + 0] = qv.x * 0.17677669529663687f;
        q[d4 + 1] = qv.y * 0.17677669529663687f;
        q[d4 + 2] = qv.z * 0.17677669529663687f;
        q[d4 + 3] = qv.w * 0.17677669529663687f;
#pragma unroll
        for (int j = 0; j < 4; j++) {
            Ks[r][d4 + j] = qrow[256 + d4 + j];
            Vs[r][d4 + j] = qrow[512 + d4 + j];
        }
    }
    __syncthreads();

    float mx = -1e30f;
    for (int c = 0; c < 64; c++) {
        float acc = 0.0f;
#pragma unroll
        for (int d = 0; d < 32; d++) acc = fmaf(q[d], Ks[c][d], acc);
        Ss[r][c] = acc;
        mx = fmaxf(mx, acc);
    }
    float sum = 0.0f;
    for (int c = 0; c < 64; c++) {
        float e = expf(Ss[r][c] - mx);
        Ss[r][c] = e;
        sum += e;
    }
    float inv = 1.0f / sum;

    float o[32];
#pragma unroll
    for (int d = 0; d < 32; d++) o[d] = 0.0f;
    for (int c = 0; c < 64; c++) {
        float p = Ss[r][c] * inv;
#pragma unroll
        for (int d = 0; d < 32; d++) o[d] = fmaf(p, Vs[c][d], o[d]);
    }

    __nv_bfloat16* obp = att + (size_t)(w * 64 + r) * DMODEL + h * 32;
#pragma unroll
    for (int d2 = 0; d2 < 32; d2 += 2) {
        __nv_bfloat162 ov = {__float2bfloat16_rn(o[d2]), __float2bfloat16_rn(o[d2 + 1])};
        *(__nv_bfloat162*)(obp + d2) = ov;
    }
}

// ---------------------------------------------------------------------------
// Fused residual + LayerNorm, warp-per-token; writes fp32 x + bf16 xb.
// ---------------------------------------------------------------------------
__global__ __launch_bounds__(256)
void add_ln(float* __restrict__ x, __nv_bfloat16* __restrict__ xb,
            const float* __restrict__ res,
            const float* __restrict__ s, const float* __restrict__ b)
{
    int warp = threadIdx.x >> 5, lane = threadIdx.x & 31;
    int t = blockIdx.x * 8 + warp;
    size_t base = (size_t)t * DMODEL + lane * 8;

    float4 v0 = *(const float4*)(x + base);
    float4 v1 = *(const float4*)(x + base + 4);
    float4 r0 = *(const float4*)(res + base);
    float4 r1 = *(const float4*)(res + base + 4);
    float v[8] = {v0.x + r0.x, v0.y + r0.y, v0.z + r0.z, v0.w + r0.w,
                  v1.x + r1.x, v1.y + r1.y, v1.z + r1.z, v1.w + r1.w};

    float sum = 0.0f;
#pragma unroll
    for (int i = 0; i < 8; i++) sum += v[i];
#pragma unroll
    for (int o = 16; o > 0; o >>= 1) sum += __shfl_xor_sync(0xffffffffu, sum, o);
    float m = sum * (1.0f / 256.0f);

    float vs = 0.0f;
#pragma unroll
    for (int i = 0; i < 8; i++) { float d = v[i] - m; vs += d * d; }
#pragma unroll
    for (int o = 16; o > 0; o >>= 1) vs += __shfl_xor_sync(0xffffffffu, vs, o);
    float rstd = rsqrtf(vs * (1.0f / 256.0f) + 1e-5f);

    float4 sv0 = *(const float4*)(s + lane * 8);
    float4 sv1 = *(const float4*)(s + lane * 8 + 4);
    float4 bv0 = *(const float4*)(b + lane * 8);
    float4 bv1 = *(const float4*)(b + lane * 8 + 4);
    float sc[8] = {sv0.x, sv0.y, sv0.z, sv0.w, sv1.x, sv1.y, sv1.z, sv1.w};
    float bi[8] = {bv0.x, bv0.y, bv0.z, bv0.w, bv1.x, bv1.y, bv1.z, bv1.w};

    float o_[8];
#pragma unroll
    for (int i = 0; i < 8; i++) o_[i] = (v[i] - m) * rstd * sc[i] + bi[i];

    float4 w0 = {o_[0], o_[1], o_[2], o_[3]};
    float4 w1 = {o_[4], o_[5], o_[6], o_[7]};
    *(float4*)(x + base) = w0;
    *(float4*)(x + base + 4) = w1;
#pragma unroll
    for (int i = 0; i < 8; i += 2) {
        __nv_bfloat162 c2 = {__float2bfloat16_rn(o_[i]), __float2bfloat16_rn(o_[i + 1])};
        *(__nv_bfloat162*)(xb + base + i) = c2;
    }
}

// ---------------------------------------------------------------------------
// Final LN + transpose back to [B, C, H*W]. Warp-per-token.
// ---------------------------------------------------------------------------
__global__ __launch_bounds__(256)
void final_ln(const float* __restrict__ x, const float* __restrict__ s,
              const float* __restrict__ b, float* __restrict__ out)
{
    int warp = threadIdx.x >> 5, lane = threadIdx.x & 31;
    int t = blockIdx.x * 8 + warp;
    size_t base = (size_t)t * DMODEL + lane * 8;

    float4 v0 = *(const float4*)(x + base);
    float4 v1 = *(const float4*)(x + base + 4);
    float v[8] = {v0.x, v0.y, v0.z, v0.w, v1.x, v1.y, v1.z, v1.w};

    float sum = 0.0f;
#pragma unroll
    for (int i = 0; i < 8; i++) sum += v[i];
#pragma unroll
    for (int o = 16; o > 0; o >>= 1) sum += __shfl_xor_sync(0xffffffffu, sum, o);
    float m = sum * (1.0f / 256.0f);

    float vs = 0.0f;
#pragma unroll
    for (int i = 0; i < 8; i++) { float d = v[i] - m; vs += d * d; }
#pragma unroll
    for (int o = 16; o > 0; o >>= 1) vs += __shfl_xor_sync(0xffffffffu, vs, o);
    float rstd = rsqrtf(vs * (1.0f / 256.0f) + 1e-5f);

    int bidx = t >> 10, l = t & 1023;
    int d0 = lane * 8;
#pragma unroll
    for (int i = 0; i < 8; i++) {
        float val = (v[i] - m) * rstd * s[d0 + i] + b[d0 + i];
        out[((size_t)bidx * DMODEL + d0 + i) * 1024 + l] = val;
    }
}

// ---------------------------------------------------------------------------
extern "C" void kernel_launch(void* const* d_in, const int* in_sizes, int n_in,
                              void* d_out, int out_size)
{
    const float* features = (const float*)d_in[0];
    const float* in_w  = (const float*)d_in[1];
    const float* in_b  = (const float*)d_in[2];
    const float* ow    = (const float*)d_in[3];
    const float* ob    = (const float*)d_in[4];
    const float* w1    = (const float*)d_in[5];
    const float* b1    = (const float*)d_in[6];
    const float* w2    = (const float*)d_in[7];
    const float* b2    = (const float*)d_in[8];
    const float* ln1s  = (const float*)d_in[9];
    const float* ln1b  = (const float*)d_in[10];
    const float* ln2s  = (const float*)d_in[11];
    const float* ln2b  = (const float*)d_in[12];
    const float* fns   = (const float*)d_in[13];
    const float* fnb   = (const float*)d_in[14];
    float* out = (float*)d_out;

    float *x, *qkv, *tmp;
    __nv_bfloat16 *xb, *att, *hh, *wb;
    cudaGetSymbolAddress((void**)&x,   g_x);
    cudaGetSymbolAddress((void**)&xb,  g_xb);
    cudaGetSymbolAddress((void**)&qkv, g_qkv);
    cudaGetSymbolAddress((void**)&att, g_att);
    cudaGetSymbolAddress((void**)&tmp, g_tmp);
    cudaGetSymbolAddress((void**)&hh,  g_h);
    cudaGetSymbolAddress((void**)&wb,  g_wb);

    // Pre-convert all weights to bf16
    {
        int n;
        n = 3 * DQKV * DMODEL / 4;
        cvt_kernel<<<(n + 255) / 256, 256>>>(in_w, wb + WT_INW, n);
        n = 3 * DMODEL * DMODEL / 4;
        cvt_kernel<<<(n + 255) / 256, 256>>>(ow, wb + WT_OW, n);
        n = 3 * DFFN * DMODEL / 4;
        cvt_kernel<<<(n + 255) / 256, 256>>>(w1, wb + WT_W1, n);
        n = 3 * DMODEL * DFFN / 4;
        cvt_kernel<<<(n + 255) / 256, 256>>>(w2, wb + WT_W2, n);
    }

    dim3 eb(32, 32);
    dim3 eg(32, 8, 32);
    embed_kernel<<<eg, eb>>>(features, x, xb);

    const int T = T_TOK;
    for (int i = 0; i < 3; i++) {
        gemm_bf16<<<dim3(DQKV / 128, T / 128), 256>>>(
            xb, wb + WT_INW + (size_t)i * DQKV * DMODEL, in_b + (size_t)i * DQKV,
            qkv, nullptr, T, DQKV, DMODEL, 0, 0);
        attn_kernel<<<dim3(512, 8), 64>>>(qkv, att);
        gemm_bf16<<<dim3(DMODEL / 128, T / 128), 256>>>(
            att, wb + WT_OW + (size_t)i * DMODEL * DMODEL, ob + (size_t)i * DMODEL,
            tmp, nullptr, T, DMODEL, DMODEL, 0, 0);
        add_ln<<<T / 8, 256>>>(x, xb, tmp,
                               ln1s + (size_t)i * DMODEL, ln1b + (size_t)i * DMODEL);
        gemm_bf16<<<dim3(DFFN / 128, T / 128), 256>>>(
            xb, wb + WT_W1 + (size_t)i * DFFN * DMODEL, b1 + (size_t)i * DFFN,
            nullptr, hh, T, DFFN, DMODEL, 1, 1);
        gemm_bf16<<<dim3(DMODEL / 128, T / 128), 256>>>(
            hh, wb + WT_W2 + (size_t)i * DMODEL * DFFN, b2 + (size_t)i * DMODEL,
            tmp, nullptr, T, DMODEL, DFFN, 0, 0);
        add_ln<<<T / 8, 256>>>(x, xb, tmp,
                               ln2s + (size_t)i * DMODEL, ln2b + (size_t)i * DMODEL);
    }
    final_ln<<<T / 8, 256>>>(x, fns, fnb, out);
}

// round 6
// speedup vs baseline: 3.3135x; 1.0585x over previous
#include <cuda_runtime.h>
#include <cuda_bf16.h>
#include <math.h>
#include <stdint.h>

// ---------------------------------------------------------------------------
// EfficientTransformerEncoder: B=32, D=256, H=W=32 -> L=1024, NH=8 (dh=32),
// NL=3, DFF=1024, WIN=64. bf16 tensor-core GEMMs (ldmatrix + cp.async).
// ---------------------------------------------------------------------------

#define T_TOK   32768
#define DMODEL  256
#define DQKV    768
#define DFFN    1024

__device__ float          g_x  [(size_t)T_TOK * DMODEL];  // fp32 residual
__device__ __nv_bfloat16  g_xb [(size_t)T_TOK * DMODEL];  // bf16 copy of x
__device__ float          g_qkv[(size_t)T_TOK * DQKV];    // fp32 (attn reads)
__device__ __nv_bfloat16  g_att[(size_t)T_TOK * DMODEL];  // bf16 (gemm reads)
__device__ float          g_tmp[(size_t)T_TOK * DMODEL];  // fp32 (add_ln reads)
__device__ __nv_bfloat16  g_h  [(size_t)T_TOK * DFFN];    // bf16 (gemm reads)

// bf16-converted weights: [in_w | ow | w1 | w2]
#define WT_INW 0
#define WT_OW  (WT_INW + 3 * DQKV * DMODEL)
#define WT_W1  (WT_OW  + 3 * DMODEL * DMODEL)
#define WT_W2  (WT_W1  + 3 * DFFN * DMODEL)
#define WT_TOT (WT_W2  + 3 * DMODEL * DFFN)
__device__ __nv_bfloat16 g_wb[WT_TOT];

// ---------------------------------------------------------------------------
__global__ void cvt_kernel(const float* __restrict__ src,
                           __nv_bfloat16* __restrict__ dst, int n4) {
    int i = blockIdx.x * blockDim.x + threadIdx.x;
    if (i >= n4) return;
    float4 v = ((const float4*)src)[i];
    __nv_bfloat162 lo = {__float2bfloat16_rn(v.x), __float2bfloat16_rn(v.y)};
    __nv_bfloat162 hi = {__float2bfloat16_rn(v.z), __float2bfloat16_rn(v.w)};
    ((__nv_bfloat162*)dst)[i * 2]     = lo;
    ((__nv_bfloat162*)dst)[i * 2 + 1] = hi;
}

// ---------------------------------------------------------------------------
// Embed: x[b,l,d] = features[b,d,l] + PE(l,d); fp32 + bf16 copies.
// ---------------------------------------------------------------------------
__device__ __forceinline__ float pe_val(int l, int d) {
    int i = d >> 1;
    float freq = expf(-(float)(2 * i) * 0.0359778920439f);
    float ang = (float)l * freq;
    return (d & 1) ? cosf(ang) : sinf(ang);
}

__global__ void embed_kernel(const float* __restrict__ f,
                             float* __restrict__ x, __nv_bfloat16* __restrict__ xb) {
    __shared__ float tile[32][33];
    int b  = blockIdx.z;
    int l0 = blockIdx.x * 32, d0 = blockIdx.y * 32;
    int tx = threadIdx.x, ty = threadIdx.y;
    tile[ty][tx] = f[((size_t)b * DMODEL + d0 + ty) * 1024 + l0 + tx];
    __syncthreads();
    int l = l0 + ty, d = d0 + tx;
    float v = tile[tx][ty] + pe_val(l, d);
    size_t idx = ((size_t)b * 1024 + l) * DMODEL + d;
    x[idx]  = v;
    xb[idx] = __float2bfloat16_rn(v);
}

// ---------------------------------------------------------------------------
// bf16 NT GEMM: cp.async double-buffered + ldmatrix fragment loads.
// Block 128x128x32, 256 threads (2x4 warps), warp tile 64x32.
// ---------------------------------------------------------------------------
__device__ __forceinline__ float gelu_exact(float v) {
    return 0.5f * v * (1.0f + erff(v * 0.7071067811865476f));
}

__device__ __forceinline__ void mma_bf16(float c[4], const uint32_t a[4], const uint32_t b[2]) {
    asm volatile(
        "mma.sync.aligned.m16n8k16.row.col.f32.bf16.bf16.f32 "
        "{%0,%1,%2,%3}, {%4,%5,%6,%7}, {%8,%9}, {%0,%1,%2,%3};\n"
        : "+f"(c[0]), "+f"(c[1]), "+f"(c[2]), "+f"(c[3])
        : "r"(a[0]), "r"(a[1]), "r"(a[2]), "r"(a[3]), "r"(b[0]), "r"(b[1]));
}

__device__ __forceinline__ void ldsm4(uint32_t& r0, uint32_t& r1, uint32_t& r2, uint32_t& r3,
                                      uint32_t addr) {
    asm volatile("ldmatrix.sync.aligned.m8n8.x4.shared.b16 {%0,%1,%2,%3}, [%4];"
                 : "=r"(r0), "=r"(r1), "=r"(r2), "=r"(r3) : "r"(addr));
}

__device__ __forceinline__ void cpa16(uint32_t dst, const void* src) {
    asm volatile("cp.async.cg.shared.global [%0], [%1], 16;\n" :: "r"(dst), "l"(src));
}
__device__ __forceinline__ void cpa_commit() {
    asm volatile("cp.async.commit_group;\n" ::: "memory");
}
__device__ __forceinline__ void cpa_wait0() {
    asm volatile("cp.async.wait_group 0;\n" ::: "memory");
}

// smem row: 32 bf16 data + 8 pad = 40 bf16 (80 B). Row word-stride 20 ->
// 8-row LDSM phases hit banks {0,20,8,28,16,4,24,12}: conflict-free.
#define SMH 40
#define ROWB (SMH * 2)          // row stride bytes
#define BUFB (128 * ROWB)       // bytes per buffer per matrix

__global__ __launch_bounds__(256, 2)
void gemm_bf16(const __nv_bfloat16* __restrict__ A, const __nv_bfloat16* __restrict__ B,
               const float* __restrict__ bias, float* __restrict__ Cf,
               __nv_bfloat16* __restrict__ Cb,
               int M, int N, int K, int act, int outbf)
{
    __shared__ __nv_bfloat16 As[2][128][SMH];
    __shared__ __nv_bfloat16 Bs[2][128][SMH];

    int tid  = threadIdx.x;
    int warp = tid >> 5, lane = tid & 31;
    int wm = (warp >> 2) * 64;
    int wn = (warp & 3) * 32;
    int grp = lane >> 2, tig = lane & 3;

    const __nv_bfloat16* Ab = A + (size_t)blockIdx.y * 128 * K;
    const __nv_bfloat16* Bb = B + (size_t)blockIdx.x * 128 * K;

    // gmem -> smem mapping: 2 chunks of 16B per thread per matrix per k32 tile
    int r0c = tid >> 1;
    int s0  = (tid & 1) * 8;
    int s1  = s0 + 16;

    const __nv_bfloat16* aS0 = Ab + (size_t)r0c * K + s0;
    const __nv_bfloat16* aS1 = Ab + (size_t)r0c * K + s1;
    const __nv_bfloat16* bS0 = Bb + (size_t)r0c * K + s0;
    const __nv_bfloat16* bS1 = Bb + (size_t)r0c * K + s1;

    uint32_t dA0 = (uint32_t)__cvta_generic_to_shared(&As[0][r0c][s0]);
    uint32_t dA1 = (uint32_t)__cvta_generic_to_shared(&As[0][r0c][s1]);
    uint32_t dB0 = (uint32_t)__cvta_generic_to_shared(&Bs[0][r0c][s0]);
    uint32_t dB1 = (uint32_t)__cvta_generic_to_shared(&Bs[0][r0c][s1]);

    // ldmatrix per-lane source addresses.
    // A x4 matrices: m0=(rows lo, k lo) m1=(rows hi, k lo) m2=(rows lo, k hi) m3=(rows hi, k hi)
    uint32_t asBase = (uint32_t)__cvta_generic_to_shared(&As[0][0][0]);
    uint32_t bsBase = (uint32_t)__cvta_generic_to_shared(&Bs[0][0][0]);
    int aRow = wm + ((lane >> 3) & 1) * 8 + (lane & 7);
    int aK   = (lane >> 4) * 8;
    // B x4 matrices: m0=(n lo, k lo) m1=(n lo, k hi) m2=(n hi, k lo) m3=(n hi, k hi)
    int bRow = wn + (lane >> 4) * 8 + (lane & 7);
    int bK   = ((lane >> 3) & 1) * 8;

    uint32_t aAddr = asBase + (uint32_t)aRow * ROWB + (uint32_t)aK * 2;
    uint32_t bAddr = bsBase + (uint32_t)bRow * ROWB + (uint32_t)bK * 2;

    float acc[4][4][4];
#pragma unroll
    for (int mi = 0; mi < 4; mi++)
#pragma unroll
        for (int ni = 0; ni < 4; ni++)
#pragma unroll
            for (int r = 0; r < 4; r++) acc[mi][ni][r] = 0.0f;

    int nt = K >> 5;

    cpa16(dA0, aS0); cpa16(dA1, aS1);
    cpa16(dB0, bS0); cpa16(dB1, bS1);
    cpa_commit();

    for (int j = 0; j < nt; j++) {
        cpa_wait0();
        __syncthreads();

        if (j + 1 < nt) {
            uint32_t o = ((j + 1) & 1) * BUFB;
            int ko = (j + 1) << 5;
            cpa16(dA0 + o, aS0 + ko); cpa16(dA1 + o, aS1 + ko);
            cpa16(dB0 + o, bS0 + ko); cpa16(dB1 + o, bS1 + ko);
            cpa_commit();
        }

        uint32_t bufOff = (uint32_t)(j & 1) * BUFB;
#pragma unroll
        for (int ks = 0; ks < 2; ks++) {
            uint32_t kOff = bufOff + (uint32_t)(ks * 16) * 2;
            uint32_t af[4][4], bf[4][2];
#pragma unroll
            for (int mi = 0; mi < 4; mi++)
                ldsm4(af[mi][0], af[mi][1], af[mi][2], af[mi][3],
                      aAddr + kOff + (uint32_t)(mi * 16) * ROWB);
#pragma unroll
            for (int pi = 0; pi < 2; pi++)
                ldsm4(bf[2 * pi][0], bf[2 * pi][1], bf[2 * pi + 1][0], bf[2 * pi + 1][1],
                      bAddr + kOff + (uint32_t)(pi * 16) * ROWB);
#pragma unroll
            for (int mi = 0; mi < 4; mi++)
#pragma unroll
                for (int ni = 0; ni < 4; ni++)
                    mma_bf16(acc[mi][ni], af[mi], bf[ni]);
        }
        __syncthreads();
    }

    // Epilogue: bias (+ GELU); fp32 or bf16 out.
#pragma unroll
    for (int mi = 0; mi < 4; mi++) {
        int r0 = blockIdx.y * 128 + wm + mi * 16 + grp;
#pragma unroll
        for (int ni = 0; ni < 4; ni++) {
            int c = blockIdx.x * 128 + wn + ni * 8 + tig * 2;
            float bv0 = bias[c], bv1 = bias[c + 1];
            float v0 = acc[mi][ni][0] + bv0;
            float v1 = acc[mi][ni][1] + bv1;
            float v2 = acc[mi][ni][2] + bv0;
            float v3 = acc[mi][ni][3] + bv1;
            if (act == 1) {
                v0 = gelu_exact(v0); v1 = gelu_exact(v1);
                v2 = gelu_exact(v2); v3 = gelu_exact(v3);
            }
            if (outbf) {
                __nv_bfloat162 p0 = {__float2bfloat16_rn(v0), __float2bfloat16_rn(v1)};
                __nv_bfloat162 p1 = {__float2bfloat16_rn(v2), __float2bfloat16_rn(v3)};
                *(__nv_bfloat162*)(Cb + (size_t)r0 * N + c) = p0;
                *(__nv_bfloat162*)(Cb + (size_t)(r0 + 8) * N + c) = p1;
            } else {
                float2 p0 = {v0, v1}, p1 = {v2, v3};
                *(float2*)(Cf + (size_t)r0 * N + c) = p0;
                *(float2*)(Cf + (size_t)(r0 + 8) * N + c) = p1;
            }
        }
    }
}

// ---------------------------------------------------------------------------
// Windowed attention (fp32 math); output bf16.
// ---------------------------------------------------------------------------
__global__ __launch_bounds__(64)
void attn_kernel(const float* __restrict__ qkv, __nv_bfloat16* __restrict__ att)
{
    __shared__ float Ks[64][33];
    __shared__ float Vs[64][33];
    __shared__ float Ss[64][65];

    int w = blockIdx.x;
    int h = blockIdx.y;
    int r = threadIdx.x;

    const float* qrow = qkv + (size_t)w * 64 * DQKV + (size_t)r * DQKV + h * 32;

    float q[32];
#pragma unroll
    for (int d4 = 0; d4 < 32; d4 += 4) {
        float4 qv = *(const float4*)(qrow + d4);
        q[d4 + 0] = qv.x * 0.17677669529663687f;
        q[d4 + 1] = qv.y * 0.17677669529663687f;
        q[d4 + 2] = qv.z * 0.17677669529663687f;
        q[d4 + 3] = qv.w * 0.17677669529663687f;
#pragma unroll
        for (int j = 0; j < 4; j++) {
            Ks[r][d4 + j] = qrow[256 + d4 + j];
            Vs[r][d4 + j] = qrow[512 + d4 + j];
        }
    }
    __syncthreads();

    float mx = -1e30f;
    for (int c = 0; c < 64; c++) {
        float acc = 0.0f;
#pragma unroll
        for (int d = 0; d < 32; d++) acc = fmaf(q[d], Ks[c][d], acc);
        Ss[r][c] = acc;
        mx = fmaxf(mx, acc);
    }
    float sum = 0.0f;
    for (int c = 0; c < 64; c++) {
        float e = expf(Ss[r][c] - mx);
        Ss[r][c] = e;
        sum += e;
    }
    float inv = 1.0f / sum;

    float o[32];
#pragma unroll
    for (int d = 0; d < 32; d++) o[d] = 0.0f;
    for (int c = 0; c < 64; c++) {
        float p = Ss[r][c] * inv;
#pragma unroll
        for (int d = 0; d < 32; d++) o[d] = fmaf(p, Vs[c][d], o[d]);
    }

    __nv_bfloat16* obp = att + (size_t)(w * 64 + r) * DMODEL + h * 32;
#pragma unroll
    for (int d2 = 0; d2 < 32; d2 += 2) {
        __nv_bfloat162 ov = {__float2bfloat16_rn(o[d2]), __float2bfloat16_rn(o[d2 + 1])};
        *(__nv_bfloat162*)(obp + d2) = ov;
    }
}

// ---------------------------------------------------------------------------
// Fused residual + LayerNorm, warp-per-token; writes fp32 x + bf16 xb.
// ---------------------------------------------------------------------------
__global__ __launch_bounds__(256)
void add_ln(float* __restrict__ x, __nv_bfloat16* __restrict__ xb,
            const float* __restrict__ res,
            const float* __restrict__ s, const float* __restrict__ b)
{
    int warp = threadIdx.x >> 5, lane = threadIdx.x & 31;
    int t = blockIdx.x * 8 + warp;
    size_t base = (size_t)t * DMODEL + lane * 8;

    float4 v0 = *(const float4*)(x + base);
    float4 v1 = *(const float4*)(x + base + 4);
    float4 r0 = *(const float4*)(res + base);
    float4 r1 = *(const float4*)(res + base + 4);
    float v[8] = {v0.x + r0.x, v0.y + r0.y, v0.z + r0.z, v0.w + r0.w,
                  v1.x + r1.x, v1.y + r1.y, v1.z + r1.z, v1.w + r1.w};

    float sum = 0.0f;
#pragma unroll
    for (int i = 0; i < 8; i++) sum += v[i];
#pragma unroll
    for (int o = 16; o > 0; o >>= 1) sum += __shfl_xor_sync(0xffffffffu, sum, o);
    float m = sum * (1.0f / 256.0f);

    float vs = 0.0f;
#pragma unroll
    for (int i = 0; i < 8; i++) { float d = v[i] - m; vs += d * d; }
#pragma unroll
    for (int o = 16; o > 0; o >>= 1) vs += __shfl_xor_sync(0xffffffffu, vs, o);
    float rstd = rsqrtf(vs * (1.0f / 256.0f) + 1e-5f);

    float4 sv0 = *(const float4*)(s + lane * 8);
    float4 sv1 = *(const float4*)(s + lane * 8 + 4);
    float4 bv0 = *(const float4*)(b + lane * 8);
    float4 bv1 = *(const float4*)(b + lane * 8 + 4);
    float sc[8] = {sv0.x, sv0.y, sv0.z, sv0.w, sv1.x, sv1.y, sv1.z, sv1.w};
    float bi[8] = {bv0.x, bv0.y, bv0.z, bv0.w, bv1.x, bv1.y, bv1.z, bv1.w};

    float o_[8];
#pragma unroll
    for (int i = 0; i < 8; i++) o_[i] = (v[i] - m) * rstd * sc[i] + bi[i];

    float4 w0 = {o_[0], o_[1], o_[2], o_[3]};
    float4 w1 = {o_[4], o_[5], o_[6], o_[7]};
    *(float4*)(x + base) = w0;
    *(float4*)(x + base + 4) = w1;
#pragma unroll
    for (int i = 0; i < 8; i += 2) {
        __nv_bfloat162 c2 = {__float2bfloat16_rn(o_[i]), __float2bfloat16_rn(o_[i + 1])};
        *(__nv_bfloat162*)(xb + base + i) = c2;
    }
}

// ---------------------------------------------------------------------------
// Final LN + transpose back to [B, C, H*W]. Warp-per-token.
// ---------------------------------------------------------------------------
__global__ __launch_bounds__(256)
void final_ln(const float* __restrict__ x, const float* __restrict__ s,
              const float* __restrict__ b, float* __restrict__ out)
{
    int warp = threadIdx.x >> 5, lane = threadIdx.x & 31;
    int t = blockIdx.x * 8 + warp;
    size_t base = (size_t)t * DMODEL + lane * 8;

    float4 v0 = *(const float4*)(x + base);
    float4 v1 = *(const float4*)(x + base + 4);
    float v[8] = {v0.x, v0.y, v0.z, v0.w, v1.x, v1.y, v1.z, v1.w};

    float sum = 0.0f;
#pragma unroll
    for (int i = 0; i < 8; i++) sum += v[i];
#pragma unroll
    for (int o = 16; o > 0; o >>= 1) sum += __shfl_xor_sync(0xffffffffu, sum, o);
    float m = sum * (1.0f / 256.0f);

    float vs = 0.0f;
#pragma unroll
    for (int i = 0; i < 8; i++) { float d = v[i] - m; vs += d * d; }
#pragma unroll
    for (int o = 16; o > 0; o >>= 1) vs += __shfl_xor_sync(0xffffffffu, vs, o);
    float rstd = rsqrtf(vs * (1.0f / 256.0f) + 1e-5f);

    int bidx = t >> 10, l = t & 1023;
    int d0 = lane * 8;
#pragma unroll
    for (int i = 0; i < 8; i++) {
        float val = (v[i] - m) * rstd * s[d0 + i] + b[d0 + i];
        out[((size_t)bidx * DMODEL + d0 + i) * 1024 + l] = val;
    }
}

// ---------------------------------------------------------------------------
extern "C" void kernel_launch(void* const* d_in, const int* in_sizes, int n_in,
                              void* d_out, int out_size)
{
    const float* features = (const float*)d_in[0];
    const float* in_w  = (const float*)d_in[1];
    const float* in_b  = (const float*)d_in[2];
    const float* ow    = (const float*)d_in[3];
    const float* ob    = (const float*)d_in[4];
    const float* w1    = (const float*)d_in[5];
    const float* b1    = (const float*)d_in[6];
    const float* w2    = (const float*)d_in[7];
    const float* b2    = (const float*)d_in[8];
    const float* ln1s  = (const float*)d_in[9];
    const float* ln1b  = (const float*)d_in[10];
    const float* ln2s  = (const float*)d_in[11];
    const float* ln2b  = (const float*)d_in[12];
    const float* fns   = (const float*)d_in[13];
    const float* fnb   = (const float*)d_in[14];
    float* out = (float*)d_out;

    float *x, *qkv, *tmp;
    __nv_bfloat16 *xb, *att, *hh, *wb;
    cudaGetSymbolAddress((void**)&x,   g_x);
    cudaGetSymbolAddress((void**)&xb,  g_xb);
    cudaGetSymbolAddress((void**)&qkv, g_qkv);
    cudaGetSymbolAddress((void**)&att, g_att);
    cudaGetSymbolAddress((void**)&tmp, g_tmp);
    cudaGetSymbolAddress((void**)&hh,  g_h);
    cudaGetSymbolAddress((void**)&wb,  g_wb);

    {
        int n;
        n = 3 * DQKV * DMODEL / 4;
        cvt_kernel<<<(n + 255) / 256, 256>>>(in_w, wb + WT_INW, n);
        n = 3 * DMODEL * DMODEL / 4;
        cvt_kernel<<<(n + 255) / 256, 256>>>(ow, wb + WT_OW, n);
        n = 3 * DFFN * DMODEL / 4;
        cvt_kernel<<<(n + 255) / 256, 256>>>(w1, wb + WT_W1, n);
        n = 3 * DMODEL * DFFN / 4;
        cvt_kernel<<<(n + 255) / 256, 256>>>(w2, wb + WT_W2, n);
    }

    dim3 eb(32, 32);
    dim3 eg(32, 8, 32);
    embed_kernel<<<eg, eb>>>(features, x, xb);

    const int T = T_TOK;
    for (int i = 0; i < 3; i++) {
        gemm_bf16<<<dim3(DQKV / 128, T / 128), 256>>>(
            xb, wb + WT_INW + (size_t)i * DQKV * DMODEL, in_b + (size_t)i * DQKV,
            qkv, nullptr, T, DQKV, DMODEL, 0, 0);
        attn_kernel<<<dim3(512, 8), 64>>>(qkv, att);
        gemm_bf16<<<dim3(DMODEL / 128, T / 128), 256>>>(
            att, wb + WT_OW + (size_t)i * DMODEL * DMODEL, ob + (size_t)i * DMODEL,
            tmp, nullptr, T, DMODEL, DMODEL, 0, 0);
        add_ln<<<T / 8, 256>>>(x, xb, tmp,
                               ln1s + (size_t)i * DMODEL, ln1b + (size_t)i * DMODEL);
        gemm_bf16<<<dim3(DFFN / 128, T / 128), 256>>>(
            xb, wb + WT_W1 + (size_t)i * DFFN * DMODEL, b1 + (size_t)i * DFFN,
            nullptr, hh, T, DFFN, DMODEL, 1, 1);
        gemm_bf16<<<dim3(DMODEL / 128, T / 128), 256>>>(
            hh, wb + WT_W2 + (size_t)i * DMODEL * DFFN, b2 + (size_t)i * DMODEL,
            tmp, nullptr, T, DMODEL, DFFN, 0, 0);
        add_ln<<<T / 8, 256>>>(x, xb, tmp,
                               ln2s + (size_t)i * DMODEL, ln2b + (size_t)i * DMODEL);
    }
    final_ln<<<T / 8, 256>>>(x, fns, fnb, out);
}

// round 8
// speedup vs baseline: 3.8248x; 1.1543x over previous
#include <cuda_runtime.h>
#include <cuda_bf16.h>
#include <math.h>
#include <stdint.h>

// ---------------------------------------------------------------------------
// EfficientTransformerEncoder: B=32, D=256 -> L=1024, NH=8, NL=3, DFF=1024,
// WIN=64. bf16 mma.sync GEMMs (ldmatrix + cp.async, k64 tiles, dyn smem).
// NOTE: tcgen05 is NOT available (harness targets sm_103 without 'a').
// ---------------------------------------------------------------------------

#define T_TOK   32768
#define DMODEL  256
#define DQKV    768
#define DFFN    1024

__device__ float          g_x  [(size_t)T_TOK * DMODEL];
__device__ __nv_bfloat16  g_xb [(size_t)T_TOK * DMODEL];
__device__ float          g_qkv[(size_t)T_TOK * DQKV];
__device__ __nv_bfloat16  g_att[(size_t)T_TOK * DMODEL];
__device__ float          g_tmp[(size_t)T_TOK * DMODEL];
__device__ __nv_bfloat16  g_h  [(size_t)T_TOK * DFFN];

#define WT_INW 0
#define WT_OW  (WT_INW + 3 * DQKV * DMODEL)
#define WT_W1  (WT_OW  + 3 * DMODEL * DMODEL)
#define WT_W2  (WT_W1  + 3 * DFFN * DMODEL)
#define WT_TOT (WT_W2  + 3 * DMODEL * DFFN)
__device__ __nv_bfloat16 g_wb[WT_TOT];

// ---------------------------------------------------------------------------
__global__ void cvt_kernel(const float* __restrict__ src,
                           __nv_bfloat16* __restrict__ dst, int n4) {
    int i = blockIdx.x * blockDim.x + threadIdx.x;
    if (i >= n4) return;
    float4 v = ((const float4*)src)[i];
    __nv_bfloat162 lo = {__float2bfloat16_rn(v.x), __float2bfloat16_rn(v.y)};
    __nv_bfloat162 hi = {__float2bfloat16_rn(v.z), __float2bfloat16_rn(v.w)};
    ((__nv_bfloat162*)dst)[i * 2]     = lo;
    ((__nv_bfloat162*)dst)[i * 2 + 1] = hi;
}

// ---------------------------------------------------------------------------
__device__ __forceinline__ float pe_val(int l, int d) {
    int i = d >> 1;
    float freq = expf(-(float)(2 * i) * 0.0359778920439f);
    float ang = (float)l * freq;
    return (d & 1) ? cosf(ang) : sinf(ang);
}

__global__ void embed_kernel(const float* __restrict__ f,
                             float* __restrict__ x, __nv_bfloat16* __restrict__ xb) {
    __shared__ float tile[32][33];
    int b  = blockIdx.z;
    int l0 = blockIdx.x * 32, d0 = blockIdx.y * 32;
    int tx = threadIdx.x, ty = threadIdx.y;
    tile[ty][tx] = f[((size_t)b * DMODEL + d0 + ty) * 1024 + l0 + tx];
    __syncthreads();
    int l = l0 + ty, d = d0 + tx;
    float v = tile[tx][ty] + pe_val(l, d);
    size_t idx = ((size_t)b * 1024 + l) * DMODEL + d;
    x[idx]  = v;
    xb[idx] = __float2bfloat16_rn(v);
}

// ---------------------------------------------------------------------------
// bf16 NT GEMM: cp.async double-buffered (k64 tiles) + ldmatrix fragments.
// Block tile 128x128x64, 256 threads (2x4 warps), warp tile 64x32.
// ---------------------------------------------------------------------------
__device__ __forceinline__ float gelu_exact(float v) {
    return 0.5f * v * (1.0f + erff(v * 0.7071067811865476f));
}

__device__ __forceinline__ void mma_bf16(float c[4], const uint32_t a[4], const uint32_t b[2]) {
    asm volatile(
        "mma.sync.aligned.m16n8k16.row.col.f32.bf16.bf16.f32 "
        "{%0,%1,%2,%3}, {%4,%5,%6,%7}, {%8,%9}, {%0,%1,%2,%3};\n"
        : "+f"(c[0]), "+f"(c[1]), "+f"(c[2]), "+f"(c[3])
        : "r"(a[0]), "r"(a[1]), "r"(a[2]), "r"(a[3]), "r"(b[0]), "r"(b[1]));
}

__device__ __forceinline__ void ldsm4(uint32_t& r0, uint32_t& r1, uint32_t& r2, uint32_t& r3,
                                      uint32_t addr) {
    asm volatile("ldmatrix.sync.aligned.m8n8.x4.shared.b16 {%0,%1,%2,%3}, [%4];"
                 : "=r"(r0), "=r"(r1), "=r"(r2), "=r"(r3) : "r"(addr));
}

__device__ __forceinline__ void cpa16(uint32_t dst, const void* src) {
    asm volatile("cp.async.cg.shared.global [%0], [%1], 16;\n" :: "r"(dst), "l"(src));
}
__device__ __forceinline__ void cpa_commit() {
    asm volatile("cp.async.commit_group;\n" ::: "memory");
}
__device__ __forceinline__ void cpa_wait0() {
    asm volatile("cp.async.wait_group 0;\n" ::: "memory");
}

// smem row: 64 bf16 data + 8 pad = 72 bf16 (144 B; 144 % 16 == 0).
// LDSM banks: word-stride 36 -> 8 rows hit bank groups 4r..4r+3, all distinct.
#define SMH  72
#define ROWB (SMH * 2)             // 144 bytes
#define MATB (128 * ROWB)          // 18432 bytes per matrix per buffer
#define GSMEM_SZ (4 * MATB)        // 73728 bytes (A0,A1,B0,B1)

__global__ void __launch_bounds__(256, 2)
gemm_bf16(const __nv_bfloat16* __restrict__ A, const __nv_bfloat16* __restrict__ B,
          const float* __restrict__ bias, float* __restrict__ Cf,
          __nv_bfloat16* __restrict__ Cb,
          int M, int N, int K, int act, int outbf)
{
    extern __shared__ __nv_bfloat16 smem[];
    // layout: A buf0 | A buf1 | B buf0 | B buf1
    uint32_t sbase = (uint32_t)__cvta_generic_to_shared(smem);
    uint32_t aBase = sbase;
    uint32_t bBase = sbase + 2 * MATB;

    int tid  = threadIdx.x;
    int warp = tid >> 5, lane = tid & 31;
    int wm = (warp >> 2) * 64;
    int wn = (warp & 3) * 32;
    int grp = lane >> 2, tig = lane & 3;

    const __nv_bfloat16* Ab = A + (size_t)blockIdx.y * 128 * K;
    const __nv_bfloat16* Bb = B + (size_t)blockIdx.x * 128 * K;

    // gmem -> smem: 1024 16B-chunks per matrix per tile; 4 per thread.
    // chunk c = tid + 256*i: row = c>>3, ch = c&7 (8 chunks per 128B row)
    int rowc[4], choff[4];
#pragma unroll
    for (int i = 0; i < 4; i++) {
        int c = tid + 256 * i;
        rowc[i]  = c >> 3;
        choff[i] = (c & 7) * 8;    // bf16 offset within row
    }

    // ldmatrix per-lane addresses (within buffer 0)
    int aRow = wm + ((lane >> 3) & 1) * 8 + (lane & 7);
    int aK   = (lane >> 4) * 8;
    int bRow = wn + (lane >> 4) * 8 + (lane & 7);
    int bK   = ((lane >> 3) & 1) * 8;
    uint32_t aAddr = aBase + (uint32_t)aRow * ROWB + (uint32_t)aK * 2;
    uint32_t bAddr = bBase + (uint32_t)bRow * ROWB + (uint32_t)bK * 2;

    float acc[4][4][4];
#pragma unroll
    for (int mi = 0; mi < 4; mi++)
#pragma unroll
        for (int ni = 0; ni < 4; ni++)
#pragma unroll
            for (int r = 0; r < 4; r++) acc[mi][ni][r] = 0.0f;

    int nt = K >> 6;   // k64 tiles

#define LOAD_TILE(t)                                                           \
    do {                                                                       \
        uint32_t off_ = (uint32_t)((t) & 1) * MATB;                            \
        int k0_ = (t) << 6;                                                    \
        _Pragma("unroll")                                                      \
        for (int i_ = 0; i_ < 4; i_++) {                                       \
            uint32_t d_ = off_ + (uint32_t)rowc[i_] * ROWB + (uint32_t)choff[i_] * 2; \
            cpa16(aBase + d_, Ab + (size_t)rowc[i_] * K + k0_ + choff[i_]);    \
            cpa16(bBase + d_, Bb + (size_t)rowc[i_] * K + k0_ + choff[i_]);    \
        }                                                                      \
        cpa_commit();                                                          \
    } while (0)

    LOAD_TILE(0);

    for (int j = 0; j < nt; j++) {
        cpa_wait0();
        __syncthreads();

        if (j + 1 < nt) LOAD_TILE(j + 1);

        uint32_t bufOff = (uint32_t)(j & 1) * MATB;
#pragma unroll
        for (int ks = 0; ks < 4; ks++) {
            uint32_t kOff = bufOff + (uint32_t)(ks * 32);   // 16 bf16 = 32 B per step
            uint32_t af[4][4], bf[4][2];
#pragma unroll
            for (int mi = 0; mi < 4; mi++)
                ldsm4(af[mi][0], af[mi][1], af[mi][2], af[mi][3],
                      aAddr + kOff + (uint32_t)(mi * 16) * ROWB);
#pragma unroll
            for (int pi = 0; pi < 2; pi++)
                ldsm4(bf[2 * pi][0], bf[2 * pi][1], bf[2 * pi + 1][0], bf[2 * pi + 1][1],
                      bAddr + kOff + (uint32_t)(pi * 16) * ROWB);
#pragma unroll
            for (int mi = 0; mi < 4; mi++)
#pragma unroll
                for (int ni = 0; ni < 4; ni++)
                    mma_bf16(acc[mi][ni], af[mi], bf[ni]);
        }
        __syncthreads();
    }

    // Epilogue: bias (+ GELU); fp32 or bf16 out.
#pragma unroll
    for (int mi = 0; mi < 4; mi++) {
        int r0 = blockIdx.y * 128 + wm + mi * 16 + grp;
#pragma unroll
        for (int ni = 0; ni < 4; ni++) {
            int c = blockIdx.x * 128 + wn + ni * 8 + tig * 2;
            float bv0 = __ldg(bias + c), bv1 = __ldg(bias + c + 1);
            float v0 = acc[mi][ni][0] + bv0;
            float v1 = acc[mi][ni][1] + bv1;
            float v2 = acc[mi][ni][2] + bv0;
            float v3 = acc[mi][ni][3] + bv1;
            if (act == 1) {
                v0 = gelu_exact(v0); v1 = gelu_exact(v1);
                v2 = gelu_exact(v2); v3 = gelu_exact(v3);
            }
            if (outbf) {
                __nv_bfloat162 p0 = {__float2bfloat16_rn(v0), __float2bfloat16_rn(v1)};
                __nv_bfloat162 p1 = {__float2bfloat16_rn(v2), __float2bfloat16_rn(v3)};
                *(__nv_bfloat162*)(Cb + (size_t)r0 * N + c) = p0;
                *(__nv_bfloat162*)(Cb + (size_t)(r0 + 8) * N + c) = p1;
            } else {
                float2 p0 = {v0, v1}, p1 = {v2, v3};
                *(float2*)(Cf + (size_t)r0 * N + c) = p0;
                *(float2*)(Cf + (size_t)(r0 + 8) * N + c) = p1;
            }
        }
    }
}

// ---------------------------------------------------------------------------
// Windowed attention (fp32 math); output bf16.
// ---------------------------------------------------------------------------
__global__ __launch_bounds__(64)
void attn_kernel(const float* __restrict__ qkv, __nv_bfloat16* __restrict__ att)
{
    __shared__ float Ks[64][33];
    __shared__ float Vs[64][33];
    __shared__ float Ss[64][65];

    int w = blockIdx.x;
    int h = blockIdx.y;
    int r = threadIdx.x;

    const float* qrow = qkv + (size_t)w * 64 * DQKV + (size_t)r * DQKV + h * 32;

    float q[32];
#pragma unroll
    for (int d4 = 0; d4 < 32; d4 += 4) {
        float4 qv = *(const float4*)(qrow + d4);
        q[d4 + 0] = qv.x * 0.17677669529663687f;
        q[d4 + 1] = qv.y * 0.17677669529663687f;
        q[d4 + 2] = qv.z * 0.17677669529663687f;
        q[d4 + 3] = qv.w * 0.17677669529663687f;
#pragma unroll
        for (int j = 0; j < 4; j++) {
            Ks[r][d4 + j] = qrow[256 + d4 + j];
            Vs[r][d4 + j] = qrow[512 + d4 + j];
        }
    }
    __syncthreads();

    float mx = -1e30f;
    for (int c = 0; c < 64; c++) {
        float acc = 0.0f;
#pragma unroll
        for (int d = 0; d < 32; d++) acc = fmaf(q[d], Ks[c][d], acc);
        Ss[r][c] = acc;
        mx = fmaxf(mx, acc);
    }
    float sum = 0.0f;
    for (int c = 0; c < 64; c++) {
        float e = expf(Ss[r][c] - mx);
        Ss[r][c] = e;
        sum += e;
    }
    float inv = 1.0f / sum;

    float o[32];
#pragma unroll
    for (int d = 0; d < 32; d++) o[d] = 0.0f;
    for (int c = 0; c < 64; c++) {
        float p = Ss[r][c] * inv;
#pragma unroll
        for (int d = 0; d < 32; d++) o[d] = fmaf(p, Vs[c][d], o[d]);
    }

    __nv_bfloat16* obp = att + (size_t)(w * 64 + r) * DMODEL + h * 32;
#pragma unroll
    for (int d2 = 0; d2 < 32; d2 += 2) {
        __nv_bfloat162 ov = {__float2bfloat16_rn(o[d2]), __float2bfloat16_rn(o[d2 + 1])};
        *(__nv_bfloat162*)(obp + d2) = ov;
    }
}

// ---------------------------------------------------------------------------
__global__ __launch_bounds__(256)
void add_ln(float* __restrict__ x, __nv_bfloat16* __restrict__ xb,
            const float* __restrict__ res,
            const float* __restrict__ s, const float* __restrict__ b)
{
    int warp = threadIdx.x >> 5, lane = threadIdx.x & 31;
    int t = blockIdx.x * 8 + warp;
    size_t base = (size_t)t * DMODEL + lane * 8;

    float4 v0 = *(const float4*)(x + base);
    float4 v1 = *(const float4*)(x + base + 4);
    float4 r0 = *(const float4*)(res + base);
    float4 r1 = *(const float4*)(res + base + 4);
    float v[8] = {v0.x + r0.x, v0.y + r0.y, v0.z + r0.z, v0.w + r0.w,
                  v1.x + r1.x, v1.y + r1.y, v1.z + r1.z, v1.w + r1.w};

    float sum = 0.0f;
#pragma unroll
    for (int i = 0; i < 8; i++) sum += v[i];
#pragma unroll
    for (int o = 16; o > 0; o >>= 1) sum += __shfl_xor_sync(0xffffffffu, sum, o);
    float m = sum * (1.0f / 256.0f);

    float vs = 0.0f;
#pragma unroll
    for (int i = 0; i < 8; i++) { float d = v[i] - m; vs += d * d; }
#pragma unroll
    for (int o = 16; o > 0; o >>= 1) vs += __shfl_xor_sync(0xffffffffu, vs, o);
    float rstd = rsqrtf(vs * (1.0f / 256.0f) + 1e-5f);

    float4 sv0 = *(const float4*)(s + lane * 8);
    float4 sv1 = *(const float4*)(s + lane * 8 + 4);
    float4 bv0 = *(const float4*)(b + lane * 8);
    float4 bv1 = *(const float4*)(b + lane * 8 + 4);
    float sc[8] = {sv0.x, sv0.y, sv0.z, sv0.w, sv1.x, sv1.y, sv1.z, sv1.w};
    float bi[8] = {bv0.x, bv0.y, bv0.z, bv0.w, bv1.x, bv1.y, bv1.z, bv1.w};

    float o_[8];
#pragma unroll
    for (int i = 0; i < 8; i++) o_[i] = (v[i] - m) * rstd * sc[i] + bi[i];

    float4 w0 = {o_[0], o_[1], o_[2], o_[3]};
    float4 w1 = {o_[4], o_[5], o_[6], o_[7]};
    *(float4*)(x + base) = w0;
    *(float4*)(x + base + 4) = w1;
#pragma unroll
    for (int i = 0; i < 8; i += 2) {
        __nv_bfloat162 c2 = {__float2bfloat16_rn(o_[i]), __float2bfloat16_rn(o_[i + 1])};
        *(__nv_bfloat162*)(xb + base + i) = c2;
    }
}

// ---------------------------------------------------------------------------
__global__ __launch_bounds__(256)
void final_ln(const float* __restrict__ x, const float* __restrict__ s,
              const float* __restrict__ b, float* __restrict__ out)
{
    int warp = threadIdx.x >> 5, lane = threadIdx.x & 31;
    int t = blockIdx.x * 8 + warp;
    size_t base = (size_t)t * DMODEL + lane * 8;

    float4 v0 = *(const float4*)(x + base);
    float4 v1 = *(const float4*)(x + base + 4);
    float v[8] = {v0.x, v0.y, v0.z, v0.w, v1.x, v1.y, v1.z, v1.w};

    float sum = 0.0f;
#pragma unroll
    for (int i = 0; i < 8; i++) sum += v[i];
#pragma unroll
    for (int o = 16; o > 0; o >>= 1) sum += __shfl_xor_sync(0xffffffffu, sum, o);
    float m = sum * (1.0f / 256.0f);

    float vs = 0.0f;
#pragma unroll
    for (int i = 0; i < 8; i++) { float d = v[i] - m; vs += d * d; }
#pragma unroll
    for (int o = 16; o > 0; o >>= 1) vs += __shfl_xor_sync(0xffffffffu, vs, o);
    float rstd = rsqrtf(vs * (1.0f / 256.0f) + 1e-5f);

    int bidx = t >> 10, l = t & 1023;
    int d0 = lane * 8;
#pragma unroll
    for (int i = 0; i < 8; i++) {
        float val = (v[i] - m) * rstd * s[d0 + i] + b[d0 + i];
        out[((size_t)bidx * DMODEL + d0 + i) * 1024 + l] = val;
    }
}

// ---------------------------------------------------------------------------
extern "C" void kernel_launch(void* const* d_in, const int* in_sizes, int n_in,
                              void* d_out, int out_size)
{
    const float* features = (const float*)d_in[0];
    const float* in_w  = (const float*)d_in[1];
    const float* in_b  = (const float*)d_in[2];
    const float* ow    = (const float*)d_in[3];
    const float* ob    = (const float*)d_in[4];
    const float* w1    = (const float*)d_in[5];
    const float* b1    = (const float*)d_in[6];
    const float* w2    = (const float*)d_in[7];
    const float* b2    = (const float*)d_in[8];
    const float* ln1s  = (const float*)d_in[9];
    const float* ln1b  = (const float*)d_in[10];
    const float* ln2s  = (const float*)d_in[11];
    const float* ln2b  = (const float*)d_in[12];
    const float* fns   = (const float*)d_in[13];
    const float* fnb   = (const float*)d_in[14];
    float* out = (float*)d_out;

    float *x, *qkv, *tmp;
    __nv_bfloat16 *xb, *att, *hh, *wb;
    cudaGetSymbolAddress((void**)&x,   g_x);
    cudaGetSymbolAddress((void**)&xb,  g_xb);
    cudaGetSymbolAddress((void**)&qkv, g_qkv);
    cudaGetSymbolAddress((void**)&att, g_att);
    cudaGetSymbolAddress((void**)&tmp, g_tmp);
    cudaGetSymbolAddress((void**)&hh,  g_h);
    cudaGetSymbolAddress((void**)&wb,  g_wb);

    cudaFuncSetAttribute(gemm_bf16, cudaFuncAttributeMaxDynamicSharedMemorySize, GSMEM_SZ);

    {
        int n;
        n = 3 * DQKV * DMODEL / 4;
        cvt_kernel<<<(n + 255) / 256, 256>>>(in_w, wb + WT_INW, n);
        n = 3 * DMODEL * DMODEL / 4;
        cvt_kernel<<<(n + 255) / 256, 256>>>(ow, wb + WT_OW, n);
        n = 3 * DFFN * DMODEL / 4;
        cvt_kernel<<<(n + 255) / 256, 256>>>(w1, wb + WT_W1, n);
        n = 3 * DMODEL * DFFN / 4;
        cvt_kernel<<<(n + 255) / 256, 256>>>(w2, wb + WT_W2, n);
    }

    dim3 eb(32, 32);
    dim3 eg(32, 8, 32);
    embed_kernel<<<eg, eb>>>(features, x, xb);

    const int T = T_TOK;
    for (int i = 0; i < 3; i++) {
        gemm_bf16<<<dim3(DQKV / 128, T / 128), 256, GSMEM_SZ>>>(
            xb, wb + WT_INW + (size_t)i * DQKV * DMODEL, in_b + (size_t)i * DQKV,
            qkv, nullptr, T, DQKV, DMODEL, 0, 0);
        attn_kernel<<<dim3(512, 8), 64>>>(qkv, att);
        gemm_bf16<<<dim3(DMODEL / 128, T / 128), 256, GSMEM_SZ>>>(
            att, wb + WT_OW + (size_t)i * DMODEL * DMODEL, ob + (size_t)i * DMODEL,
            tmp, nullptr, T, DMODEL, DMODEL, 0, 0);
        add_ln<<<T / 8, 256>>>(x, xb, tmp,
                               ln1s + (size_t)i * DMODEL, ln1b + (size_t)i * DMODEL);
        gemm_bf16<<<dim3(DFFN / 128, T / 128), 256, GSMEM_SZ>>>(
            xb, wb + WT_W1 + (size_t)i * DFFN * DMODEL, b1 + (size_t)i * DFFN,
            nullptr, hh, T, DFFN, DMODEL, 1, 1);
        gemm_bf16<<<dim3(DMODEL / 128, T / 128), 256, GSMEM_SZ>>>(
            hh, wb + WT_W2 + (size_t)i * DMODEL * DFFN, b2 + (size_t)i * DMODEL,
            tmp, nullptr, T, DMODEL, DFFN, 0, 0);
        add_ln<<<T / 8, 256>>>(x, xb, tmp,
                               ln2s + (size_t)i * DMODEL, ln2b + (size_t)i * DMODEL);
    }
    final_ln<<<T / 8, 256>>>(x, fns, fnb, out);
}

// round 9
// speedup vs baseline: 5.7398x; 1.5007x over previous
#include <cuda_runtime.h>
#include <cuda_bf16.h>
#include <cuda_fp16.h>
#include <math.h>
#include <stdint.h>

// ---------------------------------------------------------------------------
// EfficientTransformerEncoder: B=32, D=256 -> L=1024, NH=8, NL=3, DFF=1024,
// WIN=64. bf16 mma.sync GEMMs (k64) + fp16 tensor-core flash attention.
// ---------------------------------------------------------------------------

#define T_TOK   32768
#define DMODEL  256
#define DQKV    768
#define DFFN    1024

__device__ float          g_x  [(size_t)T_TOK * DMODEL];
__device__ __nv_bfloat16  g_xb [(size_t)T_TOK * DMODEL];
__device__ __half         g_qkv[(size_t)T_TOK * DQKV];    // fp16 (attn mma reads)
__device__ __nv_bfloat16  g_att[(size_t)T_TOK * DMODEL];
__device__ float          g_tmp[(size_t)T_TOK * DMODEL];
__device__ __nv_bfloat16  g_h  [(size_t)T_TOK * DFFN];

#define WT_INW 0
#define WT_OW  (WT_INW + 3 * DQKV * DMODEL)
#define WT_W1  (WT_OW  + 3 * DMODEL * DMODEL)
#define WT_W2  (WT_W1  + 3 * DFFN * DMODEL)
#define WT_TOT (WT_W2  + 3 * DMODEL * DFFN)
__device__ __nv_bfloat16 g_wb[WT_TOT];

// ---------------------------------------------------------------------------
__global__ void cvt_kernel(const float* __restrict__ src,
                           __nv_bfloat16* __restrict__ dst, int n4) {
    int i = blockIdx.x * blockDim.x + threadIdx.x;
    if (i >= n4) return;
    float4 v = ((const float4*)src)[i];
    __nv_bfloat162 lo = {__float2bfloat16_rn(v.x), __float2bfloat16_rn(v.y)};
    __nv_bfloat162 hi = {__float2bfloat16_rn(v.z), __float2bfloat16_rn(v.w)};
    ((__nv_bfloat162*)dst)[i * 2]     = lo;
    ((__nv_bfloat162*)dst)[i * 2 + 1] = hi;
}

// ---------------------------------------------------------------------------
__device__ __forceinline__ float pe_val(int l, int d) {
    int i = d >> 1;
    float freq = expf(-(float)(2 * i) * 0.0359778920439f);
    float ang = (float)l * freq;
    return (d & 1) ? cosf(ang) : sinf(ang);
}

__global__ void embed_kernel(const float* __restrict__ f,
                             float* __restrict__ x, __nv_bfloat16* __restrict__ xb) {
    __shared__ float tile[32][33];
    int b  = blockIdx.z;
    int l0 = blockIdx.x * 32, d0 = blockIdx.y * 32;
    int tx = threadIdx.x, ty = threadIdx.y;
    tile[ty][tx] = f[((size_t)b * DMODEL + d0 + ty) * 1024 + l0 + tx];
    __syncthreads();
    int l = l0 + ty, d = d0 + tx;
    float v = tile[tx][ty] + pe_val(l, d);
    size_t idx = ((size_t)b * 1024 + l) * DMODEL + d;
    x[idx]  = v;
    xb[idx] = __float2bfloat16_rn(v);
}

// ---------------------------------------------------------------------------
// common PTX wrappers
// ---------------------------------------------------------------------------
__device__ __forceinline__ float gelu_exact(float v) {
    return 0.5f * v * (1.0f + erff(v * 0.7071067811865476f));
}

__device__ __forceinline__ void mma_bf16(float c[4], const uint32_t a[4], const uint32_t b[2]) {
    asm volatile(
        "mma.sync.aligned.m16n8k16.row.col.f32.bf16.bf16.f32 "
        "{%0,%1,%2,%3}, {%4,%5,%6,%7}, {%8,%9}, {%0,%1,%2,%3};\n"
        : "+f"(c[0]), "+f"(c[1]), "+f"(c[2]), "+f"(c[3])
        : "r"(a[0]), "r"(a[1]), "r"(a[2]), "r"(a[3]), "r"(b[0]), "r"(b[1]));
}

__device__ __forceinline__ void mma_fp16(float c[4], const uint32_t a[4], const uint32_t b[2]) {
    asm volatile(
        "mma.sync.aligned.m16n8k16.row.col.f32.f16.f16.f32 "
        "{%0,%1,%2,%3}, {%4,%5,%6,%7}, {%8,%9}, {%0,%1,%2,%3};\n"
        : "+f"(c[0]), "+f"(c[1]), "+f"(c[2]), "+f"(c[3])
        : "r"(a[0]), "r"(a[1]), "r"(a[2]), "r"(a[3]), "r"(b[0]), "r"(b[1]));
}

__device__ __forceinline__ void ldsm4(uint32_t& r0, uint32_t& r1, uint32_t& r2, uint32_t& r3,
                                      uint32_t addr) {
    asm volatile("ldmatrix.sync.aligned.m8n8.x4.shared.b16 {%0,%1,%2,%3}, [%4];"
                 : "=r"(r0), "=r"(r1), "=r"(r2), "=r"(r3) : "r"(addr));
}
__device__ __forceinline__ void ldsm4t(uint32_t& r0, uint32_t& r1, uint32_t& r2, uint32_t& r3,
                                       uint32_t addr) {
    asm volatile("ldmatrix.sync.aligned.m8n8.x4.trans.shared.b16 {%0,%1,%2,%3}, [%4];"
                 : "=r"(r0), "=r"(r1), "=r"(r2), "=r"(r3) : "r"(addr));
}

__device__ __forceinline__ void cpa16(uint32_t dst, const void* src) {
    asm volatile("cp.async.cg.shared.global [%0], [%1], 16;\n" :: "r"(dst), "l"(src));
}
__device__ __forceinline__ void cpa_commit() {
    asm volatile("cp.async.commit_group;\n" ::: "memory");
}
__device__ __forceinline__ void cpa_wait0() {
    asm volatile("cp.async.wait_group 0;\n" ::: "memory");
}

__device__ __forceinline__ uint32_t packh2(float x, float y) {
    __half2 h = __floats2half2_rn(x, y);
    return *reinterpret_cast<uint32_t*>(&h);
}

// ---------------------------------------------------------------------------
// bf16 NT GEMM: cp.async double-buffered (k64 tiles) + ldmatrix fragments.
// outmode: 0 -> fp32 Cf, 1 -> bf16 Cb, 2 -> fp16 Ch.
// ---------------------------------------------------------------------------
#define SMH  72
#define ROWB (SMH * 2)
#define MATB (128 * ROWB)
#define GSMEM_SZ (4 * MATB)

__global__ void __launch_bounds__(256, 2)
gemm_bf16(const __nv_bfloat16* __restrict__ A, const __nv_bfloat16* __restrict__ B,
          const float* __restrict__ bias, float* __restrict__ Cf,
          __nv_bfloat16* __restrict__ Cb, __half* __restrict__ Ch,
          int M, int N, int K, int act, int outmode)
{
    extern __shared__ __nv_bfloat16 smem[];
    uint32_t sbase = (uint32_t)__cvta_generic_to_shared(smem);
    uint32_t aBase = sbase;
    uint32_t bBase = sbase + 2 * MATB;

    int tid  = threadIdx.x;
    int warp = tid >> 5, lane = tid & 31;
    int wm = (warp >> 2) * 64;
    int wn = (warp & 3) * 32;
    int grp = lane >> 2, tig = lane & 3;

    const __nv_bfloat16* Ab = A + (size_t)blockIdx.y * 128 * K;
    const __nv_bfloat16* Bb = B + (size_t)blockIdx.x * 128 * K;

    int rowc[4], choff[4];
#pragma unroll
    for (int i = 0; i < 4; i++) {
        int c = tid + 256 * i;
        rowc[i]  = c >> 3;
        choff[i] = (c & 7) * 8;
    }

    int aRow = wm + ((lane >> 3) & 1) * 8 + (lane & 7);
    int aK   = (lane >> 4) * 8;
    int bRow = wn + (lane >> 4) * 8 + (lane & 7);
    int bK   = ((lane >> 3) & 1) * 8;
    uint32_t aAddr = aBase + (uint32_t)aRow * ROWB + (uint32_t)aK * 2;
    uint32_t bAddr = bBase + (uint32_t)bRow * ROWB + (uint32_t)bK * 2;

    float acc[4][4][4];
#pragma unroll
    for (int mi = 0; mi < 4; mi++)
#pragma unroll
        for (int ni = 0; ni < 4; ni++)
#pragma unroll
            for (int r = 0; r < 4; r++) acc[mi][ni][r] = 0.0f;

    int nt = K >> 6;

#define LOAD_TILE(t)                                                           \
    do {                                                                       \
        uint32_t off_ = (uint32_t)((t) & 1) * MATB;                            \
        int k0_ = (t) << 6;                                                    \
        _Pragma("unroll")                                                      \
        for (int i_ = 0; i_ < 4; i_++) {                                       \
            uint32_t d_ = off_ + (uint32_t)rowc[i_] * ROWB + (uint32_t)choff[i_] * 2; \
            cpa16(aBase + d_, Ab + (size_t)rowc[i_] * K + k0_ + choff[i_]);    \
            cpa16(bBase + d_, Bb + (size_t)rowc[i_] * K + k0_ + choff[i_]);    \
        }                                                                      \
        cpa_commit();                                                          \
    } while (0)

    LOAD_TILE(0);

    for (int j = 0; j < nt; j++) {
        cpa_wait0();
        __syncthreads();

        if (j + 1 < nt) LOAD_TILE(j + 1);

        uint32_t bufOff = (uint32_t)(j & 1) * MATB;
#pragma unroll
        for (int ks = 0; ks < 4; ks++) {
            uint32_t kOff = bufOff + (uint32_t)(ks * 32);
            uint32_t af[4][4], bf[4][2];
#pragma unroll
            for (int mi = 0; mi < 4; mi++)
                ldsm4(af[mi][0], af[mi][1], af[mi][2], af[mi][3],
                      aAddr + kOff + (uint32_t)(mi * 16) * ROWB);
#pragma unroll
            for (int pi = 0; pi < 2; pi++)
                ldsm4(bf[2 * pi][0], bf[2 * pi][1], bf[2 * pi + 1][0], bf[2 * pi + 1][1],
                      bAddr + kOff + (uint32_t)(pi * 16) * ROWB);
#pragma unroll
            for (int mi = 0; mi < 4; mi++)
#pragma unroll
                for (int ni = 0; ni < 4; ni++)
                    mma_bf16(acc[mi][ni], af[mi], bf[ni]);
        }
        __syncthreads();
    }

#pragma unroll
    for (int mi = 0; mi < 4; mi++) {
        int r0 = blockIdx.y * 128 + wm + mi * 16 + grp;
#pragma unroll
        for (int ni = 0; ni < 4; ni++) {
            int c = blockIdx.x * 128 + wn + ni * 8 + tig * 2;
            float bv0 = __ldg(bias + c), bv1 = __ldg(bias + c + 1);
            float v0 = acc[mi][ni][0] + bv0;
            float v1 = acc[mi][ni][1] + bv1;
            float v2 = acc[mi][ni][2] + bv0;
            float v3 = acc[mi][ni][3] + bv1;
            if (act == 1) {
                v0 = gelu_exact(v0); v1 = gelu_exact(v1);
                v2 = gelu_exact(v2); v3 = gelu_exact(v3);
            }
            if (outmode == 0) {
                float2 p0 = {v0, v1}, p1 = {v2, v3};
                *(float2*)(Cf + (size_t)r0 * N + c) = p0;
                *(float2*)(Cf + (size_t)(r0 + 8) * N + c) = p1;
            } else if (outmode == 1) {
                __nv_bfloat162 p0 = {__float2bfloat16_rn(v0), __float2bfloat16_rn(v1)};
                __nv_bfloat162 p1 = {__float2bfloat16_rn(v2), __float2bfloat16_rn(v3)};
                *(__nv_bfloat162*)(Cb + (size_t)r0 * N + c) = p0;
                *(__nv_bfloat162*)(Cb + (size_t)(r0 + 8) * N + c) = p1;
            } else {
                uint32_t p0 = packh2(v0, v1), p1 = packh2(v2, v3);
                *(uint32_t*)(Ch + (size_t)r0 * N + c) = p0;
                *(uint32_t*)(Ch + (size_t)(r0 + 8) * N + c) = p1;
            }
        }
    }
}

// ---------------------------------------------------------------------------
// Tensor-core windowed attention (fp16 mma, fp32 softmax).
// grid (512 windows, 2), block 128 = 4 warps; warp -> head blockIdx.y*4+warp.
// smem per warp: Q,K,V tiles 64x32 fp16, row stride 40 halves (conflict-free).
// ---------------------------------------------------------------------------
#define ATT_RS   40
#define ATT_MATH (64 * ATT_RS)                 // halves per matrix
#define ATT_WARPH (3 * ATT_MATH)               // halves per warp
#define ATT_SMEM (4 * ATT_WARPH * 2)           // bytes: 61440

__global__ void __launch_bounds__(128)
attn_tc(const __half* __restrict__ qkv, __nv_bfloat16* __restrict__ att)
{
    extern __shared__ __half ash[];
    int tid = threadIdx.x, warp = tid >> 5, lane = tid & 31;
    int w = blockIdx.x;
    int head = blockIdx.y * 4 + warp;
    int grp = lane >> 2, tig = lane & 3;

    __half* base = ash + warp * ATT_WARPH;     // Q | K | V
    uint32_t sb = (uint32_t)__cvta_generic_to_shared(base);

    // ---- load Q,K,V (64 rows x 32 halves each) ----
    const __half* src = qkv + (size_t)w * 64 * DQKV + head * 32;
#pragma unroll
    for (int m = 0; m < 3; m++) {
        const __half* ms = src + m * 256;
        __half* dst = base + m * ATT_MATH;
#pragma unroll
        for (int p = 0; p < 8; p++) {
            int c = p * 32 + lane;
            int row = c >> 2, ch = c & 3;
            *(uint4*)(dst + row * ATT_RS + ch * 8) =
                *(const uint4*)(ms + (size_t)row * DQKV + ch * 8);
        }
    }
    __syncwarp();

    const uint32_t Qs = sb;
    const uint32_t Ks = sb + ATT_MATH * 2;
    const uint32_t Vs = sb + 2 * ATT_MATH * 2;

    // ---- resident K fragments: kf[ks(2)][ntile(8)][2] ----
    uint32_t kf[2][8][2];
#pragma unroll
    for (int ks = 0; ks < 2; ks++)
#pragma unroll
        for (int pi = 0; pi < 4; pi++) {
            uint32_t addr = Ks +
                (uint32_t)((pi * 16 + (lane >> 4) * 8 + (lane & 7)) * ATT_RS +
                           ((lane >> 3) & 1) * 8 + ks * 16) * 2;
            ldsm4(kf[ks][2 * pi][0], kf[ks][2 * pi][1],
                  kf[ks][2 * pi + 1][0], kf[ks][2 * pi + 1][1], addr);
        }

    // ---- resident V fragments (transposed): vf[ks2(4)][ntile(4)][2] ----
    uint32_t vf[4][4][2];
#pragma unroll
    for (int ks2 = 0; ks2 < 4; ks2++)
#pragma unroll
        for (int np = 0; np < 2; np++) {
            uint32_t addr = Vs +
                (uint32_t)((ks2 * 16 + ((lane >> 3) & 1) * 8 + (lane & 7)) * ATT_RS +
                           ((lane >> 4) + np * 2) * 8) * 2;
            ldsm4t(vf[ks2][2 * np][0], vf[ks2][2 * np][1],
                   vf[ks2][2 * np + 1][0], vf[ks2][2 * np + 1][1], addr);
        }

    const float scale = 0.17677669529663687f;   // 1/sqrt(32)

    // ---- loop over 4 q-tiles of 16 rows ----
#pragma unroll
    for (int qt = 0; qt < 4; qt++) {
        uint32_t qa[2][4];
#pragma unroll
        for (int ks = 0; ks < 2; ks++) {
            uint32_t addr = Qs +
                (uint32_t)((qt * 16 + ((lane >> 3) & 1) * 8 + (lane & 7)) * ATT_RS +
                           (lane >> 4) * 8 + ks * 16) * 2;
            ldsm4(qa[ks][0], qa[ks][1], qa[ks][2], qa[ks][3], addr);
        }

        float s[8][4];
#pragma unroll
        for (int nt2 = 0; nt2 < 8; nt2++)
#pragma unroll
            for (int r = 0; r < 4; r++) s[nt2][r] = 0.0f;
#pragma unroll
        for (int ks = 0; ks < 2; ks++)
#pragma unroll
            for (int nt2 = 0; nt2 < 8; nt2++)
                mma_fp16(s[nt2], qa[ks], kf[ks][nt2]);

        // softmax (rows: grp -> half 0 (c0,c1); grp+8 -> half 1 (c2,c3))
        float mx0 = -1e30f, mx1 = -1e30f;
#pragma unroll
        for (int nt2 = 0; nt2 < 8; nt2++) {
            s[nt2][0] *= scale; s[nt2][1] *= scale;
            s[nt2][2] *= scale; s[nt2][3] *= scale;
            mx0 = fmaxf(mx0, fmaxf(s[nt2][0], s[nt2][1]));
            mx1 = fmaxf(mx1, fmaxf(s[nt2][2], s[nt2][3]));
        }
        mx0 = fmaxf(mx0, __shfl_xor_sync(0xffffffffu, mx0, 1));
        mx0 = fmaxf(mx0, __shfl_xor_sync(0xffffffffu, mx0, 2));
        mx1 = fmaxf(mx1, __shfl_xor_sync(0xffffffffu, mx1, 1));
        mx1 = fmaxf(mx1, __shfl_xor_sync(0xffffffffu, mx1, 2));

        float sm0 = 0.0f, sm1 = 0.0f;
#pragma unroll
        for (int nt2 = 0; nt2 < 8; nt2++) {
            s[nt2][0] = expf(s[nt2][0] - mx0);
            s[nt2][1] = expf(s[nt2][1] - mx0);
            s[nt2][2] = expf(s[nt2][2] - mx1);
            s[nt2][3] = expf(s[nt2][3] - mx1);
            sm0 += s[nt2][0] + s[nt2][1];
            sm1 += s[nt2][2] + s[nt2][3];
        }
        sm0 += __shfl_xor_sync(0xffffffffu, sm0, 1);
        sm0 += __shfl_xor_sync(0xffffffffu, sm0, 2);
        sm1 += __shfl_xor_sync(0xffffffffu, sm1, 1);
        sm1 += __shfl_xor_sync(0xffffffffu, sm1, 2);
        float inv0 = 1.0f / sm0, inv1 = 1.0f / sm1;

        // pack P -> fp16 A fragments: pa[ks2(4)][4]
        uint32_t pa[4][4];
#pragma unroll
        for (int ks2 = 0; ks2 < 4; ks2++) {
            pa[ks2][0] = packh2(s[2 * ks2][0],     s[2 * ks2][1]);
            pa[ks2][1] = packh2(s[2 * ks2][2],     s[2 * ks2][3]);
            pa[ks2][2] = packh2(s[2 * ks2 + 1][0], s[2 * ks2 + 1][1]);
            pa[ks2][3] = packh2(s[2 * ks2 + 1][2], s[2 * ks2 + 1][3]);
        }

        float o[4][4];
#pragma unroll
        for (int nt2 = 0; nt2 < 4; nt2++)
#pragma unroll
            for (int r = 0; r < 4; r++) o[nt2][r] = 0.0f;
#pragma unroll
        for (int ks2 = 0; ks2 < 4; ks2++)
#pragma unroll
            for (int nt2 = 0; nt2 < 4; nt2++)
                mma_fp16(o[nt2], pa[ks2], vf[ks2][nt2]);

        int row0 = w * 64 + qt * 16 + grp;
        __nv_bfloat16* ob = att + (size_t)row0 * DMODEL + head * 32 + tig * 2;
#pragma unroll
        for (int nt2 = 0; nt2 < 4; nt2++) {
            __nv_bfloat162 p0 = {__float2bfloat16_rn(o[nt2][0] * inv0),
                                 __float2bfloat16_rn(o[nt2][1] * inv0)};
            __nv_bfloat162 p1 = {__float2bfloat16_rn(o[nt2][2] * inv1),
                                 __float2bfloat16_rn(o[nt2][3] * inv1)};
            *(__nv_bfloat162*)(ob + nt2 * 8) = p0;
            *(__nv_bfloat162*)(ob + 8 * DMODEL + nt2 * 8) = p1;
        }
    }
}

// ---------------------------------------------------------------------------
__global__ __launch_bounds__(256)
void add_ln(float* __restrict__ x, __nv_bfloat16* __restrict__ xb,
            const float* __restrict__ res,
            const float* __restrict__ s, const float* __restrict__ b)
{
    int warp = threadIdx.x >> 5, lane = threadIdx.x & 31;
    int t = blockIdx.x * 8 + warp;
    size_t base = (size_t)t * DMODEL + lane * 8;

    float4 v0 = *(const float4*)(x + base);
    float4 v1 = *(const float4*)(x + base + 4);
    float4 r0 = *(const float4*)(res + base);
    float4 r1 = *(const float4*)(res + base + 4);
    float v[8] = {v0.x + r0.x, v0.y + r0.y, v0.z + r0.z, v0.w + r0.w,
                  v1.x + r1.x, v1.y + r1.y, v1.z + r1.z, v1.w + r1.w};

    float sum = 0.0f;
#pragma unroll
    for (int i = 0; i < 8; i++) sum += v[i];
#pragma unroll
    for (int o = 16; o > 0; o >>= 1) sum += __shfl_xor_sync(0xffffffffu, sum, o);
    float m = sum * (1.0f / 256.0f);

    float vs = 0.0f;
#pragma unroll
    for (int i = 0; i < 8; i++) { float d = v[i] - m; vs += d * d; }
#pragma unroll
    for (int o = 16; o > 0; o >>= 1) vs += __shfl_xor_sync(0xffffffffu, vs, o);
    float rstd = rsqrtf(vs * (1.0f / 256.0f) + 1e-5f);

    float4 sv0 = *(const float4*)(s + lane * 8);
    float4 sv1 = *(const float4*)(s + lane * 8 + 4);
    float4 bv0 = *(const float4*)(b + lane * 8);
    float4 bv1 = *(const float4*)(b + lane * 8 + 4);
    float sc[8] = {sv0.x, sv0.y, sv0.z, sv0.w, sv1.x, sv1.y, sv1.z, sv1.w};
    float bi[8] = {bv0.x, bv0.y, bv0.z, bv0.w, bv1.x, bv1.y, bv1.z, bv1.w};

    float o_[8];
#pragma unroll
    for (int i = 0; i < 8; i++) o_[i] = (v[i] - m) * rstd * sc[i] + bi[i];

    float4 w0 = {o_[0], o_[1], o_[2], o_[3]};
    float4 w1 = {o_[4], o_[5], o_[6], o_[7]};
    *(float4*)(x + base) = w0;
    *(float4*)(x + base + 4) = w1;
#pragma unroll
    for (int i = 0; i < 8; i += 2) {
        __nv_bfloat162 c2 = {__float2bfloat16_rn(o_[i]), __float2bfloat16_rn(o_[i + 1])};
        *(__nv_bfloat162*)(xb + base + i) = c2;
    }
}

// ---------------------------------------------------------------------------
__global__ __launch_bounds__(256)
void final_ln(const float* __restrict__ x, const float* __restrict__ s,
              const float* __restrict__ b, float* __restrict__ out)
{
    int warp = threadIdx.x >> 5, lane = threadIdx.x & 31;
    int t = blockIdx.x * 8 + warp;
    size_t base = (size_t)t * DMODEL + lane * 8;

    float4 v0 = *(const float4*)(x + base);
    float4 v1 = *(const float4*)(x + base + 4);
    float v[8] = {v0.x, v0.y, v0.z, v0.w, v1.x, v1.y, v1.z, v1.w};

    float sum = 0.0f;
#pragma unroll
    for (int i = 0; i < 8; i++) sum += v[i];
#pragma unroll
    for (int o = 16; o > 0; o >>= 1) sum += __shfl_xor_sync(0xffffffffu, sum, o);
    float m = sum * (1.0f / 256.0f);

    float vs = 0.0f;
#pragma unroll
    for (int i = 0; i < 8; i++) { float d = v[i] - m; vs += d * d; }
#pragma unroll
    for (int o = 16; o > 0; o >>= 1) vs += __shfl_xor_sync(0xffffffffu, vs, o);
    float rstd = rsqrtf(vs * (1.0f / 256.0f) + 1e-5f);

    int bidx = t >> 10, l = t & 1023;
    int d0 = lane * 8;
#pragma unroll
    for (int i = 0; i < 8; i++) {
        float val = (v[i] - m) * rstd * s[d0 + i] + b[d0 + i];
        out[((size_t)bidx * DMODEL + d0 + i) * 1024 + l] = val;
    }
}

// ---------------------------------------------------------------------------
extern "C" void kernel_launch(void* const* d_in, const int* in_sizes, int n_in,
                              void* d_out, int out_size)
{
    const float* features = (const float*)d_in[0];
    const float* in_w  = (const float*)d_in[1];
    const float* in_b  = (const float*)d_in[2];
    const float* ow    = (const float*)d_in[3];
    const float* ob    = (const float*)d_in[4];
    const float* w1    = (const float*)d_in[5];
    const float* b1    = (const float*)d_in[6];
    const float* w2    = (const float*)d_in[7];
    const float* b2    = (const float*)d_in[8];
    const float* ln1s  = (const float*)d_in[9];
    const float* ln1b  = (const float*)d_in[10];
    const float* ln2s  = (const float*)d_in[11];
    const float* ln2b  = (const float*)d_in[12];
    const float* fns   = (const float*)d_in[13];
    const float* fnb   = (const float*)d_in[14];
    float* out = (float*)d_out;

    float *x, *tmp;
    __half* qkvh;
    __nv_bfloat16 *xb, *att, *hh, *wb;
    cudaGetSymbolAddress((void**)&x,    g_x);
    cudaGetSymbolAddress((void**)&xb,   g_xb);
    cudaGetSymbolAddress((void**)&qkvh, g_qkv);
    cudaGetSymbolAddress((void**)&att,  g_att);
    cudaGetSymbolAddress((void**)&tmp,  g_tmp);
    cudaGetSymbolAddress((void**)&hh,   g_h);
    cudaGetSymbolAddress((void**)&wb,   g_wb);

    cudaFuncSetAttribute(gemm_bf16, cudaFuncAttributeMaxDynamicSharedMemorySize, GSMEM_SZ);
    cudaFuncSetAttribute(attn_tc,   cudaFuncAttributeMaxDynamicSharedMemorySize, ATT_SMEM);

    {
        int n;
        n = 3 * DQKV * DMODEL / 4;
        cvt_kernel<<<(n + 255) / 256, 256>>>(in_w, wb + WT_INW, n);
        n = 3 * DMODEL * DMODEL / 4;
        cvt_kernel<<<(n + 255) / 256, 256>>>(ow, wb + WT_OW, n);
        n = 3 * DFFN * DMODEL / 4;
        cvt_kernel<<<(n + 255) / 256, 256>>>(w1, wb + WT_W1, n);
        n = 3 * DMODEL * DFFN / 4;
        cvt_kernel<<<(n + 255) / 256, 256>>>(w2, wb + WT_W2, n);
    }

    dim3 eb(32, 32);
    dim3 eg(32, 8, 32);
    embed_kernel<<<eg, eb>>>(features, x, xb);

    const int T = T_TOK;
    for (int i = 0; i < 3; i++) {
        gemm_bf16<<<dim3(DQKV / 128, T / 128), 256, GSMEM_SZ>>>(
            xb, wb + WT_INW + (size_t)i * DQKV * DMODEL, in_b + (size_t)i * DQKV,
            nullptr, nullptr, qkvh, T, DQKV, DMODEL, 0, 2);
        attn_tc<<<dim3(512, 2), 128, ATT_SMEM>>>(qkvh, att);
        gemm_bf16<<<dim3(DMODEL / 128, T / 128), 256, GSMEM_SZ>>>(
            att, wb + WT_OW + (size_t)i * DMODEL * DMODEL, ob + (size_t)i * DMODEL,
            tmp, nullptr, nullptr, T, DMODEL, DMODEL, 0, 0);
        add_ln<<<T / 8, 256>>>(x, xb, tmp,
                               ln1s + (size_t)i * DMODEL, ln1b + (size_t)i * DMODEL);
        gemm_bf16<<<dim3(DFFN / 128, T / 128), 256, GSMEM_SZ>>>(
            xb, wb + WT_W1 + (size_t)i * DFFN * DMODEL, b1 + (size_t)i * DFFN,
            nullptr, hh, nullptr, T, DFFN, DMODEL, 1, 1);
        gemm_bf16<<<dim3(DMODEL / 128, T / 128), 256, GSMEM_SZ>>>(
            hh, wb + WT_W2 + (size_t)i * DMODEL * DFFN, b2 + (size_t)i * DMODEL,
            tmp, nullptr, nullptr, T, DMODEL, DFFN, 0, 0);
        add_ln<<<T / 8, 256>>>(x, xb, tmp,
                               ln2s + (size_t)i * DMODEL, ln2b + (size_t)i * DMODEL);
    }
    final_ln<<<T / 8, 256>>>(x, fns, fnb, out);
}

// round 10
// speedup vs baseline: 5.8680x; 1.0223x over previous
#include <cuda_runtime.h>
#include <cuda_bf16.h>
#include <cuda_fp16.h>
#include <math.h>
#include <stdint.h>

// ---------------------------------------------------------------------------
// EfficientTransformerEncoder: B=32, D=256 -> L=1024, NH=8, NL=3, DFF=1024,
// WIN=64. bf16 mma.sync GEMMs + fp16 TC flash attention + fused LN epilogues.
// ---------------------------------------------------------------------------

#define T_TOK   32768
#define DMODEL  256
#define DQKV    768
#define DFFN    1024

__device__ float          g_x  [(size_t)T_TOK * DMODEL];
__device__ __nv_bfloat16  g_xb [(size_t)T_TOK * DMODEL];
__device__ __half         g_qkv[(size_t)T_TOK * DQKV];
__device__ __nv_bfloat16  g_att[(size_t)T_TOK * DMODEL];
__device__ __nv_bfloat16  g_h  [(size_t)T_TOK * DFFN];

#define WT_INW 0
#define WT_OW  (WT_INW + 3 * DQKV * DMODEL)
#define WT_W1  (WT_OW  + 3 * DMODEL * DMODEL)
#define WT_W2  (WT_W1  + 3 * DFFN * DMODEL)
#define WT_TOT (WT_W2  + 3 * DMODEL * DFFN)
__device__ __nv_bfloat16 g_wb[WT_TOT];

// f4-unit segment boundaries for the merged converter
#define CV0 0
#define CV1 (WT_OW  / 4)
#define CV2 (WT_W1  / 4)
#define CV3 (WT_W2  / 4)
#define CV4 (WT_TOT / 4)

// ---------------------------------------------------------------------------
__global__ void cvt_all(const float* __restrict__ s0, const float* __restrict__ s1,
                        const float* __restrict__ s2, const float* __restrict__ s3,
                        __nv_bfloat16* __restrict__ dst) {
    int i = blockIdx.x * blockDim.x + threadIdx.x;
    if (i >= CV4) return;
    const float* src;
    int off;
    if (i < CV1)      { src = s0; off = i - CV0; }
    else if (i < CV2) { src = s1; off = i - CV1; }
    else if (i < CV3) { src = s2; off = i - CV2; }
    else              { src = s3; off = i - CV3; }
    float4 v = ((const float4*)src)[off];
    __nv_bfloat162 lo = {__float2bfloat16_rn(v.x), __float2bfloat16_rn(v.y)};
    __nv_bfloat162 hi = {__float2bfloat16_rn(v.z), __float2bfloat16_rn(v.w)};
    ((__nv_bfloat162*)dst)[i * 2]     = lo;
    ((__nv_bfloat162*)dst)[i * 2 + 1] = hi;
}

// ---------------------------------------------------------------------------
__device__ __forceinline__ float pe_val(int l, int d) {
    int i = d >> 1;
    float freq = expf(-(float)(2 * i) * 0.0359778920439f);
    float ang = (float)l * freq;
    return (d & 1) ? cosf(ang) : sinf(ang);
}

__global__ void embed_kernel(const float* __restrict__ f,
                             float* __restrict__ x, __nv_bfloat16* __restrict__ xb) {
    __shared__ float tile[32][33];
    int b  = blockIdx.z;
    int l0 = blockIdx.x * 32, d0 = blockIdx.y * 32;
    int tx = threadIdx.x, ty = threadIdx.y;
    tile[ty][tx] = f[((size_t)b * DMODEL + d0 + ty) * 1024 + l0 + tx];
    __syncthreads();
    int l = l0 + ty, d = d0 + tx;
    float v = tile[tx][ty] + pe_val(l, d);
    size_t idx = ((size_t)b * 1024 + l) * DMODEL + d;
    x[idx]  = v;
    xb[idx] = __float2bfloat16_rn(v);
}

// ---------------------------------------------------------------------------
__device__ __forceinline__ float gelu_exact(float v) {
    return 0.5f * v * (1.0f + erff(v * 0.7071067811865476f));
}

__device__ __forceinline__ void mma_bf16(float c[4], const uint32_t a[4], const uint32_t b[2]) {
    asm volatile(
        "mma.sync.aligned.m16n8k16.row.col.f32.bf16.bf16.f32 "
        "{%0,%1,%2,%3}, {%4,%5,%6,%7}, {%8,%9}, {%0,%1,%2,%3};\n"
        : "+f"(c[0]), "+f"(c[1]), "+f"(c[2]), "+f"(c[3])
        : "r"(a[0]), "r"(a[1]), "r"(a[2]), "r"(a[3]), "r"(b[0]), "r"(b[1]));
}

__device__ __forceinline__ void mma_fp16(float c[4], const uint32_t a[4], const uint32_t b[2]) {
    asm volatile(
        "mma.sync.aligned.m16n8k16.row.col.f32.f16.f16.f32 "
        "{%0,%1,%2,%3}, {%4,%5,%6,%7}, {%8,%9}, {%0,%1,%2,%3};\n"
        : "+f"(c[0]), "+f"(c[1]), "+f"(c[2]), "+f"(c[3])
        : "r"(a[0]), "r"(a[1]), "r"(a[2]), "r"(a[3]), "r"(b[0]), "r"(b[1]));
}

__device__ __forceinline__ void ldsm4(uint32_t& r0, uint32_t& r1, uint32_t& r2, uint32_t& r3,
                                      uint32_t addr) {
    asm volatile("ldmatrix.sync.aligned.m8n8.x4.shared.b16 {%0,%1,%2,%3}, [%4];"
                 : "=r"(r0), "=r"(r1), "=r"(r2), "=r"(r3) : "r"(addr));
}
__device__ __forceinline__ void ldsm4t(uint32_t& r0, uint32_t& r1, uint32_t& r2, uint32_t& r3,
                                       uint32_t addr) {
    asm volatile("ldmatrix.sync.aligned.m8n8.x4.trans.shared.b16 {%0,%1,%2,%3}, [%4];"
                 : "=r"(r0), "=r"(r1), "=r"(r2), "=r"(r3) : "r"(addr));
}

__device__ __forceinline__ void cpa16(uint32_t dst, const void* src) {
    asm volatile("cp.async.cg.shared.global [%0], [%1], 16;\n" :: "r"(dst), "l"(src));
}
__device__ __forceinline__ void cpa_commit() {
    asm volatile("cp.async.commit_group;\n" ::: "memory");
}
__device__ __forceinline__ void cpa_wait0() {
    asm volatile("cp.async.wait_group 0;\n" ::: "memory");
}

__device__ __forceinline__ uint32_t packh2(float x, float y) {
    __half2 h = __floats2half2_rn(x, y);
    return *reinterpret_cast<uint32_t*>(&h);
}

#define SMH  72
#define ROWB (SMH * 2)

// ---------------------------------------------------------------------------
// Generic 128x128 bf16 GEMM (QKV: outmode=2 fp16 out; FFN1: act=1, bf16 out).
// ---------------------------------------------------------------------------
#define MATB (128 * ROWB)
#define GSMEM_SZ (4 * MATB)

__global__ void __launch_bounds__(256, 2)
gemm_bf16(const __nv_bfloat16* __restrict__ A, const __nv_bfloat16* __restrict__ B,
          const float* __restrict__ bias,
          __nv_bfloat16* __restrict__ Cb, __half* __restrict__ Ch,
          int M, int N, int K, int act, int outmode)
{
    extern __shared__ __nv_bfloat16 smem[];
    uint32_t sbase = (uint32_t)__cvta_generic_to_shared(smem);
    uint32_t aBase = sbase;
    uint32_t bBase = sbase + 2 * MATB;

    int tid  = threadIdx.x;
    int warp = tid >> 5, lane = tid & 31;
    int wm = (warp >> 2) * 64;
    int wn = (warp & 3) * 32;
    int grp = lane >> 2, tig = lane & 3;

    const __nv_bfloat16* Ab = A + (size_t)blockIdx.y * 128 * K;
    const __nv_bfloat16* Bb = B + (size_t)blockIdx.x * 128 * K;

    int rowc[4], choff[4];
#pragma unroll
    for (int i = 0; i < 4; i++) {
        int c = tid + 256 * i;
        rowc[i]  = c >> 3;
        choff[i] = (c & 7) * 8;
    }

    int aRow = wm + ((lane >> 3) & 1) * 8 + (lane & 7);
    int aK   = (lane >> 4) * 8;
    int bRow = wn + (lane >> 4) * 8 + (lane & 7);
    int bK   = ((lane >> 3) & 1) * 8;
    uint32_t aAddr = aBase + (uint32_t)aRow * ROWB + (uint32_t)aK * 2;
    uint32_t bAddr = bBase + (uint32_t)bRow * ROWB + (uint32_t)bK * 2;

    float acc[4][4][4];
#pragma unroll
    for (int mi = 0; mi < 4; mi++)
#pragma unroll
        for (int ni = 0; ni < 4; ni++)
#pragma unroll
            for (int r = 0; r < 4; r++) acc[mi][ni][r] = 0.0f;

    int nt = K >> 6;

#define LOAD_TILE(t)                                                           \
    do {                                                                       \
        uint32_t off_ = (uint32_t)((t) & 1) * MATB;                            \
        int k0_ = (t) << 6;                                                    \
        _Pragma("unroll")                                                      \
        for (int i_ = 0; i_ < 4; i_++) {                                       \
            uint32_t d_ = off_ + (uint32_t)rowc[i_] * ROWB + (uint32_t)choff[i_] * 2; \
            cpa16(aBase + d_, Ab + (size_t)rowc[i_] * K + k0_ + choff[i_]);    \
            cpa16(bBase + d_, Bb + (size_t)rowc[i_] * K + k0_ + choff[i_]);    \
        }                                                                      \
        cpa_commit();                                                          \
    } while (0)

    LOAD_TILE(0);

    for (int j = 0; j < nt; j++) {
        cpa_wait0();
        __syncthreads();
        if (j + 1 < nt) LOAD_TILE(j + 1);

        uint32_t bufOff = (uint32_t)(j & 1) * MATB;
#pragma unroll
        for (int ks = 0; ks < 4; ks++) {
            uint32_t kOff = bufOff + (uint32_t)(ks * 32);
            uint32_t af[4][4], bf[4][2];
#pragma unroll
            for (int mi = 0; mi < 4; mi++)
                ldsm4(af[mi][0], af[mi][1], af[mi][2], af[mi][3],
                      aAddr + kOff + (uint32_t)(mi * 16) * ROWB);
#pragma unroll
            for (int pi = 0; pi < 2; pi++)
                ldsm4(bf[2 * pi][0], bf[2 * pi][1], bf[2 * pi + 1][0], bf[2 * pi + 1][1],
                      bAddr + kOff + (uint32_t)(pi * 16) * ROWB);
#pragma unroll
            for (int mi = 0; mi < 4; mi++)
#pragma unroll
                for (int ni = 0; ni < 4; ni++)
                    mma_bf16(acc[mi][ni], af[mi], bf[ni]);
        }
        __syncthreads();
    }

#pragma unroll
    for (int mi = 0; mi < 4; mi++) {
        int r0 = blockIdx.y * 128 + wm + mi * 16 + grp;
#pragma unroll
        for (int ni = 0; ni < 4; ni++) {
            int c = blockIdx.x * 128 + wn + ni * 8 + tig * 2;
            float bv0 = __ldg(bias + c), bv1 = __ldg(bias + c + 1);
            float v0 = acc[mi][ni][0] + bv0;
            float v1 = acc[mi][ni][1] + bv1;
            float v2 = acc[mi][ni][2] + bv0;
            float v3 = acc[mi][ni][3] + bv1;
            if (act == 1) {
                v0 = gelu_exact(v0); v1 = gelu_exact(v1);
                v2 = gelu_exact(v2); v3 = gelu_exact(v3);
            }
            if (outmode == 1) {
                __nv_bfloat162 p0 = {__float2bfloat16_rn(v0), __float2bfloat16_rn(v1)};
                __nv_bfloat162 p1 = {__float2bfloat16_rn(v2), __float2bfloat16_rn(v3)};
                *(__nv_bfloat162*)(Cb + (size_t)r0 * N + c) = p0;
                *(__nv_bfloat162*)(Cb + (size_t)(r0 + 8) * N + c) = p1;
            } else {
                uint32_t p0 = packh2(v0, v1), p1 = packh2(v2, v3);
                *(uint32_t*)(Ch + (size_t)r0 * N + c) = p0;
                *(uint32_t*)(Ch + (size_t)(r0 + 8) * N + c) = p1;
            }
        }
    }
}

// ---------------------------------------------------------------------------
// Fused GEMM(N=256) + residual + LayerNorm. Block tile 64x256, 8 warps (1x8).
// C = A*B^T + bias; x = LN(x + C)*s + ln_b; writes fp32 x and bf16 xb.
// ---------------------------------------------------------------------------
#define FA_B  (64 * ROWB)              // 9216  (A buffer)
#define FB_B  (256 * ROWB)             // 36864 (B buffer)
#define FG_SMEM (2 * FA_B + 2 * FB_B)  // 92160
#define STG_S 264                      // stage row stride (floats)

__global__ void __launch_bounds__(256, 2)
gemm_ln(const __nv_bfloat16* __restrict__ A, const __nv_bfloat16* __restrict__ B,
        const float* __restrict__ bias,
        const float* __restrict__ lns, const float* __restrict__ lnb,
        float* __restrict__ x, __nv_bfloat16* __restrict__ xb, int K)
{
    extern __shared__ __nv_bfloat16 smem[];
    uint32_t sbase = (uint32_t)__cvta_generic_to_shared(smem);
    uint32_t aBase = sbase;
    uint32_t bBase = sbase + 2 * FA_B;

    int tid  = threadIdx.x;
    int warp = tid >> 5, lane = tid & 31;
    int wn = warp * 32;
    int grp = lane >> 2, tig = lane & 3;

    const __nv_bfloat16* Ab = A + (size_t)blockIdx.x * 64 * K;

    // A: 512 chunks (2/thread); B: 2048 chunks (8/thread)
    int aRowc[2], aChoff[2];
#pragma unroll
    for (int i = 0; i < 2; i++) {
        int c = tid + 256 * i;
        aRowc[i]  = c >> 3;
        aChoff[i] = (c & 7) * 8;
    }
    int bRowc[8], bChoff[8];
#pragma unroll
    for (int i = 0; i < 8; i++) {
        int c = tid + 256 * i;
        bRowc[i]  = c >> 3;
        bChoff[i] = (c & 7) * 8;
    }

    int aRow = ((lane >> 3) & 1) * 8 + (lane & 7);
    int aK   = (lane >> 4) * 8;
    int bRow = wn + (lane >> 4) * 8 + (lane & 7);
    int bK   = ((lane >> 3) & 1) * 8;
    uint32_t aAddr = aBase + (uint32_t)aRow * ROWB + (uint32_t)aK * 2;
    uint32_t bAddr = bBase + (uint32_t)bRow * ROWB + (uint32_t)bK * 2;

    float acc[4][4][4];
#pragma unroll
    for (int mi = 0; mi < 4; mi++)
#pragma unroll
        for (int ni = 0; ni < 4; ni++)
#pragma unroll
            for (int r = 0; r < 4; r++) acc[mi][ni][r] = 0.0f;

    int nt = K >> 6;

#define FLOAD_TILE(t)                                                          \
    do {                                                                       \
        uint32_t oa_ = (uint32_t)((t) & 1) * FA_B;                             \
        uint32_t ob_ = (uint32_t)((t) & 1) * FB_B;                             \
        int k0_ = (t) << 6;                                                    \
        _Pragma("unroll")                                                      \
        for (int i_ = 0; i_ < 2; i_++)                                         \
            cpa16(aBase + oa_ + (uint32_t)aRowc[i_] * ROWB + (uint32_t)aChoff[i_] * 2, \
                  Ab + (size_t)aRowc[i_] * K + k0_ + aChoff[i_]);              \
        _Pragma("unroll")                                                      \
        for (int i_ = 0; i_ < 8; i_++)                                         \
            cpa16(bBase + ob_ + (uint32_t)bRowc[i_] * ROWB + (uint32_t)bChoff[i_] * 2, \
                  B + (size_t)bRowc[i_] * K + k0_ + bChoff[i_]);               \
        cpa_commit();                                                          \
    } while (0)

    FLOAD_TILE(0);

    for (int j = 0; j < nt; j++) {
        cpa_wait0();
        __syncthreads();
        if (j + 1 < nt) FLOAD_TILE(j + 1);

        uint32_t aOff = (uint32_t)(j & 1) * FA_B;
        uint32_t bOff = (uint32_t)(j & 1) * FB_B;
#pragma unroll
        for (int ks = 0; ks < 4; ks++) {
            uint32_t kb = (uint32_t)(ks * 32);
            uint32_t af[4][4], bf[4][2];
#pragma unroll
            for (int mi = 0; mi < 4; mi++)
                ldsm4(af[mi][0], af[mi][1], af[mi][2], af[mi][3],
                      aAddr + aOff + kb + (uint32_t)(mi * 16) * ROWB);
#pragma unroll
            for (int pi = 0; pi < 2; pi++)
                ldsm4(bf[2 * pi][0], bf[2 * pi][1], bf[2 * pi + 1][0], bf[2 * pi + 1][1],
                      bAddr + bOff + kb + (uint32_t)(pi * 16) * ROWB);
#pragma unroll
            for (int mi = 0; mi < 4; mi++)
#pragma unroll
                for (int ni = 0; ni < 4; ni++)
                    mma_bf16(acc[mi][ni], af[mi], bf[ni]);
        }
        __syncthreads();
    }

    // stage fp32 result (64 x 256) into smem
    float* stage = (float*)smem;
#pragma unroll
    for (int mi = 0; mi < 4; mi++) {
        int r0 = mi * 16 + grp;
#pragma unroll
        for (int ni = 0; ni < 4; ni++) {
            int c = wn + ni * 8 + tig * 2;
            float bv0 = __ldg(bias + c), bv1 = __ldg(bias + c + 1);
            stage[r0 * STG_S + c]           = acc[mi][ni][0] + bv0;
            stage[r0 * STG_S + c + 1]       = acc[mi][ni][1] + bv1;
            stage[(r0 + 8) * STG_S + c]     = acc[mi][ni][2] + bv0;
            stage[(r0 + 8) * STG_S + c + 1] = acc[mi][ni][3] + bv1;
        }
    }
    __syncthreads();

    // LN: warp handles 8 tokens
    float4 sv0 = *(const float4*)(lns + lane * 8);
    float4 sv1 = *(const float4*)(lns + lane * 8 + 4);
    float4 bv0 = *(const float4*)(lnb + lane * 8);
    float4 bv1 = *(const float4*)(lnb + lane * 8 + 4);
    float sc[8] = {sv0.x, sv0.y, sv0.z, sv0.w, sv1.x, sv1.y, sv1.z, sv1.w};
    float bi[8] = {bv0.x, bv0.y, bv0.z, bv0.w, bv1.x, bv1.y, bv1.z, bv1.w};

#pragma unroll
    for (int it = 0; it < 8; it++) {
        int tok = warp * 8 + it;
        size_t gbase = ((size_t)blockIdx.x * 64 + tok) * DMODEL + lane * 8;
        const float* sp = stage + tok * STG_S + lane * 8;

        float4 xv0 = *(const float4*)(x + gbase);
        float4 xv1 = *(const float4*)(x + gbase + 4);
        float v[8] = {xv0.x + sp[0], xv0.y + sp[1], xv0.z + sp[2], xv0.w + sp[3],
                      xv1.x + sp[4], xv1.y + sp[5], xv1.z + sp[6], xv1.w + sp[7]};

        float sum = 0.0f;
#pragma unroll
        for (int i = 0; i < 8; i++) sum += v[i];
#pragma unroll
        for (int o = 16; o > 0; o >>= 1) sum += __shfl_xor_sync(0xffffffffu, sum, o);
        float m = sum * (1.0f / 256.0f);

        float vs = 0.0f;
#pragma unroll
        for (int i = 0; i < 8; i++) { float d = v[i] - m; vs += d * d; }
#pragma unroll
        for (int o = 16; o > 0; o >>= 1) vs += __shfl_xor_sync(0xffffffffu, vs, o);
        float rstd = rsqrtf(vs * (1.0f / 256.0f) + 1e-5f);

        float o_[8];
#pragma unroll
        for (int i = 0; i < 8; i++) o_[i] = (v[i] - m) * rstd * sc[i] + bi[i];

        float4 w0 = {o_[0], o_[1], o_[2], o_[3]};
        float4 w1 = {o_[4], o_[5], o_[6], o_[7]};
        *(float4*)(x + gbase) = w0;
        *(float4*)(x + gbase + 4) = w1;
#pragma unroll
        for (int i = 0; i < 8; i += 2) {
            __nv_bfloat162 c2 = {__float2bfloat16_rn(o_[i]), __float2bfloat16_rn(o_[i + 1])};
            *(__nv_bfloat162*)(xb + gbase + i) = c2;
        }
    }
}

// ---------------------------------------------------------------------------
// Tensor-core windowed attention (fp16 mma, fp32 softmax).
// ---------------------------------------------------------------------------
#define ATT_RS   40
#define ATT_MATH (64 * ATT_RS)
#define ATT_WARPH (3 * ATT_MATH)
#define ATT_SMEM (4 * ATT_WARPH * 2)

__global__ void __launch_bounds__(128)
attn_tc(const __half* __restrict__ qkv, __nv_bfloat16* __restrict__ att)
{
    extern __shared__ __half ash[];
    int tid = threadIdx.x, warp = tid >> 5, lane = tid & 31;
    int w = blockIdx.x;
    int head = blockIdx.y * 4 + warp;
    int grp = lane >> 2, tig = lane & 3;

    __half* base = ash + warp * ATT_WARPH;
    uint32_t sb = (uint32_t)__cvta_generic_to_shared(base);

    const __half* src = qkv + (size_t)w * 64 * DQKV + head * 32;
#pragma unroll
    for (int m = 0; m < 3; m++) {
        const __half* ms = src + m * 256;
        __half* dst = base + m * ATT_MATH;
#pragma unroll
        for (int p = 0; p < 8; p++) {
            int c = p * 32 + lane;
            int row = c >> 2, ch = c & 3;
            *(uint4*)(dst + row * ATT_RS + ch * 8) =
                *(const uint4*)(ms + (size_t)row * DQKV + ch * 8);
        }
    }
    __syncwarp();

    const uint32_t Qs = sb;
    const uint32_t Ks = sb + ATT_MATH * 2;
    const uint32_t Vs = sb + 2 * ATT_MATH * 2;

    uint32_t kf[2][8][2];
#pragma unroll
    for (int ks = 0; ks < 2; ks++)
#pragma unroll
        for (int pi = 0; pi < 4; pi++) {
            uint32_t addr = Ks +
                (uint32_t)((pi * 16 + (lane >> 4) * 8 + (lane & 7)) * ATT_RS +
                           ((lane >> 3) & 1) * 8 + ks * 16) * 2;
            ldsm4(kf[ks][2 * pi][0], kf[ks][2 * pi][1],
                  kf[ks][2 * pi + 1][0], kf[ks][2 * pi + 1][1], addr);
        }

    uint32_t vf[4][4][2];
#pragma unroll
    for (int ks2 = 0; ks2 < 4; ks2++)
#pragma unroll
        for (int np = 0; np < 2; np++) {
            uint32_t addr = Vs +
                (uint32_t)((ks2 * 16 + ((lane >> 3) & 1) * 8 + (lane & 7)) * ATT_RS +
                           ((lane >> 4) + np * 2) * 8) * 2;
            ldsm4t(vf[ks2][2 * np][0], vf[ks2][2 * np][1],
                   vf[ks2][2 * np + 1][0], vf[ks2][2 * np + 1][1], addr);
        }

    const float scale = 0.17677669529663687f;

#pragma unroll
    for (int qt = 0; qt < 4; qt++) {
        uint32_t qa[2][4];
#pragma unroll
        for (int ks = 0; ks < 2; ks++) {
            uint32_t addr = Qs +
                (uint32_t)((qt * 16 + ((lane >> 3) & 1) * 8 + (lane & 7)) * ATT_RS +
                           (lane >> 4) * 8 + ks * 16) * 2;
            ldsm4(qa[ks][0], qa[ks][1], qa[ks][2], qa[ks][3], addr);
        }

        float s[8][4];
#pragma unroll
        for (int nt2 = 0; nt2 < 8; nt2++)
#pragma unroll
            for (int r = 0; r < 4; r++) s[nt2][r] = 0.0f;
#pragma unroll
        for (int ks = 0; ks < 2; ks++)
#pragma unroll
            for (int nt2 = 0; nt2 < 8; nt2++)
                mma_fp16(s[nt2], qa[ks], kf[ks][nt2]);

        float mx0 = -1e30f, mx1 = -1e30f;
#pragma unroll
        for (int nt2 = 0; nt2 < 8; nt2++) {
            s[nt2][0] *= scale; s[nt2][1] *= scale;
            s[nt2][2] *= scale; s[nt2][3] *= scale;
            mx0 = fmaxf(mx0, fmaxf(s[nt2][0], s[nt2][1]));
            mx1 = fmaxf(mx1, fmaxf(s[nt2][2], s[nt2][3]));
        }
        mx0 = fmaxf(mx0, __shfl_xor_sync(0xffffffffu, mx0, 1));
        mx0 = fmaxf(mx0, __shfl_xor_sync(0xffffffffu, mx0, 2));
        mx1 = fmaxf(mx1, __shfl_xor_sync(0xffffffffu, mx1, 1));
        mx1 = fmaxf(mx1, __shfl_xor_sync(0xffffffffu, mx1, 2));

        float sm0 = 0.0f, sm1 = 0.0f;
#pragma unroll
        for (int nt2 = 0; nt2 < 8; nt2++) {
            s[nt2][0] = expf(s[nt2][0] - mx0);
            s[nt2][1] = expf(s[nt2][1] - mx0);
            s[nt2][2] = expf(s[nt2][2] - mx1);
            s[nt2][3] = expf(s[nt2][3] - mx1);
            sm0 += s[nt2][0] + s[nt2][1];
            sm1 += s[nt2][2] + s[nt2][3];
        }
        sm0 += __shfl_xor_sync(0xffffffffu, sm0, 1);
        sm0 += __shfl_xor_sync(0xffffffffu, sm0, 2);
        sm1 += __shfl_xor_sync(0xffffffffu, sm1, 1);
        sm1 += __shfl_xor_sync(0xffffffffu, sm1, 2);
        float inv0 = 1.0f / sm0, inv1 = 1.0f / sm1;

        uint32_t pa[4][4];
#pragma unroll
        for (int ks2 = 0; ks2 < 4; ks2++) {
            pa[ks2][0] = packh2(s[2 * ks2][0],     s[2 * ks2][1]);
            pa[ks2][1] = packh2(s[2 * ks2][2],     s[2 * ks2][3]);
            pa[ks2][2] = packh2(s[2 * ks2 + 1][0], s[2 * ks2 + 1][1]);
            pa[ks2][3] = packh2(s[2 * ks2 + 1][2], s[2 * ks2 + 1][3]);
        }

        float o[4][4];
#pragma unroll
        for (int nt2 = 0; nt2 < 4; nt2++)
#pragma unroll
            for (int r = 0; r < 4; r++) o[nt2][r] = 0.0f;
#pragma unroll
        for (int ks2 = 0; ks2 < 4; ks2++)
#pragma unroll
            for (int nt2 = 0; nt2 < 4; nt2++)
                mma_fp16(o[nt2], pa[ks2], vf[ks2][nt2]);

        int row0 = w * 64 + qt * 16 + grp;
        __nv_bfloat16* ob = att + (size_t)row0 * DMODEL + head * 32 + tig * 2;
#pragma unroll
        for (int nt2 = 0; nt2 < 4; nt2++) {
            __nv_bfloat162 p0 = {__float2bfloat16_rn(o[nt2][0] * inv0),
                                 __float2bfloat16_rn(o[nt2][1] * inv0)};
            __nv_bfloat162 p1 = {__float2bfloat16_rn(o[nt2][2] * inv1),
                                 __float2bfloat16_rn(o[nt2][3] * inv1)};
            *(__nv_bfloat162*)(ob + nt2 * 8) = p0;
            *(__nv_bfloat162*)(ob + 8 * DMODEL + nt2 * 8) = p1;
        }
    }
}

// ---------------------------------------------------------------------------
__global__ __launch_bounds__(256)
void final_ln(const float* __restrict__ x, const float* __restrict__ s,
              const float* __restrict__ b, float* __restrict__ out)
{
    int warp = threadIdx.x >> 5, lane = threadIdx.x & 31;
    int t = blockIdx.x * 8 + warp;
    size_t base = (size_t)t * DMODEL + lane * 8;

    float4 v0 = *(const float4*)(x + base);
    float4 v1 = *(const float4*)(x + base + 4);
    float v[8] = {v0.x, v0.y, v0.z, v0.w, v1.x, v1.y, v1.z, v1.w};

    float sum = 0.0f;
#pragma unroll
    for (int i = 0; i < 8; i++) sum += v[i];
#pragma unroll
    for (int o = 16; o > 0; o >>= 1) sum += __shfl_xor_sync(0xffffffffu, sum, o);
    float m = sum * (1.0f / 256.0f);

    float vs = 0.0f;
#pragma unroll
    for (int i = 0; i < 8; i++) { float d = v[i] - m; vs += d * d; }
#pragma unroll
    for (int o = 16; o > 0; o >>= 1) vs += __shfl_xor_sync(0xffffffffu, vs, o);
    float rstd = rsqrtf(vs * (1.0f / 256.0f) + 1e-5f);

    int bidx = t >> 10, l = t & 1023;
    int d0 = lane * 8;
#pragma unroll
    for (int i = 0; i < 8; i++) {
        float val = (v[i] - m) * rstd * s[d0 + i] + b[d0 + i];
        out[((size_t)bidx * DMODEL + d0 + i) * 1024 + l] = val;
    }
}

// ---------------------------------------------------------------------------
extern "C" void kernel_launch(void* const* d_in, const int* in_sizes, int n_in,
                              void* d_out, int out_size)
{
    const float* features = (const float*)d_in[0];
    const float* in_w  = (const float*)d_in[1];
    const float* in_b  = (const float*)d_in[2];
    const float* ow    = (const float*)d_in[3];
    const float* ob    = (const float*)d_in[4];
    const float* w1    = (const float*)d_in[5];
    const float* b1    = (const float*)d_in[6];
    const float* w2    = (const float*)d_in[7];
    const float* b2    = (const float*)d_in[8];
    const float* ln1s  = (const float*)d_in[9];
    const float* ln1b  = (const float*)d_in[10];
    const float* ln2s  = (const float*)d_in[11];
    const float* ln2b  = (const float*)d_in[12];
    const float* fns   = (const float*)d_in[13];
    const float* fnb   = (const float*)d_in[14];
    float* out = (float*)d_out;

    float* x;
    __half* qkvh;
    __nv_bfloat16 *xb, *att, *hh, *wb;
    cudaGetSymbolAddress((void**)&x,    g_x);
    cudaGetSymbolAddress((void**)&xb,   g_xb);
    cudaGetSymbolAddress((void**)&qkvh, g_qkv);
    cudaGetSymbolAddress((void**)&att,  g_att);
    cudaGetSymbolAddress((void**)&hh,   g_h);
    cudaGetSymbolAddress((void**)&wb,   g_wb);

    cudaFuncSetAttribute(gemm_bf16, cudaFuncAttributeMaxDynamicSharedMemorySize, GSMEM_SZ);
    cudaFuncSetAttribute(gemm_ln,   cudaFuncAttributeMaxDynamicSharedMemorySize, FG_SMEM);
    cudaFuncSetAttribute(attn_tc,   cudaFuncAttributeMaxDynamicSharedMemorySize, ATT_SMEM);

    cvt_all<<<(CV4 + 255) / 256, 256>>>(in_w, ow, w1, w2, wb);

    dim3 eb(32, 32);
    dim3 eg(32, 8, 32);
    embed_kernel<<<eg, eb>>>(features, x, xb);

    const int T = T_TOK;
    for (int i = 0; i < 3; i++) {
        gemm_bf16<<<dim3(DQKV / 128, T / 128), 256, GSMEM_SZ>>>(
            xb, wb + WT_INW + (size_t)i * DQKV * DMODEL, in_b + (size_t)i * DQKV,
            nullptr, qkvh, T, DQKV, DMODEL, 0, 2);
        attn_tc<<<dim3(512, 2), 128, ATT_SMEM>>>(qkvh, att);
        gemm_ln<<<T / 64, 256, FG_SMEM>>>(
            att, wb + WT_OW + (size_t)i * DMODEL * DMODEL, ob + (size_t)i * DMODEL,
            ln1s + (size_t)i * DMODEL, ln1b + (size_t)i * DMODEL, x, xb, DMODEL);
        gemm_bf16<<<dim3(DFFN / 128, T / 128), 256, GSMEM_SZ>>>(
            xb, wb + WT_W1 + (size_t)i * DFFN * DMODEL, b1 + (size_t)i * DFFN,
            hh, nullptr, T, DFFN, DMODEL, 1, 1);
        gemm_ln<<<T / 64, 256, FG_SMEM>>>(
            hh, wb + WT_W2 + (size_t)i * DMODEL * DFFN, b2 + (size_t)i * DMODEL,
            ln2s + (size_t)i * DMODEL, ln2b + (size_t)i * DMODEL, x, xb, DFFN);
    }
    final_ln<<<T / 8, 256>>>(x, fns, fnb, out);
}

// round 11
// speedup vs baseline: 5.9088x; 1.0070x over previous
#include <cuda_runtime.h>
#include <cuda_bf16.h>
#include <cuda_fp16.h>
#include <math.h>
#include <stdint.h>

// ---------------------------------------------------------------------------
// EfficientTransformerEncoder: B=32, D=256 -> L=1024, NH=8, NL=3, DFF=1024,
// WIN=64. bf16 mma.sync GEMMs (3-stage cp.async) + fp16 TC attention + fused LN.
// ---------------------------------------------------------------------------

#define T_TOK   32768
#define DMODEL  256
#define DQKV    768
#define DFFN    1024

__device__ float          g_x  [(size_t)T_TOK * DMODEL];
__device__ __nv_bfloat16  g_xb [(size_t)T_TOK * DMODEL];
__device__ __half         g_qkv[(size_t)T_TOK * DQKV];
__device__ __nv_bfloat16  g_att[(size_t)T_TOK * DMODEL];
__device__ __nv_bfloat16  g_h  [(size_t)T_TOK * DFFN];

#define WT_INW 0
#define WT_OW  (WT_INW + 3 * DQKV * DMODEL)
#define WT_W1  (WT_OW  + 3 * DMODEL * DMODEL)
#define WT_W2  (WT_W1  + 3 * DFFN * DMODEL)
#define WT_TOT (WT_W2  + 3 * DMODEL * DFFN)
__device__ __nv_bfloat16 g_wb[WT_TOT];

#define CV0 0
#define CV1 (WT_OW  / 4)
#define CV2 (WT_W1  / 4)
#define CV3 (WT_W2  / 4)
#define CV4 (WT_TOT / 4)

// ---------------------------------------------------------------------------
__global__ void cvt_all(const float* __restrict__ s0, const float* __restrict__ s1,
                        const float* __restrict__ s2, const float* __restrict__ s3,
                        __nv_bfloat16* __restrict__ dst) {
    int i = blockIdx.x * blockDim.x + threadIdx.x;
    if (i >= CV4) return;
    const float* src;
    int off;
    if (i < CV1)      { src = s0; off = i - CV0; }
    else if (i < CV2) { src = s1; off = i - CV1; }
    else if (i < CV3) { src = s2; off = i - CV2; }
    else              { src = s3; off = i - CV3; }
    float4 v = ((const float4*)src)[off];
    __nv_bfloat162 lo = {__float2bfloat16_rn(v.x), __float2bfloat16_rn(v.y)};
    __nv_bfloat162 hi = {__float2bfloat16_rn(v.z), __float2bfloat16_rn(v.w)};
    ((__nv_bfloat162*)dst)[i * 2]     = lo;
    ((__nv_bfloat162*)dst)[i * 2 + 1] = hi;
}

// ---------------------------------------------------------------------------
__device__ __forceinline__ float pe_val(int l, int d) {
    int i = d >> 1;
    float freq = expf(-(float)(2 * i) * 0.0359778920439f);
    float ang = (float)l * freq;
    return (d & 1) ? cosf(ang) : sinf(ang);
}

__global__ void embed_kernel(const float* __restrict__ f,
                             float* __restrict__ x, __nv_bfloat16* __restrict__ xb) {
    __shared__ float tile[32][33];
    int b  = blockIdx.z;
    int l0 = blockIdx.x * 32, d0 = blockIdx.y * 32;
    int tx = threadIdx.x, ty = threadIdx.y;
    tile[ty][tx] = f[((size_t)b * DMODEL + d0 + ty) * 1024 + l0 + tx];
    __syncthreads();
    int l = l0 + ty, d = d0 + tx;
    float v = tile[tx][ty] + pe_val(l, d);
    size_t idx = ((size_t)b * 1024 + l) * DMODEL + d;
    x[idx]  = v;
    xb[idx] = __float2bfloat16_rn(v);
}

// ---------------------------------------------------------------------------
__device__ __forceinline__ float gelu_exact(float v) {
    return 0.5f * v * (1.0f + erff(v * 0.7071067811865476f));
}

__device__ __forceinline__ void mma_bf16(float c[4], const uint32_t a[4], const uint32_t b[2]) {
    asm volatile(
        "mma.sync.aligned.m16n8k16.row.col.f32.bf16.bf16.f32 "
        "{%0,%1,%2,%3}, {%4,%5,%6,%7}, {%8,%9}, {%0,%1,%2,%3};\n"
        : "+f"(c[0]), "+f"(c[1]), "+f"(c[2]), "+f"(c[3])
        : "r"(a[0]), "r"(a[1]), "r"(a[2]), "r"(a[3]), "r"(b[0]), "r"(b[1]));
}

__device__ __forceinline__ void mma_fp16(float c[4], const uint32_t a[4], const uint32_t b[2]) {
    asm volatile(
        "mma.sync.aligned.m16n8k16.row.col.f32.f16.f16.f32 "
        "{%0,%1,%2,%3}, {%4,%5,%6,%7}, {%8,%9}, {%0,%1,%2,%3};\n"
        : "+f"(c[0]), "+f"(c[1]), "+f"(c[2]), "+f"(c[3])
        : "r"(a[0]), "r"(a[1]), "r"(a[2]), "r"(a[3]), "r"(b[0]), "r"(b[1]));
}

__device__ __forceinline__ void ldsm4(uint32_t& r0, uint32_t& r1, uint32_t& r2, uint32_t& r3,
                                      uint32_t addr) {
    asm volatile("ldmatrix.sync.aligned.m8n8.x4.shared.b16 {%0,%1,%2,%3}, [%4];"
                 : "=r"(r0), "=r"(r1), "=r"(r2), "=r"(r3) : "r"(addr));
}
__device__ __forceinline__ void ldsm4t(uint32_t& r0, uint32_t& r1, uint32_t& r2, uint32_t& r3,
                                       uint32_t addr) {
    asm volatile("ldmatrix.sync.aligned.m8n8.x4.trans.shared.b16 {%0,%1,%2,%3}, [%4];"
                 : "=r"(r0), "=r"(r1), "=r"(r2), "=r"(r3) : "r"(addr));
}

__device__ __forceinline__ void cpa16(uint32_t dst, const void* src) {
    asm volatile("cp.async.cg.shared.global [%0], [%1], 16;\n" :: "r"(dst), "l"(src));
}
__device__ __forceinline__ void cpa_commit() {
    asm volatile("cp.async.commit_group;\n" ::: "memory");
}
__device__ __forceinline__ void cpa_wait0() {
    asm volatile("cp.async.wait_group 0;\n" ::: "memory");
}
__device__ __forceinline__ void cpa_wait1() {
    asm volatile("cp.async.wait_group 1;\n" ::: "memory");
}

__device__ __forceinline__ uint32_t packh2(float x, float y) {
    __half2 h = __floats2half2_rn(x, y);
    return *reinterpret_cast<uint32_t*>(&h);
}

#define SMH  72
#define ROWB (SMH * 2)

// ---------------------------------------------------------------------------
// Generic 128x128 bf16 GEMM, 3-stage cp.async pipeline.
// outmode: 1 -> bf16 Cb, 2 -> fp16 Ch.
// ---------------------------------------------------------------------------
#define MATB (128 * ROWB)          // 18432 per matrix per stage
#define GSMEM_SZ (6 * MATB)        // 110592 (A0..A2 | B0..B2)

__global__ void __launch_bounds__(256, 2)
gemm_bf16(const __nv_bfloat16* __restrict__ A, const __nv_bfloat16* __restrict__ B,
          const float* __restrict__ bias,
          __nv_bfloat16* __restrict__ Cb, __half* __restrict__ Ch,
          int M, int N, int K, int act, int outmode)
{
    extern __shared__ __nv_bfloat16 smem[];
    uint32_t sbase = (uint32_t)__cvta_generic_to_shared(smem);
    uint32_t aBase = sbase;
    uint32_t bBase = sbase + 3 * MATB;

    int tid  = threadIdx.x;
    int warp = tid >> 5, lane = tid & 31;
    int wm = (warp >> 2) * 64;
    int wn = (warp & 3) * 32;
    int grp = lane >> 2, tig = lane & 3;

    const __nv_bfloat16* Ab = A + (size_t)blockIdx.y * 128 * K;
    const __nv_bfloat16* Bb = B + (size_t)blockIdx.x * 128 * K;

    int rowc[4], choff[4];
#pragma unroll
    for (int i = 0; i < 4; i++) {
        int c = tid + 256 * i;
        rowc[i]  = c >> 3;
        choff[i] = (c & 7) * 8;
    }

    int aRow = wm + ((lane >> 3) & 1) * 8 + (lane & 7);
    int aK   = (lane >> 4) * 8;
    int bRow = wn + (lane >> 4) * 8 + (lane & 7);
    int bK   = ((lane >> 3) & 1) * 8;
    uint32_t aAddr = aBase + (uint32_t)aRow * ROWB + (uint32_t)aK * 2;
    uint32_t bAddr = bBase + (uint32_t)bRow * ROWB + (uint32_t)bK * 2;

    float acc[4][4][4];
#pragma unroll
    for (int mi = 0; mi < 4; mi++)
#pragma unroll
        for (int ni = 0; ni < 4; ni++)
#pragma unroll
            for (int r = 0; r < 4; r++) acc[mi][ni][r] = 0.0f;

    int nt = K >> 6;

#define LOAD_TILE(t)                                                           \
    do {                                                                       \
        uint32_t off_ = (uint32_t)((t) % 3) * MATB;                            \
        int k0_ = (t) << 6;                                                    \
        _Pragma("unroll")                                                      \
        for (int i_ = 0; i_ < 4; i_++) {                                       \
            uint32_t d_ = off_ + (uint32_t)rowc[i_] * ROWB + (uint32_t)choff[i_] * 2; \
            cpa16(aBase + d_, Ab + (size_t)rowc[i_] * K + k0_ + choff[i_]);    \
            cpa16(bBase + d_, Bb + (size_t)rowc[i_] * K + k0_ + choff[i_]);    \
        }                                                                      \
        cpa_commit();                                                          \
    } while (0)

    // prefetch 2 tiles
    LOAD_TILE(0);
    if (nt > 1) LOAD_TILE(1);

    for (int j = 0; j < nt; j++) {
        if (j + 1 < nt) cpa_wait1(); else cpa_wait0();
        __syncthreads();
        if (j + 2 < nt) LOAD_TILE(j + 2);

        uint32_t bufOff = (uint32_t)(j % 3) * MATB;
#pragma unroll
        for (int ks = 0; ks < 4; ks++) {
            uint32_t kOff = bufOff + (uint32_t)(ks * 32);
            uint32_t af[4][4], bf[4][2];
#pragma unroll
            for (int mi = 0; mi < 4; mi++)
                ldsm4(af[mi][0], af[mi][1], af[mi][2], af[mi][3],
                      aAddr + kOff + (uint32_t)(mi * 16) * ROWB);
#pragma unroll
            for (int pi = 0; pi < 2; pi++)
                ldsm4(bf[2 * pi][0], bf[2 * pi][1], bf[2 * pi + 1][0], bf[2 * pi + 1][1],
                      bAddr + kOff + (uint32_t)(pi * 16) * ROWB);
#pragma unroll
            for (int mi = 0; mi < 4; mi++)
#pragma unroll
                for (int ni = 0; ni < 4; ni++)
                    mma_bf16(acc[mi][ni], af[mi], bf[ni]);
        }
    }

#pragma unroll
    for (int mi = 0; mi < 4; mi++) {
        int r0 = blockIdx.y * 128 + wm + mi * 16 + grp;
#pragma unroll
        for (int ni = 0; ni < 4; ni++) {
            int c = blockIdx.x * 128 + wn + ni * 8 + tig * 2;
            float bv0 = __ldg(bias + c), bv1 = __ldg(bias + c + 1);
            float v0 = acc[mi][ni][0] + bv0;
            float v1 = acc[mi][ni][1] + bv1;
            float v2 = acc[mi][ni][2] + bv0;
            float v3 = acc[mi][ni][3] + bv1;
            if (act == 1) {
                v0 = gelu_exact(v0); v1 = gelu_exact(v1);
                v2 = gelu_exact(v2); v3 = gelu_exact(v3);
            }
            if (outmode == 1) {
                __nv_bfloat162 p0 = {__float2bfloat16_rn(v0), __float2bfloat16_rn(v1)};
                __nv_bfloat162 p1 = {__float2bfloat16_rn(v2), __float2bfloat16_rn(v3)};
                *(__nv_bfloat162*)(Cb + (size_t)r0 * N + c) = p0;
                *(__nv_bfloat162*)(Cb + (size_t)(r0 + 8) * N + c) = p1;
            } else {
                uint32_t p0 = packh2(v0, v1), p1 = packh2(v2, v3);
                *(uint32_t*)(Ch + (size_t)r0 * N + c) = p0;
                *(uint32_t*)(Ch + (size_t)(r0 + 8) * N + c) = p1;
            }
        }
    }
}

// ---------------------------------------------------------------------------
// Fused GEMM(N=256) + residual + LayerNorm. Block tile 64x256, 8 warps (1x8).
// 2-stage pipeline, single barrier per k-tile.
// ---------------------------------------------------------------------------
#define FA_B  (64 * ROWB)
#define FB_B  (256 * ROWB)
#define FG_SMEM (2 * FA_B + 2 * FB_B)
#define STG_S 264

__global__ void __launch_bounds__(256, 2)
gemm_ln(const __nv_bfloat16* __restrict__ A, const __nv_bfloat16* __restrict__ B,
        const float* __restrict__ bias,
        const float* __restrict__ lns, const float* __restrict__ lnb,
        float* __restrict__ x, __nv_bfloat16* __restrict__ xb, int K)
{
    extern __shared__ __nv_bfloat16 smem[];
    uint32_t sbase = (uint32_t)__cvta_generic_to_shared(smem);
    uint32_t aBase = sbase;
    uint32_t bBase = sbase + 2 * FA_B;

    int tid  = threadIdx.x;
    int warp = tid >> 5, lane = tid & 31;
    int wn = warp * 32;
    int grp = lane >> 2, tig = lane & 3;

    const __nv_bfloat16* Ab = A + (size_t)blockIdx.x * 64 * K;

    int aRowc[2], aChoff[2];
#pragma unroll
    for (int i = 0; i < 2; i++) {
        int c = tid + 256 * i;
        aRowc[i]  = c >> 3;
        aChoff[i] = (c & 7) * 8;
    }
    int bRowc[8], bChoff[8];
#pragma unroll
    for (int i = 0; i < 8; i++) {
        int c = tid + 256 * i;
        bRowc[i]  = c >> 3;
        bChoff[i] = (c & 7) * 8;
    }

    int aRow = ((lane >> 3) & 1) * 8 + (lane & 7);
    int aK   = (lane >> 4) * 8;
    int bRow = wn + (lane >> 4) * 8 + (lane & 7);
    int bK   = ((lane >> 3) & 1) * 8;
    uint32_t aAddr = aBase + (uint32_t)aRow * ROWB + (uint32_t)aK * 2;
    uint32_t bAddr = bBase + (uint32_t)bRow * ROWB + (uint32_t)bK * 2;

    float acc[4][4][4];
#pragma unroll
    for (int mi = 0; mi < 4; mi++)
#pragma unroll
        for (int ni = 0; ni < 4; ni++)
#pragma unroll
            for (int r = 0; r < 4; r++) acc[mi][ni][r] = 0.0f;

    int nt = K >> 6;

#define FLOAD_TILE(t)                                                          \
    do {                                                                       \
        uint32_t oa_ = (uint32_t)((t) & 1) * FA_B;                             \
        uint32_t ob_ = (uint32_t)((t) & 1) * FB_B;                             \
        int k0_ = (t) << 6;                                                    \
        _Pragma("unroll")                                                      \
        for (int i_ = 0; i_ < 2; i_++)                                         \
            cpa16(aBase + oa_ + (uint32_t)aRowc[i_] * ROWB + (uint32_t)aChoff[i_] * 2, \
                  Ab + (size_t)aRowc[i_] * K + k0_ + aChoff[i_]);              \
        _Pragma("unroll")                                                      \
        for (int i_ = 0; i_ < 8; i_++)                                         \
            cpa16(bBase + ob_ + (uint32_t)bRowc[i_] * ROWB + (uint32_t)bChoff[i_] * 2, \
                  B + (size_t)bRowc[i_] * K + k0_ + bChoff[i_]);               \
        cpa_commit();                                                          \
    } while (0)

    FLOAD_TILE(0);

    for (int j = 0; j < nt; j++) {
        cpa_wait0();
        __syncthreads();
        if (j + 1 < nt) FLOAD_TILE(j + 1);

        uint32_t aOff = (uint32_t)(j & 1) * FA_B;
        uint32_t bOff = (uint32_t)(j & 1) * FB_B;
#pragma unroll
        for (int ks = 0; ks < 4; ks++) {
            uint32_t kb = (uint32_t)(ks * 32);
            uint32_t af[4][4], bf[4][2];
#pragma unroll
            for (int mi = 0; mi < 4; mi++)
                ldsm4(af[mi][0], af[mi][1], af[mi][2], af[mi][3],
                      aAddr + aOff + kb + (uint32_t)(mi * 16) * ROWB);
#pragma unroll
            for (int pi = 0; pi < 2; pi++)
                ldsm4(bf[2 * pi][0], bf[2 * pi][1], bf[2 * pi + 1][0], bf[2 * pi + 1][1],
                      bAddr + bOff + kb + (uint32_t)(pi * 16) * ROWB);
#pragma unroll
            for (int mi = 0; mi < 4; mi++)
#pragma unroll
                for (int ni = 0; ni < 4; ni++)
                    mma_bf16(acc[mi][ni], af[mi], bf[ni]);
        }
    }
    __syncthreads();   // all warps done before smem is reused for staging

    float* stage = (float*)smem;
#pragma unroll
    for (int mi = 0; mi < 4; mi++) {
        int r0 = mi * 16 + grp;
#pragma unroll
        for (int ni = 0; ni < 4; ni++) {
            int c = wn + ni * 8 + tig * 2;
            float bv0 = __ldg(bias + c), bv1 = __ldg(bias + c + 1);
            stage[r0 * STG_S + c]           = acc[mi][ni][0] + bv0;
            stage[r0 * STG_S + c + 1]       = acc[mi][ni][1] + bv1;
            stage[(r0 + 8) * STG_S + c]     = acc[mi][ni][2] + bv0;
            stage[(r0 + 8) * STG_S + c + 1] = acc[mi][ni][3] + bv1;
        }
    }
    __syncthreads();

    float4 sv0 = *(const float4*)(lns + lane * 8);
    float4 sv1 = *(const float4*)(lns + lane * 8 + 4);
    float4 bv0 = *(const float4*)(lnb + lane * 8);
    float4 bv1 = *(const float4*)(lnb + lane * 8 + 4);
    float sc[8] = {sv0.x, sv0.y, sv0.z, sv0.w, sv1.x, sv1.y, sv1.z, sv1.w};
    float bi[8] = {bv0.x, bv0.y, bv0.z, bv0.w, bv1.x, bv1.y, bv1.z, bv1.w};

#pragma unroll
    for (int it = 0; it < 8; it++) {
        int tok = warp * 8 + it;
        size_t gbase = ((size_t)blockIdx.x * 64 + tok) * DMODEL + lane * 8;
        const float* sp = stage + tok * STG_S + lane * 8;

        float4 xv0 = *(const float4*)(x + gbase);
        float4 xv1 = *(const float4*)(x + gbase + 4);
        float v[8] = {xv0.x + sp[0], xv0.y + sp[1], xv0.z + sp[2], xv0.w + sp[3],
                      xv1.x + sp[4], xv1.y + sp[5], xv1.z + sp[6], xv1.w + sp[7]};

        float sum = 0.0f;
#pragma unroll
        for (int i = 0; i < 8; i++) sum += v[i];
#pragma unroll
        for (int o = 16; o > 0; o >>= 1) sum += __shfl_xor_sync(0xffffffffu, sum, o);
        float m = sum * (1.0f / 256.0f);

        float vs = 0.0f;
#pragma unroll
        for (int i = 0; i < 8; i++) { float d = v[i] - m; vs += d * d; }
#pragma unroll
        for (int o = 16; o > 0; o >>= 1) vs += __shfl_xor_sync(0xffffffffu, vs, o);
        float rstd = rsqrtf(vs * (1.0f / 256.0f) + 1e-5f);

        float o_[8];
#pragma unroll
        for (int i = 0; i < 8; i++) o_[i] = (v[i] - m) * rstd * sc[i] + bi[i];

        float4 w0 = {o_[0], o_[1], o_[2], o_[3]};
        float4 w1 = {o_[4], o_[5], o_[6], o_[7]};
        *(float4*)(x + gbase) = w0;
        *(float4*)(x + gbase + 4) = w1;
#pragma unroll
        for (int i = 0; i < 8; i += 2) {
            __nv_bfloat162 c2 = {__float2bfloat16_rn(o_[i]), __float2bfloat16_rn(o_[i + 1])};
            *(__nv_bfloat162*)(xb + gbase + i) = c2;
        }
    }
}

// ---------------------------------------------------------------------------
// Tensor-core windowed attention (fp16 mma, fp32 softmax).
// ---------------------------------------------------------------------------
#define ATT_RS   40
#define ATT_MATH (64 * ATT_RS)
#define ATT_WARPH (3 * ATT_MATH)
#define ATT_SMEM (4 * ATT_WARPH * 2)

__global__ void __launch_bounds__(128)
attn_tc(const __half* __restrict__ qkv, __nv_bfloat16* __restrict__ att)
{
    extern __shared__ __half ash[];
    int tid = threadIdx.x, warp = tid >> 5, lane = tid & 31;
    int w = blockIdx.x;
    int head = blockIdx.y * 4 + warp;
    int grp = lane >> 2, tig = lane & 3;

    __half* base = ash + warp * ATT_WARPH;
    uint32_t sb = (uint32_t)__cvta_generic_to_shared(base);

    const __half* src = qkv + (size_t)w * 64 * DQKV + head * 32;
#pragma unroll
    for (int m = 0; m < 3; m++) {
        const __half* ms = src + m * 256;
        __half* dst = base + m * ATT_MATH;
#pragma unroll
        for (int p = 0; p < 8; p++) {
            int c = p * 32 + lane;
            int row = c >> 2, ch = c & 3;
            *(uint4*)(dst + row * ATT_RS + ch * 8) =
                *(const uint4*)(ms + (size_t)row * DQKV + ch * 8);
        }
    }
    __syncwarp();

    const uint32_t Qs = sb;
    const uint32_t Ks = sb + ATT_MATH * 2;
    const uint32_t Vs = sb + 2 * ATT_MATH * 2;

    uint32_t kf[2][8][2];
#pragma unroll
    for (int ks = 0; ks < 2; ks++)
#pragma unroll
        for (int pi = 0; pi < 4; pi++) {
            uint32_t addr = Ks +
                (uint32_t)((pi * 16 + (lane >> 4) * 8 + (lane & 7)) * ATT_RS +
                           ((lane >> 3) & 1) * 8 + ks * 16) * 2;
            ldsm4(kf[ks][2 * pi][0], kf[ks][2 * pi][1],
                  kf[ks][2 * pi + 1][0], kf[ks][2 * pi + 1][1], addr);
        }

    uint32_t vf[4][4][2];
#pragma unroll
    for (int ks2 = 0; ks2 < 4; ks2++)
#pragma unroll
        for (int np = 0; np < 2; np++) {
            uint32_t addr = Vs +
                (uint32_t)((ks2 * 16 + ((lane >> 3) & 1) * 8 + (lane & 7)) * ATT_RS +
                           ((lane >> 4) + np * 2) * 8) * 2;
            ldsm4t(vf[ks2][2 * np][0], vf[ks2][2 * np][1],
                   vf[ks2][2 * np + 1][0], vf[ks2][2 * np + 1][1], addr);
        }

    const float scale = 0.17677669529663687f;

#pragma unroll
    for (int qt = 0; qt < 4; qt++) {
        uint32_t qa[2][4];
#pragma unroll
        for (int ks = 0; ks < 2; ks++) {
            uint32_t addr = Qs +
                (uint32_t)((qt * 16 + ((lane >> 3) & 1) * 8 + (lane & 7)) * ATT_RS +
                           (lane >> 4) * 8 + ks * 16) * 2;
            ldsm4(qa[ks][0], qa[ks][1], qa[ks][2], qa[ks][3], addr);
        }

        float s[8][4];
#pragma unroll
        for (int nt2 = 0; nt2 < 8; nt2++)
#pragma unroll
            for (int r = 0; r < 4; r++) s[nt2][r] = 0.0f;
#pragma unroll
        for (int ks = 0; ks < 2; ks++)
#pragma unroll
            for (int nt2 = 0; nt2 < 8; nt2++)
                mma_fp16(s[nt2], qa[ks], kf[ks][nt2]);

        float mx0 = -1e30f, mx1 = -1e30f;
#pragma unroll
        for (int nt2 = 0; nt2 < 8; nt2++) {
            s[nt2][0] *= scale; s[nt2][1] *= scale;
            s[nt2][2] *= scale; s[nt2][3] *= scale;
            mx0 = fmaxf(mx0, fmaxf(s[nt2][0], s[nt2][1]));
            mx1 = fmaxf(mx1, fmaxf(s[nt2][2], s[nt2][3]));
        }
        mx0 = fmaxf(mx0, __shfl_xor_sync(0xffffffffu, mx0, 1));
        mx0 = fmaxf(mx0, __shfl_xor_sync(0xffffffffu, mx0, 2));
        mx1 = fmaxf(mx1, __shfl_xor_sync(0xffffffffu, mx1, 1));
        mx1 = fmaxf(mx1, __shfl_xor_sync(0xffffffffu, mx1, 2));

        float sm0 = 0.0f, sm1 = 0.0f;
#pragma unroll
        for (int nt2 = 0; nt2 < 8; nt2++) {
            s[nt2][0] = expf(s[nt2][0] - mx0);
            s[nt2][1] = expf(s[nt2][1] - mx0);
            s[nt2][2] = expf(s[nt2][2] - mx1);
            s[nt2][3] = expf(s[nt2][3] - mx1);
            sm0 += s[nt2][0] + s[nt2][1];
            sm1 += s[nt2][2] + s[nt2][3];
        }
        sm0 += __shfl_xor_sync(0xffffffffu, sm0, 1);
        sm0 += __shfl_xor_sync(0xffffffffu, sm0, 2);
        sm1 += __shfl_xor_sync(0xffffffffu, sm1, 1);
        sm1 += __shfl_xor_sync(0xffffffffu, sm1, 2);
        float inv0 = 1.0f / sm0, inv1 = 1.0f / sm1;

        uint32_t pa[4][4];
#pragma unroll
        for (int ks2 = 0; ks2 < 4; ks2++) {
            pa[ks2][0] = packh2(s[2 * ks2][0],     s[2 * ks2][1]);
            pa[ks2][1] = packh2(s[2 * ks2][2],     s[2 * ks2][3]);
            pa[ks2][2] = packh2(s[2 * ks2 + 1][0], s[2 * ks2 + 1][1]);
            pa[ks2][3] = packh2(s[2 * ks2 + 1][2], s[2 * ks2 + 1][3]);
        }

        float o[4][4];
#pragma unroll
        for (int nt2 = 0; nt2 < 4; nt2++)
#pragma unroll
            for (int r = 0; r < 4; r++) o[nt2][r] = 0.0f;
#pragma unroll
        for (int ks2 = 0; ks2 < 4; ks2++)
#pragma unroll
            for (int nt2 = 0; nt2 < 4; nt2++)
                mma_fp16(o[nt2], pa[ks2], vf[ks2][nt2]);

        int row0 = w * 64 + qt * 16 + grp;
        __nv_bfloat16* ob = att + (size_t)row0 * DMODEL + head * 32 + tig * 2;
#pragma unroll
        for (int nt2 = 0; nt2 < 4; nt2++) {
            __nv_bfloat162 p0 = {__float2bfloat16_rn(o[nt2][0] * inv0),
                                 __float2bfloat16_rn(o[nt2][1] * inv0)};
            __nv_bfloat162 p1 = {__float2bfloat16_rn(o[nt2][2] * inv1),
                                 __float2bfloat16_rn(o[nt2][3] * inv1)};
            *(__nv_bfloat162*)(ob + nt2 * 8) = p0;
            *(__nv_bfloat162*)(ob + 8 * DMODEL + nt2 * 8) = p1;
        }
    }
}

// ---------------------------------------------------------------------------
__global__ __launch_bounds__(256)
void final_ln(const float* __restrict__ x, const float* __restrict__ s,
              const float* __restrict__ b, float* __restrict__ out)
{
    int warp = threadIdx.x >> 5, lane = threadIdx.x & 31;
    int t = blockIdx.x * 8 + warp;
    size_t base = (size_t)t * DMODEL + lane * 8;

    float4 v0 = *(const float4*)(x + base);
    float4 v1 = *(const float4*)(x + base + 4);
    float v[8] = {v0.x, v0.y, v0.z, v0.w, v1.x, v1.y, v1.z, v1.w};

    float sum = 0.0f;
#pragma unroll
    for (int i = 0; i < 8; i++) sum += v[i];
#pragma unroll
    for (int o = 16; o > 0; o >>= 1) sum += __shfl_xor_sync(0xffffffffu, sum, o);
    float m = sum * (1.0f / 256.0f);

    float vs = 0.0f;
#pragma unroll
    for (int i = 0; i < 8; i++) { float d = v[i] - m; vs += d * d; }
#pragma unroll
    for (int o = 16; o > 0; o >>= 1) vs += __shfl_xor_sync(0xffffffffu, vs, o);
    float rstd = rsqrtf(vs * (1.0f / 256.0f) + 1e-5f);

    int bidx = t >> 10, l = t & 1023;
    int d0 = lane * 8;
#pragma unroll
    for (int i = 0; i < 8; i++) {
        float val = (v[i] - m) * rstd * s[d0 + i] + b[d0 + i];
        out[((size_t)bidx * DMODEL + d0 + i) * 1024 + l] = val;
    }
}

// ---------------------------------------------------------------------------
extern "C" void kernel_launch(void* const* d_in, const int* in_sizes, int n_in,
                              void* d_out, int out_size)
{
    const float* features = (const float*)d_in[0];
    const float* in_w  = (const float*)d_in[1];
    const float* in_b  = (const float*)d_in[2];
    const float* ow    = (const float*)d_in[3];
    const float* ob    = (const float*)d_in[4];
    const float* w1    = (const float*)d_in[5];
    const float* b1    = (const float*)d_in[6];
    const float* w2    = (const float*)d_in[7];
    const float* b2    = (const float*)d_in[8];
    const float* ln1s  = (const float*)d_in[9];
    const float* ln1b  = (const float*)d_in[10];
    const float* ln2s  = (const float*)d_in[11];
    const float* ln2b  = (const float*)d_in[12];
    const float* fns   = (const float*)d_in[13];
    const float* fnb   = (const float*)d_in[14];
    float* out = (float*)d_out;

    float* x;
    __half* qkvh;
    __nv_bfloat16 *xb, *att, *hh, *wb;
    cudaGetSymbolAddress((void**)&x,    g_x);
    cudaGetSymbolAddress((void**)&xb,   g_xb);
    cudaGetSymbolAddress((void**)&qkvh, g_qkv);
    cudaGetSymbolAddress((void**)&att,  g_att);
    cudaGetSymbolAddress((void**)&hh,   g_h);
    cudaGetSymbolAddress((void**)&wb,   g_wb);

    cudaFuncSetAttribute(gemm_bf16, cudaFuncAttributeMaxDynamicSharedMemorySize, GSMEM_SZ);
    cudaFuncSetAttribute(gemm_ln,   cudaFuncAttributeMaxDynamicSharedMemorySize, FG_SMEM);
    cudaFuncSetAttribute(attn_tc,   cudaFuncAttributeMaxDynamicSharedMemorySize, ATT_SMEM);

    cvt_all<<<(CV4 + 255) / 256, 256>>>(in_w, ow, w1, w2, wb);

    dim3 eb(32, 32);
    dim3 eg(32, 8, 32);
    embed_kernel<<<eg, eb>>>(features, x, xb);

    const int T = T_TOK;
    for (int i = 0; i < 3; i++) {
        gemm_bf16<<<dim3(DQKV / 128, T / 128), 256, GSMEM_SZ>>>(
            xb, wb + WT_INW + (size_t)i * DQKV * DMODEL, in_b + (size_t)i * DQKV,
            nullptr, qkvh, T, DQKV, DMODEL, 0, 2);
        attn_tc<<<dim3(512, 2), 128, ATT_SMEM>>>(qkvh, att);
        gemm_ln<<<T / 64, 256, FG_SMEM>>>(
            att, wb + WT_OW + (size_t)i * DMODEL * DMODEL, ob + (size_t)i * DMODEL,
            ln1s + (size_t)i * DMODEL, ln1b + (size_t)i * DMODEL, x, xb, DMODEL);
        gemm_bf16<<<dim3(DFFN / 128, T / 128), 256, GSMEM_SZ>>>(
            xb, wb + WT_W1 + (size_t)i * DFFN * DMODEL, b1 + (size_t)i * DFFN,
            hh, nullptr, T, DFFN, DMODEL, 1, 1);
        gemm_ln<<<T / 64, 256, FG_SMEM>>>(
            hh, wb + WT_W2 + (size_t)i * DMODEL * DFFN, b2 + (size_t)i * DMODEL,
            ln2s + (size_t)i * DMODEL, ln2b + (size_t)i * DMODEL, x, xb, DFFN);
    }
    final_ln<<<T / 8, 256>>>(x, fns, fnb, out);
}

// round 12
// speedup vs baseline: 6.1798x; 1.0459x over previous
#include <cuda_runtime.h>
#include <cuda_bf16.h>
#include <cuda_fp16.h>
#include <math.h>
#include <stdint.h>

// ---------------------------------------------------------------------------
// EfficientTransformerEncoder: B=32, D=256 -> L=1024, NH=8, NL=3, DFF=1024,
// WIN=64. bf16 mma.sync GEMMs (3-stage cp.async) + fp16 TC attention + fused LN.
// ---------------------------------------------------------------------------

#define T_TOK   32768
#define DMODEL  256
#define DQKV    768
#define DFFN    1024

__device__ float          g_x  [(size_t)T_TOK * DMODEL];
__device__ __nv_bfloat16  g_xb [(size_t)T_TOK * DMODEL];
__device__ __half         g_qkv[(size_t)T_TOK * DQKV];
__device__ __nv_bfloat16  g_att[(size_t)T_TOK * DMODEL];
__device__ __nv_bfloat16  g_h  [(size_t)T_TOK * DFFN];

#define WT_INW 0
#define WT_OW  (WT_INW + 3 * DQKV * DMODEL)
#define WT_W1  (WT_OW  + 3 * DMODEL * DMODEL)
#define WT_W2  (WT_W1  + 3 * DFFN * DMODEL)
#define WT_TOT (WT_W2  + 3 * DMODEL * DFFN)
__device__ __nv_bfloat16 g_wb[WT_TOT];

#define CV0 0
#define CV1 (WT_OW  / 4)
#define CV2 (WT_W1  / 4)
#define CV3 (WT_W2  / 4)
#define CV4 (WT_TOT / 4)

// ---------------------------------------------------------------------------
__global__ void cvt_all(const float* __restrict__ s0, const float* __restrict__ s1,
                        const float* __restrict__ s2, const float* __restrict__ s3,
                        __nv_bfloat16* __restrict__ dst) {
    int i = blockIdx.x * blockDim.x + threadIdx.x;
    if (i >= CV4) return;
    const float* src;
    int off;
    if (i < CV1)      { src = s0; off = i - CV0; }
    else if (i < CV2) { src = s1; off = i - CV1; }
    else if (i < CV3) { src = s2; off = i - CV2; }
    else              { src = s3; off = i - CV3; }
    float4 v = ((const float4*)src)[off];
    __nv_bfloat162 lo = {__float2bfloat16_rn(v.x), __float2bfloat16_rn(v.y)};
    __nv_bfloat162 hi = {__float2bfloat16_rn(v.z), __float2bfloat16_rn(v.w)};
    ((__nv_bfloat162*)dst)[i * 2]     = lo;
    ((__nv_bfloat162*)dst)[i * 2 + 1] = hi;
}

// ---------------------------------------------------------------------------
__device__ __forceinline__ float pe_val(int l, int d) {
    int i = d >> 1;
    float freq = expf(-(float)(2 * i) * 0.0359778920439f);
    float ang = (float)l * freq;
    return (d & 1) ? cosf(ang) : sinf(ang);
}

__global__ void embed_kernel(const float* __restrict__ f,
                             float* __restrict__ x, __nv_bfloat16* __restrict__ xb) {
    __shared__ float tile[32][33];
    int b  = blockIdx.z;
    int l0 = blockIdx.x * 32, d0 = blockIdx.y * 32;
    int tx = threadIdx.x, ty = threadIdx.y;
    tile[ty][tx] = f[((size_t)b * DMODEL + d0 + ty) * 1024 + l0 + tx];
    __syncthreads();
    int l = l0 + ty, d = d0 + tx;
    float v = tile[tx][ty] + pe_val(l, d);
    size_t idx = ((size_t)b * 1024 + l) * DMODEL + d;
    x[idx]  = v;
    xb[idx] = __float2bfloat16_rn(v);
}

// ---------------------------------------------------------------------------
__device__ __forceinline__ float gelu_exact(float v) {
    return 0.5f * v * (1.0f + erff(v * 0.7071067811865476f));
}

__device__ __forceinline__ void mma_bf16(float c[4], const uint32_t a[4], const uint32_t b[2]) {
    asm volatile(
        "mma.sync.aligned.m16n8k16.row.col.f32.bf16.bf16.f32 "
        "{%0,%1,%2,%3}, {%4,%5,%6,%7}, {%8,%9}, {%0,%1,%2,%3};\n"
        : "+f"(c[0]), "+f"(c[1]), "+f"(c[2]), "+f"(c[3])
        : "r"(a[0]), "r"(a[1]), "r"(a[2]), "r"(a[3]), "r"(b[0]), "r"(b[1]));
}

__device__ __forceinline__ void mma_fp16(float c[4], const uint32_t a[4], const uint32_t b[2]) {
    asm volatile(
        "mma.sync.aligned.m16n8k16.row.col.f32.f16.f16.f32 "
        "{%0,%1,%2,%3}, {%4,%5,%6,%7}, {%8,%9}, {%0,%1,%2,%3};\n"
        : "+f"(c[0]), "+f"(c[1]), "+f"(c[2]), "+f"(c[3])
        : "r"(a[0]), "r"(a[1]), "r"(a[2]), "r"(a[3]), "r"(b[0]), "r"(b[1]));
}

__device__ __forceinline__ void ldsm4(uint32_t& r0, uint32_t& r1, uint32_t& r2, uint32_t& r3,
                                      uint32_t addr) {
    asm volatile("ldmatrix.sync.aligned.m8n8.x4.shared.b16 {%0,%1,%2,%3}, [%4];"
                 : "=r"(r0), "=r"(r1), "=r"(r2), "=r"(r3) : "r"(addr));
}
__device__ __forceinline__ void ldsm4t(uint32_t& r0, uint32_t& r1, uint32_t& r2, uint32_t& r3,
                                       uint32_t addr) {
    asm volatile("ldmatrix.sync.aligned.m8n8.x4.trans.shared.b16 {%0,%1,%2,%3}, [%4];"
                 : "=r"(r0), "=r"(r1), "=r"(r2), "=r"(r3) : "r"(addr));
}

__device__ __forceinline__ void cpa16(uint32_t dst, const void* src) {
    asm volatile("cp.async.cg.shared.global [%0], [%1], 16;\n" :: "r"(dst), "l"(src));
}
__device__ __forceinline__ void cpa_commit() {
    asm volatile("cp.async.commit_group;\n" ::: "memory");
}
__device__ __forceinline__ void cpa_wait0() {
    asm volatile("cp.async.wait_group 0;\n" ::: "memory");
}
__device__ __forceinline__ void cpa_wait1() {
    asm volatile("cp.async.wait_group 1;\n" ::: "memory");
}

__device__ __forceinline__ uint32_t packh2(float x, float y) {
    __half2 h = __floats2half2_rn(x, y);
    return *reinterpret_cast<uint32_t*>(&h);
}

#define SMH  72
#define ROWB (SMH * 2)

// ---------------------------------------------------------------------------
// Generic 128x128 bf16 GEMM, 3-stage cp.async pipeline.
// ---------------------------------------------------------------------------
#define MATB (128 * ROWB)
#define GSMEM_SZ (6 * MATB)

__global__ void __launch_bounds__(256, 2)
gemm_bf16(const __nv_bfloat16* __restrict__ A, const __nv_bfloat16* __restrict__ B,
          const float* __restrict__ bias,
          __nv_bfloat16* __restrict__ Cb, __half* __restrict__ Ch,
          int M, int N, int K, int act, int outmode)
{
    extern __shared__ __nv_bfloat16 smem[];
    uint32_t sbase = (uint32_t)__cvta_generic_to_shared(smem);
    uint32_t aBase = sbase;
    uint32_t bBase = sbase + 3 * MATB;

    int tid  = threadIdx.x;
    int warp = tid >> 5, lane = tid & 31;
    int wm = (warp >> 2) * 64;
    int wn = (warp & 3) * 32;
    int grp = lane >> 2, tig = lane & 3;

    const __nv_bfloat16* Ab = A + (size_t)blockIdx.y * 128 * K;
    const __nv_bfloat16* Bb = B + (size_t)blockIdx.x * 128 * K;

    int rowc[4], choff[4];
#pragma unroll
    for (int i = 0; i < 4; i++) {
        int c = tid + 256 * i;
        rowc[i]  = c >> 3;
        choff[i] = (c & 7) * 8;
    }

    int aRow = wm + ((lane >> 3) & 1) * 8 + (lane & 7);
    int aK   = (lane >> 4) * 8;
    int bRow = wn + (lane >> 4) * 8 + (lane & 7);
    int bK   = ((lane >> 3) & 1) * 8;
    uint32_t aAddr = aBase + (uint32_t)aRow * ROWB + (uint32_t)aK * 2;
    uint32_t bAddr = bBase + (uint32_t)bRow * ROWB + (uint32_t)bK * 2;

    float acc[4][4][4];
#pragma unroll
    for (int mi = 0; mi < 4; mi++)
#pragma unroll
        for (int ni = 0; ni < 4; ni++)
#pragma unroll
            for (int r = 0; r < 4; r++) acc[mi][ni][r] = 0.0f;

    int nt = K >> 6;

#define LOAD_TILE(t)                                                           \
    do {                                                                       \
        uint32_t off_ = (uint32_t)((t) % 3) * MATB;                            \
        int k0_ = (t) << 6;                                                    \
        _Pragma("unroll")                                                      \
        for (int i_ = 0; i_ < 4; i_++) {                                       \
            uint32_t d_ = off_ + (uint32_t)rowc[i_] * ROWB + (uint32_t)choff[i_] * 2; \
            cpa16(aBase + d_, Ab + (size_t)rowc[i_] * K + k0_ + choff[i_]);    \
            cpa16(bBase + d_, Bb + (size_t)rowc[i_] * K + k0_ + choff[i_]);    \
        }                                                                      \
        cpa_commit();                                                          \
    } while (0)

    LOAD_TILE(0);
    if (nt > 1) LOAD_TILE(1);

    for (int j = 0; j < nt; j++) {
        if (j + 1 < nt) cpa_wait1(); else cpa_wait0();
        __syncthreads();
        if (j + 2 < nt) LOAD_TILE(j + 2);

        uint32_t bufOff = (uint32_t)(j % 3) * MATB;
#pragma unroll
        for (int ks = 0; ks < 4; ks++) {
            uint32_t kOff = bufOff + (uint32_t)(ks * 32);
            uint32_t af[4][4], bf[4][2];
#pragma unroll
            for (int mi = 0; mi < 4; mi++)
                ldsm4(af[mi][0], af[mi][1], af[mi][2], af[mi][3],
                      aAddr + kOff + (uint32_t)(mi * 16) * ROWB);
#pragma unroll
            for (int pi = 0; pi < 2; pi++)
                ldsm4(bf[2 * pi][0], bf[2 * pi][1], bf[2 * pi + 1][0], bf[2 * pi + 1][1],
                      bAddr + kOff + (uint32_t)(pi * 16) * ROWB);
#pragma unroll
            for (int mi = 0; mi < 4; mi++)
#pragma unroll
                for (int ni = 0; ni < 4; ni++)
                    mma_bf16(acc[mi][ni], af[mi], bf[ni]);
        }
    }

#pragma unroll
    for (int mi = 0; mi < 4; mi++) {
        int r0 = blockIdx.y * 128 + wm + mi * 16 + grp;
#pragma unroll
        for (int ni = 0; ni < 4; ni++) {
            int c = blockIdx.x * 128 + wn + ni * 8 + tig * 2;
            float bv0 = __ldg(bias + c), bv1 = __ldg(bias + c + 1);
            float v0 = acc[mi][ni][0] + bv0;
            float v1 = acc[mi][ni][1] + bv1;
            float v2 = acc[mi][ni][2] + bv0;
            float v3 = acc[mi][ni][3] + bv1;
            if (act == 1) {
                v0 = gelu_exact(v0); v1 = gelu_exact(v1);
                v2 = gelu_exact(v2); v3 = gelu_exact(v3);
            }
            if (outmode == 1) {
                __nv_bfloat162 p0 = {__float2bfloat16_rn(v0), __float2bfloat16_rn(v1)};
                __nv_bfloat162 p1 = {__float2bfloat16_rn(v2), __float2bfloat16_rn(v3)};
                *(__nv_bfloat162*)(Cb + (size_t)r0 * N + c) = p0;
                *(__nv_bfloat162*)(Cb + (size_t)(r0 + 8) * N + c) = p1;
            } else {
                uint32_t p0 = packh2(v0, v1), p1 = packh2(v2, v3);
                *(uint32_t*)(Ch + (size_t)r0 * N + c) = p0;
                *(uint32_t*)(Ch + (size_t)(r0 + 8) * N + c) = p1;
            }
        }
    }
}

// ---------------------------------------------------------------------------
// Fused GEMM(N=256) + residual + LayerNorm. Block tile 64x256, 8 warps (1x8).
// ---------------------------------------------------------------------------
#define FA_B  (64 * ROWB)
#define FB_B  (256 * ROWB)
#define FG_SMEM (2 * FA_B + 2 * FB_B)
#define STG_S 264

__global__ void __launch_bounds__(256, 2)
gemm_ln(const __nv_bfloat16* __restrict__ A, const __nv_bfloat16* __restrict__ B,
        const float* __restrict__ bias,
        const float* __restrict__ lns, const float* __restrict__ lnb,
        float* __restrict__ x, __nv_bfloat16* __restrict__ xb, int K)
{
    extern __shared__ __nv_bfloat16 smem[];
    uint32_t sbase = (uint32_t)__cvta_generic_to_shared(smem);
    uint32_t aBase = sbase;
    uint32_t bBase = sbase + 2 * FA_B;

    int tid  = threadIdx.x;
    int warp = tid >> 5, lane = tid & 31;
    int wn = warp * 32;
    int grp = lane >> 2, tig = lane & 3;

    const __nv_bfloat16* Ab = A + (size_t)blockIdx.x * 64 * K;

    int aRowc[2], aChoff[2];
#pragma unroll
    for (int i = 0; i < 2; i++) {
        int c = tid + 256 * i;
        aRowc[i]  = c >> 3;
        aChoff[i] = (c & 7) * 8;
    }
    int bRowc[8], bChoff[8];
#pragma unroll
    for (int i = 0; i < 8; i++) {
        int c = tid + 256 * i;
        bRowc[i]  = c >> 3;
        bChoff[i] = (c & 7) * 8;
    }

    int aRow = ((lane >> 3) & 1) * 8 + (lane & 7);
    int aK   = (lane >> 4) * 8;
    int bRow = wn + (lane >> 4) * 8 + (lane & 7);
    int bK   = ((lane >> 3) & 1) * 8;
    uint32_t aAddr = aBase + (uint32_t)aRow * ROWB + (uint32_t)aK * 2;
    uint32_t bAddr = bBase + (uint32_t)bRow * ROWB + (uint32_t)bK * 2;

    float acc[4][4][4];
#pragma unroll
    for (int mi = 0; mi < 4; mi++)
#pragma unroll
        for (int ni = 0; ni < 4; ni++)
#pragma unroll
            for (int r = 0; r < 4; r++) acc[mi][ni][r] = 0.0f;

    int nt = K >> 6;

#define FLOAD_TILE(t)                                                          \
    do {                                                                       \
        uint32_t oa_ = (uint32_t)((t) & 1) * FA_B;                             \
        uint32_t ob_ = (uint32_t)((t) & 1) * FB_B;                             \
        int k0_ = (t) << 6;                                                    \
        _Pragma("unroll")                                                      \
        for (int i_ = 0; i_ < 2; i_++)                                         \
            cpa16(aBase + oa_ + (uint32_t)aRowc[i_] * ROWB + (uint32_t)aChoff[i_] * 2, \
                  Ab + (size_t)aRowc[i_] * K + k0_ + aChoff[i_]);              \
        _Pragma("unroll")                                                      \
        for (int i_ = 0; i_ < 8; i_++)                                         \
            cpa16(bBase + ob_ + (uint32_t)bRowc[i_] * ROWB + (uint32_t)bChoff[i_] * 2, \
                  B + (size_t)bRowc[i_] * K + k0_ + bChoff[i_]);               \
        cpa_commit();                                                          \
    } while (0)

    FLOAD_TILE(0);

    for (int j = 0; j < nt; j++) {
        cpa_wait0();
        __syncthreads();
        if (j + 1 < nt) FLOAD_TILE(j + 1);

        uint32_t aOff = (uint32_t)(j & 1) * FA_B;
        uint32_t bOff = (uint32_t)(j & 1) * FB_B;
#pragma unroll
        for (int ks = 0; ks < 4; ks++) {
            uint32_t kb = (uint32_t)(ks * 32);
            uint32_t af[4][4], bf[4][2];
#pragma unroll
            for (int mi = 0; mi < 4; mi++)
                ldsm4(af[mi][0], af[mi][1], af[mi][2], af[mi][3],
                      aAddr + aOff + kb + (uint32_t)(mi * 16) * ROWB);
#pragma unroll
            for (int pi = 0; pi < 2; pi++)
                ldsm4(bf[2 * pi][0], bf[2 * pi][1], bf[2 * pi + 1][0], bf[2 * pi + 1][1],
                      bAddr + bOff + kb + (uint32_t)(pi * 16) * ROWB);
#pragma unroll
            for (int mi = 0; mi < 4; mi++)
#pragma unroll
                for (int ni = 0; ni < 4; ni++)
                    mma_bf16(acc[mi][ni], af[mi], bf[ni]);
        }
    }
    __syncthreads();

    float* stage = (float*)smem;
#pragma unroll
    for (int mi = 0; mi < 4; mi++) {
        int r0 = mi * 16 + grp;
#pragma unroll
        for (int ni = 0; ni < 4; ni++) {
            int c = wn + ni * 8 + tig * 2;
            float bv0 = __ldg(bias + c), bv1 = __ldg(bias + c + 1);
            stage[r0 * STG_S + c]           = acc[mi][ni][0] + bv0;
            stage[r0 * STG_S + c + 1]       = acc[mi][ni][1] + bv1;
            stage[(r0 + 8) * STG_S + c]     = acc[mi][ni][2] + bv0;
            stage[(r0 + 8) * STG_S + c + 1] = acc[mi][ni][3] + bv1;
        }
    }
    __syncthreads();

    float4 sv0 = *(const float4*)(lns + lane * 8);
    float4 sv1 = *(const float4*)(lns + lane * 8 + 4);
    float4 bv0 = *(const float4*)(lnb + lane * 8);
    float4 bv1 = *(const float4*)(lnb + lane * 8 + 4);
    float sc[8] = {sv0.x, sv0.y, sv0.z, sv0.w, sv1.x, sv1.y, sv1.z, sv1.w};
    float bi[8] = {bv0.x, bv0.y, bv0.z, bv0.w, bv1.x, bv1.y, bv1.z, bv1.w};

#pragma unroll
    for (int it = 0; it < 8; it++) {
        int tok = warp * 8 + it;
        size_t gbase = ((size_t)blockIdx.x * 64 + tok) * DMODEL + lane * 8;
        const float* sp = stage + tok * STG_S + lane * 8;

        float4 xv0 = *(const float4*)(x + gbase);
        float4 xv1 = *(const float4*)(x + gbase + 4);
        float v[8] = {xv0.x + sp[0], xv0.y + sp[1], xv0.z + sp[2], xv0.w + sp[3],
                      xv1.x + sp[4], xv1.y + sp[5], xv1.z + sp[6], xv1.w + sp[7]};

        float sum = 0.0f;
#pragma unroll
        for (int i = 0; i < 8; i++) sum += v[i];
#pragma unroll
        for (int o = 16; o > 0; o >>= 1) sum += __shfl_xor_sync(0xffffffffu, sum, o);
        float m = sum * (1.0f / 256.0f);

        float vs = 0.0f;
#pragma unroll
        for (int i = 0; i < 8; i++) { float d = v[i] - m; vs += d * d; }
#pragma unroll
        for (int o = 16; o > 0; o >>= 1) vs += __shfl_xor_sync(0xffffffffu, vs, o);
        float rstd = rsqrtf(vs * (1.0f / 256.0f) + 1e-5f);

        float o_[8];
#pragma unroll
        for (int i = 0; i < 8; i++) o_[i] = (v[i] - m) * rstd * sc[i] + bi[i];

        float4 w0 = {o_[0], o_[1], o_[2], o_[3]};
        float4 w1 = {o_[4], o_[5], o_[6], o_[7]};
        *(float4*)(x + gbase) = w0;
        *(float4*)(x + gbase + 4) = w1;
#pragma unroll
        for (int i = 0; i < 8; i += 2) {
            __nv_bfloat162 c2 = {__float2bfloat16_rn(o_[i]), __float2bfloat16_rn(o_[i + 1])};
            *(__nv_bfloat162*)(xb + gbase + i) = c2;
        }
    }
}

// ---------------------------------------------------------------------------
// Tensor-core windowed attention (fp16 mma, fp32 softmax).
// K/V staged in smem per warp; Q fragments loaded directly from gmem.
// grid (512, 2), block 128 = 4 warps (head = blockIdx.y*4 + warp).
// ---------------------------------------------------------------------------
#define ATT_RS   40
#define ATT_MATH (64 * ATT_RS)
#define ATT_WARPH (2 * ATT_MATH)           // K | V only
#define ATT_SMEM (4 * ATT_WARPH * 2)       // 40960 bytes

__global__ void __launch_bounds__(128, 4)
attn_tc(const __half* __restrict__ qkv, __nv_bfloat16* __restrict__ att)
{
    extern __shared__ __half ash[];
    int tid = threadIdx.x, warp = tid >> 5, lane = tid & 31;
    int w = blockIdx.x;
    int head = blockIdx.y * 4 + warp;
    int grp = lane >> 2, tig = lane & 3;

    __half* base = ash + warp * ATT_WARPH;   // K | V
    uint32_t sb = (uint32_t)__cvta_generic_to_shared(base);

    const __half* src = qkv + (size_t)w * 64 * DQKV + head * 32;
#pragma unroll
    for (int m = 0; m < 2; m++) {
        const __half* ms = src + 256 + m * 256;   // K at +256, V at +512
        __half* dst = base + m * ATT_MATH;
#pragma unroll
        for (int p = 0; p < 8; p++) {
            int c = p * 32 + lane;
            int row = c >> 2, ch = c & 3;
            *(uint4*)(dst + row * ATT_RS + ch * 8) =
                *(const uint4*)(ms + (size_t)row * DQKV + ch * 8);
        }
    }
    __syncwarp();

    const uint32_t Ks = sb;
    const uint32_t Vs = sb + ATT_MATH * 2;
    const __half* qbase = src;   // Q at offset 0

    const float scale = 0.17677669529663687f;

#pragma unroll
    for (int qt = 0; qt < 4; qt++) {
        // Q A-fragments directly from gmem (mapping == ldmatrix non-trans)
        uint32_t qa[2][4];
#pragma unroll
        for (int ks = 0; ks < 2; ks++) {
            const __half* qp = qbase + (size_t)(qt * 16 + grp) * DQKV + ks * 16 + tig * 2;
            qa[ks][0] = *(const uint32_t*)(qp);
            qa[ks][1] = *(const uint32_t*)(qp + 8 * DQKV);
            qa[ks][2] = *(const uint32_t*)(qp + 8);
            qa[ks][3] = *(const uint32_t*)(qp + 8 * DQKV + 8);
        }

        float s[8][4];
#pragma unroll
        for (int nt2 = 0; nt2 < 8; nt2++)
#pragma unroll
            for (int r = 0; r < 4; r++) s[nt2][r] = 0.0f;

#pragma unroll
        for (int ks = 0; ks < 2; ks++) {
            uint32_t kf[8][2];
#pragma unroll
            for (int pi = 0; pi < 4; pi++) {
                uint32_t addr = Ks +
                    (uint32_t)((pi * 16 + (lane >> 4) * 8 + (lane & 7)) * ATT_RS +
                               ((lane >> 3) & 1) * 8 + ks * 16) * 2;
                ldsm4(kf[2 * pi][0], kf[2 * pi][1],
                      kf[2 * pi + 1][0], kf[2 * pi + 1][1], addr);
            }
#pragma unroll
            for (int nt2 = 0; nt2 < 8; nt2++)
                mma_fp16(s[nt2], qa[ks], kf[nt2]);
        }

        float mx0 = -1e30f, mx1 = -1e30f;
#pragma unroll
        for (int nt2 = 0; nt2 < 8; nt2++) {
            s[nt2][0] *= scale; s[nt2][1] *= scale;
            s[nt2][2] *= scale; s[nt2][3] *= scale;
            mx0 = fmaxf(mx0, fmaxf(s[nt2][0], s[nt2][1]));
            mx1 = fmaxf(mx1, fmaxf(s[nt2][2], s[nt2][3]));
        }
        mx0 = fmaxf(mx0, __shfl_xor_sync(0xffffffffu, mx0, 1));
        mx0 = fmaxf(mx0, __shfl_xor_sync(0xffffffffu, mx0, 2));
        mx1 = fmaxf(mx1, __shfl_xor_sync(0xffffffffu, mx1, 1));
        mx1 = fmaxf(mx1, __shfl_xor_sync(0xffffffffu, mx1, 2));

        float sm0 = 0.0f, sm1 = 0.0f;
#pragma unroll
        for (int nt2 = 0; nt2 < 8; nt2++) {
            s[nt2][0] = expf(s[nt2][0] - mx0);
            s[nt2][1] = expf(s[nt2][1] - mx0);
            s[nt2][2] = expf(s[nt2][2] - mx1);
            s[nt2][3] = expf(s[nt2][3] - mx1);
            sm0 += s[nt2][0] + s[nt2][1];
            sm1 += s[nt2][2] + s[nt2][3];
        }
        sm0 += __shfl_xor_sync(0xffffffffu, sm0, 1);
        sm0 += __shfl_xor_sync(0xffffffffu, sm0, 2);
        sm1 += __shfl_xor_sync(0xffffffffu, sm1, 1);
        sm1 += __shfl_xor_sync(0xffffffffu, sm1, 2);
        float inv0 = 1.0f / sm0, inv1 = 1.0f / sm1;

        uint32_t pa[4][4];
#pragma unroll
        for (int ks2 = 0; ks2 < 4; ks2++) {
            pa[ks2][0] = packh2(s[2 * ks2][0],     s[2 * ks2][1]);
            pa[ks2][1] = packh2(s[2 * ks2][2],     s[2 * ks2][3]);
            pa[ks2][2] = packh2(s[2 * ks2 + 1][0], s[2 * ks2 + 1][1]);
            pa[ks2][3] = packh2(s[2 * ks2 + 1][2], s[2 * ks2 + 1][3]);
        }

        float o[4][4];
#pragma unroll
        for (int nt2 = 0; nt2 < 4; nt2++)
#pragma unroll
            for (int r = 0; r < 4; r++) o[nt2][r] = 0.0f;

#pragma unroll
        for (int ks2 = 0; ks2 < 4; ks2++) {
            uint32_t vf[4][2];
#pragma unroll
            for (int np = 0; np < 2; np++) {
                uint32_t addr = Vs +
                    (uint32_t)((ks2 * 16 + ((lane >> 3) & 1) * 8 + (lane & 7)) * ATT_RS +
                               ((lane >> 4) + np * 2) * 8) * 2;
                ldsm4t(vf[2 * np][0], vf[2 * np][1],
                       vf[2 * np + 1][0], vf[2 * np + 1][1], addr);
            }
#pragma unroll
            for (int nt2 = 0; nt2 < 4; nt2++)
                mma_fp16(o[nt2], pa[ks2], vf[nt2]);
        }

        int row0 = w * 64 + qt * 16 + grp;
        __nv_bfloat16* ob = att + (size_t)row0 * DMODEL + head * 32 + tig * 2;
#pragma unroll
        for (int nt2 = 0; nt2 < 4; nt2++) {
            __nv_bfloat162 p0 = {__float2bfloat16_rn(o[nt2][0] * inv0),
                                 __float2bfloat16_rn(o[nt2][1] * inv0)};
            __nv_bfloat162 p1 = {__float2bfloat16_rn(o[nt2][2] * inv1),
                                 __float2bfloat16_rn(o[nt2][3] * inv1)};
            *(__nv_bfloat162*)(ob + nt2 * 8) = p0;
            *(__nv_bfloat162*)(ob + 8 * DMODEL + nt2 * 8) = p1;
        }
    }
}

// ---------------------------------------------------------------------------
// Final LN + transposed, fully-coalesced write to [B, C, H*W].
// grid (32 l-chunks, 32 batches), block 256 (8 warps x 4 tokens each).
// ---------------------------------------------------------------------------
__global__ __launch_bounds__(256)
void final_ln_t(const float* __restrict__ x, const float* __restrict__ s,
                const float* __restrict__ b, float* __restrict__ out)
{
    __shared__ float stage[32][257];   // [token_local][d], stride 257 -> clean reads
    int bb = blockIdx.y, l0 = blockIdx.x * 32;
    int warp = threadIdx.x >> 5, lane = threadIdx.x & 31;

    float4 sv0 = *(const float4*)(s + lane * 8);
    float4 sv1 = *(const float4*)(s + lane * 8 + 4);
    float4 bv0 = *(const float4*)(b + lane * 8);
    float4 bv1 = *(const float4*)(b + lane * 8 + 4);
    float sc[8] = {sv0.x, sv0.y, sv0.z, sv0.w, sv1.x, sv1.y, sv1.z, sv1.w};
    float bi[8] = {bv0.x, bv0.y, bv0.z, bv0.w, bv1.x, bv1.y, bv1.z, bv1.w};

#pragma unroll
    for (int it = 0; it < 4; it++) {
        int tl = warp * 4 + it;
        size_t base = ((size_t)(bb * 1024 + l0 + tl)) * DMODEL + lane * 8;
        float4 v0 = *(const float4*)(x + base);
        float4 v1 = *(const float4*)(x + base + 4);
        float v[8] = {v0.x, v0.y, v0.z, v0.w, v1.x, v1.y, v1.z, v1.w};

        float sum = 0.0f;
#pragma unroll
        for (int i = 0; i < 8; i++) sum += v[i];
#pragma unroll
        for (int o = 16; o > 0; o >>= 1) sum += __shfl_xor_sync(0xffffffffu, sum, o);
        float m = sum * (1.0f / 256.0f);

        float vs = 0.0f;
#pragma unroll
        for (int i = 0; i < 8; i++) { float d = v[i] - m; vs += d * d; }
#pragma unroll
        for (int o = 16; o > 0; o >>= 1) vs += __shfl_xor_sync(0xffffffffu, vs, o);
        float rstd = rsqrtf(vs * (1.0f / 256.0f) + 1e-5f);

#pragma unroll
        for (int i = 0; i < 8; i++)
            stage[tl][lane * 8 + i] = (v[i] - m) * rstd * sc[i] + bi[i];
    }
    __syncthreads();

    // coalesced output: lanes sweep l for fixed d
#pragma unroll
    for (int dd = warp; dd < DMODEL; dd += 8)
        out[((size_t)bb * DMODEL + dd) * 1024 + l0 + lane] = stage[lane][dd];
}

// ---------------------------------------------------------------------------
extern "C" void kernel_launch(void* const* d_in, const int* in_sizes, int n_in,
                              void* d_out, int out_size)
{
    const float* features = (const float*)d_in[0];
    const float* in_w  = (const float*)d_in[1];
    const float* in_b  = (const float*)d_in[2];
    const float* ow    = (const float*)d_in[3];
    const float* ob    = (const float*)d_in[4];
    const float* w1    = (const float*)d_in[5];
    const float* b1    = (const float*)d_in[6];
    const float* w2    = (const float*)d_in[7];
    const float* b2    = (const float*)d_in[8];
    const float* ln1s  = (const float*)d_in[9];
    const float* ln1b  = (const float*)d_in[10];
    const float* ln2s  = (const float*)d_in[11];
    const float* ln2b  = (const float*)d_in[12];
    const float* fns   = (const float*)d_in[13];
    const float* fnb   = (const float*)d_in[14];
    float* out = (float*)d_out;

    float* x;
    __half* qkvh;
    __nv_bfloat16 *xb, *att, *hh, *wb;
    cudaGetSymbolAddress((void**)&x,    g_x);
    cudaGetSymbolAddress((void**)&xb,   g_xb);
    cudaGetSymbolAddress((void**)&qkvh, g_qkv);
    cudaGetSymbolAddress((void**)&att,  g_att);
    cudaGetSymbolAddress((void**)&hh,   g_h);
    cudaGetSymbolAddress((void**)&wb,   g_wb);

    cudaFuncSetAttribute(gemm_bf16, cudaFuncAttributeMaxDynamicSharedMemorySize, GSMEM_SZ);
    cudaFuncSetAttribute(gemm_ln,   cudaFuncAttributeMaxDynamicSharedMemorySize, FG_SMEM);
    cudaFuncSetAttribute(attn_tc,   cudaFuncAttributeMaxDynamicSharedMemorySize, ATT_SMEM);

    cvt_all<<<(CV4 + 255) / 256, 256>>>(in_w, ow, w1, w2, wb);

    dim3 eb(32, 32);
    dim3 eg(32, 8, 32);
    embed_kernel<<<eg, eb>>>(features, x, xb);

    const int T = T_TOK;
    for (int i = 0; i < 3; i++) {
        gemm_bf16<<<dim3(DQKV / 128, T / 128), 256, GSMEM_SZ>>>(
            xb, wb + WT_INW + (size_t)i * DQKV * DMODEL, in_b + (size_t)i * DQKV,
            nullptr, qkvh, T, DQKV, DMODEL, 0, 2);
        attn_tc<<<dim3(512, 2), 128, ATT_SMEM>>>(qkvh, att);
        gemm_ln<<<T / 64, 256, FG_SMEM>>>(
            att, wb + WT_OW + (size_t)i * DMODEL * DMODEL, ob + (size_t)i * DMODEL,
            ln1s + (size_t)i * DMODEL, ln1b + (size_t)i * DMODEL, x, xb, DMODEL);
        gemm_bf16<<<dim3(DFFN / 128, T / 128), 256, GSMEM_SZ>>>(
            xb, wb + WT_W1 + (size_t)i * DFFN * DMODEL, b1 + (size_t)i * DFFN,
            hh, nullptr, T, DFFN, DMODEL, 1, 1);
        gemm_ln<<<T / 64, 256, FG_SMEM>>>(
            hh, wb + WT_W2 + (size_t)i * DMODEL * DFFN, b2 + (size_t)i * DMODEL,
            ln2s + (size_t)i * DMODEL, ln2b + (size_t)i * DMODEL, x, xb, DFFN);
    }
    final_ln_t<<<dim3(32, 32), 256>>>(x, fns, fnb, out);
}